// round 5
// baseline (speedup 1.0000x reference)
#include <cuda_runtime.h>
#include <cuda_bf16.h>
#include <math.h>
#include <stdint.h>

#define Bb 8
#define C0 64
#define Hh 256
#define Ww 256
#define MX 16
#define NL4 4
#define HW 65536
#define LDA 104

typedef unsigned long long ull;
typedef unsigned int u32;
typedef unsigned short u16;

// -------------------- f32x2 helpers ----------------------------------------
__device__ __forceinline__ ull pk(float lo, float hi) {
    ull r; asm("mov.b64 %0,{%1,%2};" : "=l"(r) : "f"(lo), "f"(hi)); return r;
}
__device__ __forceinline__ void upk(ull v, float& lo, float& hi) {
    asm("mov.b64 {%0,%1},%2;" : "=f"(lo), "=f"(hi) : "l"(v));
}
__device__ __forceinline__ ull f2fma(ull a, ull b, ull c) {
    ull d; asm("fma.rn.f32x2 %0,%1,%2,%3;" : "=l"(d) : "l"(a), "l"(b), "l"(c)); return d;
}
__device__ __forceinline__ void split1(float v, u16& hi, u16& lo) {
    __nv_bfloat16 h = __float2bfloat16(v);
    hi = __bfloat16_as_ushort(h);
    lo = __bfloat16_as_ushort(__float2bfloat16(v - __bfloat162float(h)));
}
__device__ __forceinline__ u32 smem_u32(const void* p) {
    u32 a; asm("{ .reg .u64 t; cvta.to.shared.u64 t, %1; cvt.u32.u64 %0, t; }" : "=r"(a) : "l"(p));
    return a;
}

// -------------------- mma/ldmatrix wrappers ---------------------------------
__device__ __forceinline__ void ldmx4(u32* r, u32 addr) {
    asm volatile("ldmatrix.sync.aligned.m8n8.x4.shared.b16 {%0,%1,%2,%3},[%4];"
        : "=r"(r[0]), "=r"(r[1]), "=r"(r[2]), "=r"(r[3]) : "r"(addr));
}
__device__ __forceinline__ void mma16816(float* d, const u32* a, u32 b0, u32 b1) {
    asm volatile("mma.sync.aligned.m16n8k16.row.col.f32.bf16.bf16.f32 "
        "{%0,%1,%2,%3},{%4,%5,%6,%7},{%8,%9},{%0,%1,%2,%3};"
        : "+f"(d[0]), "+f"(d[1]), "+f"(d[2]), "+f"(d[3])
        : "r"(a[0]), "r"(a[1]), "r"(a[2]), "r"(a[3]), "r"(b0), "r"(b1));
}

// -------------------- globals -----------------------------------------------
__device__ u32 g_actA[(size_t)Bb * HW * C0];   // packed (hi | lo<<16) bf16
__device__ u32 g_actB[(size_t)Bb * HW * C0];
__device__ ull g_T [(size_t)Bb * C0 * Hh * MX];
__device__ ull g_Xf[(size_t)Bb * C0 * 256];
__device__ ull g_G [(size_t)256 * Bb * C0];
__device__ ull g_Q [(size_t)Bb * C0 * Hh * MX];
__device__ ull g_W2[(size_t)NL4 * 256 * 4096];
__device__ ull g_FwR[MX * 128], g_FwI[MX * 128];
__device__ ull g_Fh2a[MX * Hh], g_Fh2b[MX * Hh];
__device__ ull g_Eh2a[Hh * MX], g_Eh2b[Hh * MX];
__device__ u16 g_PwH[NL4 * 4096], g_PwL[NL4 * 4096];   // [l][o][c]
__device__ u16 g_SynH[256 * 32], g_SynL[256 * 32];     // [w][2ky|2ky+1]

// -------------------- tables ------------------------------------------------
__global__ void k_tables() {
    int idx = blockIdx.x * 256 + threadIdx.x;
    int a = idx >> 8, p = idx & 255, m = (a * p) & 255;
    float s, c; sincospif((float)m * (1.0f / 128.0f), &s, &c);
    g_Fh2a[idx] = pk(c, -s);  g_Fh2b[idx] = pk(s, c);
    g_Eh2a[p * MX + a] = pk(c, s);  g_Eh2b[p * MX + a] = pk(-s, c);
}
__global__ void k_tables2() {
    int idx = blockIdx.x * 256 + threadIdx.x;   // 0..2047
    int ky = idx >> 7, j = idx & 127, w = 2 * j;
    float s0, c0, s1, c1;
    sincospif((float)((ky * w) & 255) * (1.0f / 128.0f), &s0, &c0);
    sincospif((float)((ky * (w + 1)) & 255) * (1.0f / 128.0f), &s1, &c1);
    const float n = 1.0f / 256.0f;
    g_FwR[idx] = pk(c0 * n, c1 * n);
    g_FwI[idx] = pk(-s0 * n, -s1 * n);
}
__global__ void k_prep_pw(const float* __restrict__ pw_w) {
    int i = blockIdx.x * 256 + threadIdx.x;   // 0..16383
    u16 h, l; split1(pw_w[i], h, l);
    g_PwH[i] = h; g_PwL[i] = l;
}
__global__ void k_prep_syn() {
    int i = blockIdx.x * 256 + threadIdx.x;   // 0..8191
    int w = i >> 5, j = i & 31, ky = j >> 1, ri = j & 1;
    float s, c; sincospif((float)((ky * w) & 255) * (1.0f / 128.0f), &s, &c);
    float ck = ((ky == 0) ? 1.0f : 2.0f) * (1.0f / 256.0f);
    float v = ri ? s * ck : c * ck;
    u16 h, l; split1(v, h, l);
    g_SynH[i] = h; g_SynL[i] = l;
}
__global__ void k_twt(const float* __restrict__ wr, const float* __restrict__ wi) {
    __shared__ ull tile[32][33];
    int l = blockIdx.z, tio = blockIdx.x, tm = blockIdx.y;
    int tx = threadIdx.x, ty = threadIdx.y;
    const float* wrl = wr + (size_t)l * 4096 * 256;
    const float* wil = wi + (size_t)l * 4096 * 256;
    #pragma unroll
    for (int r = 0; r < 4; r++) {
        int row = tio * 32 + ty + 8 * r, col = tm * 32 + tx;
        size_t idx = (size_t)row * 256 + col;
        tile[ty + 8 * r][tx] = pk(wrl[idx], wil[idx]);
    }
    __syncthreads();
    #pragma unroll
    for (int r = 0; r < 4; r++) {
        int mm = tm * 32 + ty + 8 * r, io = tio * 32 + tx;
        g_W2[(((size_t)l * 256) + mm) * 4096 + io] = tile[tx][ty + 8 * r];
    }
}

__device__ __forceinline__ float gelu_exact(float z) {
    return 0.5f * z * (1.0f + erff(z * 0.70710678118654752f));
}

// -------------------- fwd w-DFT epilogue (stag [c][260] f32) ----------------
__device__ __forceinline__ void epilogue_fwd_w(const float* stag, char* rb,
                                               int b, int h, int t) {
    ull* frp = (ull*)rb;
    ull* fip = (ull*)(rb + 16640);
    for (int i = t; i < 2048; i += 256) {
        int ky = i >> 7, j = i & 127;
        frp[ky * 130 + j] = g_FwR[i];
        fip[ky * 130 + j] = g_FwI[i];
    }
    __syncthreads();
    ull* Tg = g_T + ((size_t)b * C0) * 4096 + (size_t)h * MX;
    #pragma unroll
    for (int pass = 0; pass < 4; pass++) {
        int o = (t >> 4) + 16 * pass, ky = t & 15;
        const ull* fr = frp + ky * 130;
        const ull* fi = fip + ky * 130;
        const float* vs = stag + o * 260;
        ull ar = 0ull, ai = 0ull;
        for (int iw = 0; iw < 64; iw++) {
            ulonglong2 vv = *(const ulonglong2*)(vs + iw * 4);
            ulonglong2 fR = *(const ulonglong2*)(fr + iw * 2);
            ulonglong2 fI = *(const ulonglong2*)(fi + iw * 2);
            ar = f2fma(vv.x, fR.x, ar); ar = f2fma(vv.y, fR.y, ar);
            ai = f2fma(vv.x, fI.x, ai); ai = f2fma(vv.y, fI.y, ai);
        }
        float r0, r1, i0, i1; upk(ar, r0, r1); upk(ai, i0, i1);
        Tg[(size_t)o * 4096 + ky] = pk(r0 + r1, i0 + i1);
    }
}

// -------------------- lift --------------------------------------------------
__global__ __launch_bounds__(256, 1)
void k_lift(const float* __restrict__ x, const float* __restrict__ in_w,
            const float* __restrict__ in_b) {
    extern __shared__ __align__(16) char sm[];
    float* stag = (float*)sm;            // [64][260]
    char* rb = sm + 66560;
    __shared__ float siw[128], sib[64];
    int h = blockIdx.x, b = blockIdx.y, t = threadIdx.x;
    if (t < 128) siw[t] = in_w[t];
    if (t < 64) sib[t] = in_b[t];
    float x0 = x[(((size_t)b * 2 + 0) * Hh + h) * Ww + t];
    float x1 = x[(((size_t)b * 2 + 1) * Hh + h) * Ww + t];
    __syncthreads();
    for (int o = 0; o < C0; o++)
        stag[o * 260 + t] = fmaf(siw[2 * o], x0, fmaf(siw[2 * o + 1], x1, sib[o]));
    __syncthreads();
    u32* dst = g_actA + ((size_t)(b * 256 + h)) * 16384;
    for (int i = t; i < 16384; i += 256) {
        int w = i >> 6, c = i & 63;
        u16 hi, lo; split1(stag[c * 260 + w], hi, lo);
        dst[i] = (u32)hi | ((u32)lo << 16);
    }
    epilogue_fwd_w(stag, rb, b, h, t);
}

// -------------------- spectral trio (proven) --------------------------------
__global__ __launch_bounds__(256, 2) void k_fwd_h() {
    extern __shared__ __align__(16) char smraw[];
    ull* Ts = (ull*)smraw;
    ull* fa = Ts + 4096;
    ull* fb = fa + 4096;
    int bc = blockIdx.x, t = threadIdx.x;
    const ull* Tg = g_T + (size_t)bc * 4096;
    for (int i = t; i < 4096; i += 256) { Ts[i] = Tg[i]; fa[i] = g_Fh2a[i]; fb[i] = g_Fh2b[i]; }
    __syncthreads();
    int kx = t >> 4, ky = t & 15;
    const ull* fak = fa + kx * 256;
    const ull* fbk = fb + kx * 256;
    ull acc = 0ull;
    for (int h = 0; h < Hh; h++) {
        float tr, ti; upk(Ts[h * MX + ky], tr, ti);
        acc = f2fma(pk(tr, tr), fak[h], acc);
        acc = f2fma(pk(ti, ti), fbk[h], acc);
    }
    g_Xf[(size_t)bc * 256 + t] = acc;
}
__global__ __launch_bounds__(512, 2) void k_modegemm(int l) {
    __shared__ __align__(16) ull ws[4096];
    __shared__ ull xA[512], xB[512];
    int m = blockIdx.x, t = threadIdx.x;
    const ull* W = g_W2 + (((size_t)l * 256) + m) * 4096;
    for (int i = t; i < 4096; i += 512) ws[i] = W[i];
    {
        int b = t >> 6, i = t & 63;
        float xr, xi; upk(g_Xf[((size_t)b * C0 + i) * 256 + m], xr, xi);
        xA[t] = pk(xr, xr);
        xB[t] = pk(-xi, xi);
    }
    __syncthreads();
    int b = t >> 6, o = t & 63;
    ull acc = 0ull;
    const ull* xa = xA + b * 64;
    const ull* xb = xB + b * 64;
    #pragma unroll 4
    for (int i = 0; i < C0; i++) {
        ull w2 = ws[i * 64 + o];
        float wr, wi; upk(w2, wr, wi);
        acc = f2fma(xa[i], w2, acc);
        acc = f2fma(xb[i], pk(wi, wr), acc);
    }
    g_G[(size_t)m * 512 + t] = acc;
}
__global__ __launch_bounds__(256, 2) void k_inv_h() {
    extern __shared__ __align__(16) char smraw[];
    ull* Gs = (ull*)smraw;
    ull* ea = Gs + 256;
    ull* eb = ea + 4096;
    int bo = blockIdx.x, t = threadIdx.x;
    for (int i = t; i < 256; i += 256) Gs[i] = g_G[(size_t)i * 512 + bo];
    for (int i = t; i < 4096; i += 256) { ea[i] = g_Eh2a[i]; eb[i] = g_Eh2b[i]; }
    __syncthreads();
    int hg = t >> 4, ky = t & 15;
    ull acc[16];
    #pragma unroll
    for (int i = 0; i < 16; i++) acc[i] = 0ull;
    #pragma unroll
    for (int kx = 0; kx < MX; kx++) {
        float gr, gi; upk(Gs[kx * MX + ky], gr, gi);
        ull gr2 = pk(gr, gr), gi2 = pk(gi, gi);
        #pragma unroll
        for (int hp = 0; hp < 16; hp++) {
            int h = hp * 16 + hg;
            acc[hp] = f2fma(gr2, ea[h * MX + kx], acc[hp]);
            acc[hp] = f2fma(gi2, eb[h * MX + kx], acc[hp]);
        }
    }
    ull* Qg = g_Q + (size_t)bo * 4096;
    #pragma unroll
    for (int hp = 0; hp < 16; hp++)
        Qg[(size_t)(hp * 16 + hg) * MX + ky] = acc[hp];
}

// -------------------- HMMA layer kernel -------------------------------------
// smem layout (bytes):
#define AHI 0
#define ALO 26624
#define BHI 53248
#define BLO 66560
#define STG 79872          // f32 [64][260] = 66560 B
#define MSC 146432         // bias (64 f32)
#define SMEM_G 146944

template <bool LAST>
__global__ __launch_bounds__(256, 1)
void k_gemm(const u32* __restrict__ actin, u32* __restrict__ actout,
            const float* __restrict__ pw_b, int l,
            float* __restrict__ out,
            const float* __restrict__ o1w, const float* __restrict__ o1b,
            const float* __restrict__ o2w, const float* __restrict__ o2b) {
    extern __shared__ __align__(16) char sm[];
    int h = blockIdx.x, b = blockIdx.y, t = threadIdx.x;
    int warp = t >> 5, lane = t & 31;
    u16* aH = (u16*)(sm + AHI);
    u16* aL = (u16*)(sm + ALO);
    u16* bHs = (u16*)(sm + BHI);
    u16* bLs = (u16*)(sm + BLO);
    float* stag = (float*)(sm + STG);
    float* bias = (float*)(sm + MSC);
    u32 sa = smem_u32(sm);

    // B: pointwise weights (cols 0..63)
    for (int i = t; i < 4096; i += 256) {
        int o = i >> 6, c = i & 63;
        bHs[o * LDA + c] = g_PwH[l * 4096 + i];
        bLs[o * LDA + c] = g_PwL[l * 4096 + i];
    }
    // B: Q (cols 64..95): (q_re, -q_im)
    {
        const ull* Qg = g_Q + ((size_t)(b * 64)) * 4096 + h * 16;
        for (int i = t; i < 1024; i += 256) {
            int o = i >> 4, ky = i & 15;
            float re, im; upk(Qg[(size_t)o * 4096 + ky], re, im);
            u16 rh, rl, ih, il;
            split1(re, rh, rl);
            split1(-im, ih, il);
            bHs[o * LDA + 64 + 2 * ky] = rh;  bLs[o * LDA + 64 + 2 * ky] = rl;
            bHs[o * LDA + 65 + 2 * ky] = ih;  bLs[o * LDA + 65 + 2 * ky] = il;
        }
    }
    if (t < 64) bias[t] = pw_b[t];

    int mg = warp & 3, ng = warp >> 2;
    int aRow = (lane & 7) + ((lane >> 3) & 1) * 8;
    int aKq = (lane >> 4) * 8;
    int bSel = (lane >> 4) & 1;
    int bN = lane & 7;
    int bKq = ((lane >> 3) & 1) * 8;

    for (int wv = 0; wv < 2; wv++) {
        // A: activations (cols 0..63)
        const u32* src = actin + ((size_t)(b * 256 + h)) * 16384 + wv * 8192;
        for (int i = t; i < 8192; i += 256) {
            u32 v = src[i];
            int w = i >> 6, c = i & 63;
            aH[w * LDA + c] = (u16)v;
            aL[w * LDA + c] = (u16)(v >> 16);
        }
        // A: synthesis twiddles (cols 64..95)
        for (int i = t; i < 4096; i += 256) {
            int w = i >> 5, j = i & 31;
            aH[w * LDA + 64 + j] = g_SynH[(wv * 128 + w) * 32 + j];
            aL[w * LDA + 64 + j] = g_SynL[(wv * 128 + w) * 32 + j];
        }
        __syncthreads();

        float d[2][4][4];
        #pragma unroll
        for (int i1 = 0; i1 < 2; i1++)
            #pragma unroll
            for (int i2 = 0; i2 < 4; i2++)
                #pragma unroll
                for (int i3 = 0; i3 < 4; i3++) d[i1][i2][i3] = 0.0f;

        #pragma unroll
        for (int k6 = 0; k6 < 6; k6++) {
            int k0 = k6 * 16;
            u32 ah[2][4], al[2][4];
            #pragma unroll
            for (int mt = 0; mt < 2; mt++) {
                u32 ad = (u32)((32 * mg + mt * 16 + aRow) * LDA + k0 + aKq) * 2;
                ldmx4(ah[mt], sa + AHI + ad);
                ldmx4(al[mt], sa + ALO + ad);
            }
            #pragma unroll
            for (int np = 0; np < 2; np++) {
                int q0 = ng * 4 + np * 2;
                u32 bd = (u32)(((q0 + bSel) * 8 + bN) * LDA + k0 + bKq) * 2;
                u32 bh4[4], bl4[4];
                ldmx4(bh4, sa + BHI + bd);
                ldmx4(bl4, sa + BLO + bd);
                #pragma unroll
                for (int sub = 0; sub < 2; sub++) {
                    int nt = np * 2 + sub;
                    #pragma unroll
                    for (int mt = 0; mt < 2; mt++) {
                        mma16816(d[mt][nt], ah[mt], bh4[2 * sub], bh4[2 * sub + 1]);
                        mma16816(d[mt][nt], ah[mt], bl4[2 * sub], bl4[2 * sub + 1]);
                        mma16816(d[mt][nt], al[mt], bh4[2 * sub], bh4[2 * sub + 1]);
                    }
                }
            }
        }
        // epilogue: bias + gelu -> stag
        int g = lane >> 2, c2 = lane & 3;
        #pragma unroll
        for (int mt = 0; mt < 2; mt++) {
            int wb = wv * 128 + 32 * mg + mt * 16 + g;
            #pragma unroll
            for (int nt = 0; nt < 4; nt++) {
                int ob = (ng * 4 + nt) * 8 + 2 * c2;
                stag[ob * 260 + wb]           = gelu_exact(d[mt][nt][0] + bias[ob]);
                stag[(ob + 1) * 260 + wb]     = gelu_exact(d[mt][nt][1] + bias[ob + 1]);
                stag[ob * 260 + wb + 8]       = gelu_exact(d[mt][nt][2] + bias[ob]);
                stag[(ob + 1) * 260 + wb + 8] = gelu_exact(d[mt][nt][3] + bias[ob + 1]);
            }
        }
        __syncthreads();
    }

    if (!LAST) {
        u32* dst = actout + ((size_t)(b * 256 + h)) * 16384;
        for (int i = t; i < 16384; i += 256) {
            int w = i >> 6, c = i & 63;
            u16 hi, lo; split1(stag[c * 260 + w], hi, lo);
            dst[i] = (u32)hi | ((u32)lo << 16);
        }
        epilogue_fwd_w(stag, sm, b, h, t);
    } else {
        float* w1s = (float*)sm;           // 2048 f32 (overlays A region, done with it)
        float* b1s = (float*)(sm + 8192);
        float* w2s = (float*)(sm + 8320);
        for (int i = t; i < 2048; i += 256) w1s[i] = o1w[i];
        if (t < 32) { b1s[t] = o1b[t]; w2s[t] = o2w[t]; }
        __syncthreads();
        ull x2[32];
        #pragma unroll
        for (int j = 0; j < 32; j++)
            x2[j] = pk(stag[(2 * j) * 260 + t], stag[(2 * j + 1) * 260 + t]);
        float acc = __ldg(o2b);
        for (int o2 = 0; o2 < 32; o2++) {
            ull s = pk(b1s[o2], 0.0f);
            const ulonglong2* wv2 = (const ulonglong2*)(w1s + o2 * 64);
            #pragma unroll
            for (int j = 0; j < 16; j++) {
                ulonglong2 p = wv2[j];
                s = f2fma(p.x, x2[2 * j], s);
                s = f2fma(p.y, x2[2 * j + 1], s);
            }
            float lo, hi; upk(s, lo, hi);
            acc = fmaf(w2s[o2], gelu_exact(lo + hi), acc);
        }
        out[((size_t)(b * 256 + h)) * 256 + t] = acc;
    }
}

// ---------------------------------------------------------------------------
extern "C" void kernel_launch(void* const* d_in, const int* in_sizes, int n_in,
                              void* d_out, int out_size) {
    const float* x       = (const float*)d_in[0];
    const float* in_w    = (const float*)d_in[1];
    const float* in_b    = (const float*)d_in[2];
    const float* spec_wr = (const float*)d_in[3];
    const float* spec_wi = (const float*)d_in[4];
    const float* pw_w    = (const float*)d_in[5];
    const float* pw_b    = (const float*)d_in[6];
    const float* o1w     = (const float*)d_in[7];
    const float* o1b     = (const float*)d_in[8];
    const float* o2w     = (const float*)d_in[9];
    const float* o2b     = (const float*)d_in[10];
    float* out = (float*)d_out;

    const int SMEM_LIFT = 99840;
    const int SMEM_FH   = 98304;
    const int SMEM_IH   = 67584;
    cudaFuncSetAttribute(k_lift, cudaFuncAttributeMaxDynamicSharedMemorySize, SMEM_LIFT);
    cudaFuncSetAttribute(k_gemm<false>, cudaFuncAttributeMaxDynamicSharedMemorySize, SMEM_G);
    cudaFuncSetAttribute(k_gemm<true>,  cudaFuncAttributeMaxDynamicSharedMemorySize, SMEM_G);
    cudaFuncSetAttribute(k_fwd_h, cudaFuncAttributeMaxDynamicSharedMemorySize, SMEM_FH);
    cudaFuncSetAttribute(k_inv_h, cudaFuncAttributeMaxDynamicSharedMemorySize, SMEM_IH);

    u32 *actA, *actB;
    cudaGetSymbolAddress((void**)&actA, g_actA);
    cudaGetSymbolAddress((void**)&actB, g_actB);

    k_tables<<<16, 256>>>();
    k_tables2<<<8, 256>>>();
    k_prep_pw<<<64, 256>>>(pw_w);
    k_prep_syn<<<32, 256>>>();
    k_twt<<<dim3(128, 8, NL4), dim3(32, 8)>>>(spec_wr, spec_wi);

    dim3 grid(Hh, Bb);
    k_lift<<<grid, 256, SMEM_LIFT>>>(x, in_w, in_b);

    const u32* cur = actA;
    u32* nxt = actB;
    for (int l = 0; l < NL4; l++) {
        k_fwd_h<<<Bb * C0, 256, SMEM_FH>>>();
        k_modegemm<<<256, 512>>>(l);
        k_inv_h<<<Bb * C0, 256, SMEM_IH>>>();
        if (l < NL4 - 1) {
            k_gemm<false><<<grid, 256, SMEM_G>>>(cur, nxt, pw_b + l * 64, l,
                                                 nullptr, nullptr, nullptr, nullptr, nullptr);
            const u32* tmp = cur; cur = nxt; nxt = (u32*)tmp;
        } else {
            k_gemm<true><<<grid, 256, SMEM_G>>>(cur, nullptr, pw_b + l * 64, l,
                                                out, o1w, o1b, o2w, o2b);
        }
    }
}

// round 6
// speedup vs baseline: 1.8186x; 1.8186x over previous
#include <cuda_runtime.h>
#include <cuda_bf16.h>
#include <math.h>
#include <stdint.h>

#define Bb 8
#define C0 64
#define Hh 256
#define Ww 256
#define MX 16
#define NL4 4
#define HW 65536
#define LDA 104

typedef unsigned long long ull;
typedef unsigned int u32;
typedef unsigned short u16;

// -------------------- helpers ----------------------------------------------
__device__ __forceinline__ ull pk(float lo, float hi) {
    ull r; asm("mov.b64 %0,{%1,%2};" : "=l"(r) : "f"(lo), "f"(hi)); return r;
}
__device__ __forceinline__ void upk(ull v, float& lo, float& hi) {
    asm("mov.b64 {%0,%1},%2;" : "=f"(lo), "=f"(hi) : "l"(v));
}
__device__ __forceinline__ ull f2fma(ull a, ull b, ull c) {
    ull d; asm("fma.rn.f32x2 %0,%1,%2,%3;" : "=l"(d) : "l"(a), "l"(b), "l"(c)); return d;
}
__device__ __forceinline__ void split1(float v, u16& hi, u16& lo) {
    __nv_bfloat16 h = __float2bfloat16(v);
    hi = __bfloat16_as_ushort(h);
    lo = __bfloat16_as_ushort(__float2bfloat16(v - __bfloat162float(h)));
}
__device__ __forceinline__ u32 smem_u32(const void* p) {
    u32 a; asm("{ .reg .u64 t; cvta.to.shared.u64 t, %1; cvt.u32.u64 %0, t; }" : "=r"(a) : "l"(p));
    return a;
}
__device__ __forceinline__ void ldmx4(u32* r, u32 addr) {
    asm volatile("ldmatrix.sync.aligned.m8n8.x4.shared.b16 {%0,%1,%2,%3},[%4];"
        : "=r"(r[0]), "=r"(r[1]), "=r"(r[2]), "=r"(r[3]) : "r"(addr));
}
__device__ __forceinline__ void ldmx4t(u32* r, u32 addr) {
    asm volatile("ldmatrix.sync.aligned.m8n8.x4.trans.shared.b16 {%0,%1,%2,%3},[%4];"
        : "=r"(r[0]), "=r"(r[1]), "=r"(r[2]), "=r"(r[3]) : "r"(addr));
}
__device__ __forceinline__ void mma16816(float* d, const u32* a, u32 b0, u32 b1) {
    asm volatile("mma.sync.aligned.m16n8k16.row.col.f32.bf16.bf16.f32 "
        "{%0,%1,%2,%3},{%4,%5,%6,%7},{%8,%9},{%0,%1,%2,%3};"
        : "+f"(d[0]), "+f"(d[1]), "+f"(d[2]), "+f"(d[3])
        : "r"(a[0]), "r"(a[1]), "r"(a[2]), "r"(a[3]), "r"(b0), "r"(b1));
}
__device__ __forceinline__ float gelu_exact(float z) {
    return 0.5f * z * (1.0f + erff(z * 0.70710678118654752f));
}

// -------------------- globals -----------------------------------------------
__device__ u32 g_actA[(size_t)Bb * HW * C0];
__device__ u32 g_actB[(size_t)Bb * HW * C0];
__device__ ull g_T [(size_t)Bb * C0 * Hh * MX];
__device__ ull g_Xf[(size_t)Bb * C0 * 256];
__device__ ull g_G [(size_t)256 * Bb * C0];
__device__ ull g_Q [(size_t)Bb * C0 * Hh * MX];
__device__ ull g_W2[(size_t)NL4 * 256 * 4096];
__device__ ull g_Fh2a[MX * Hh], g_Fh2b[MX * Hh];
__device__ ull g_Eh2a[Hh * MX], g_Eh2b[Hh * MX];
__device__ u16 g_PwH[NL4 * 4096], g_PwL[NL4 * 4096];
__device__ u16 g_SynH[256 * 32], g_SynL[256 * 32];
__device__ u16 g_FwAh[32 * 256], g_FwAl[32 * 256];   // fwd-DFT A op [2ky+ri][w]

// -------------------- prep kernels ------------------------------------------
__global__ void k_tables() {
    int idx = blockIdx.x * 256 + threadIdx.x;
    int a = idx >> 8, p = idx & 255, m = (a * p) & 255;
    float s, c; sincospif((float)m * (1.0f / 128.0f), &s, &c);
    g_Fh2a[idx] = pk(c, -s);  g_Fh2b[idx] = pk(s, c);
    g_Eh2a[p * MX + a] = pk(c, s);  g_Eh2b[p * MX + a] = pk(-s, c);
}
__global__ void k_prep_pw(const float* __restrict__ pw_w) {
    int i = blockIdx.x * 256 + threadIdx.x;
    u16 h, l; split1(pw_w[i], h, l);
    g_PwH[i] = h; g_PwL[i] = l;
}
__global__ void k_prep_syn() {
    int i = blockIdx.x * 256 + threadIdx.x;   // 0..8191
    int w = i >> 5, j = i & 31, ky = j >> 1, ri = j & 1;
    float s, c; sincospif((float)((ky * w) & 255) * (1.0f / 128.0f), &s, &c);
    float ck = ((ky == 0) ? 1.0f : 2.0f) * (1.0f / 256.0f);
    float v = ri ? s * ck : c * ck;
    u16 h, l; split1(v, h, l);
    g_SynH[i] = h; g_SynL[i] = l;
}
__global__ void k_prep_fwa() {
    int idx = blockIdx.x * 256 + threadIdx.x;   // 0..8191
    int row = idx >> 8, w = idx & 255, ky = row >> 1, ri = row & 1;
    float s, c; sincospif((float)((ky * w) & 255) * (1.0f / 128.0f), &s, &c);
    float v = (ri ? -s : c) * (1.0f / 256.0f);
    u16 h, l; split1(v, h, l);
    g_FwAh[idx] = h; g_FwAl[idx] = l;
}
__global__ void k_twt(const float* __restrict__ wr, const float* __restrict__ wi) {
    __shared__ ull tile[32][33];
    int l = blockIdx.z, tio = blockIdx.x, tm = blockIdx.y;
    int tx = threadIdx.x, ty = threadIdx.y;
    const float* wrl = wr + (size_t)l * 4096 * 256;
    const float* wil = wi + (size_t)l * 4096 * 256;
    #pragma unroll
    for (int r = 0; r < 4; r++) {
        int row = tio * 32 + ty + 8 * r, col = tm * 32 + tx;
        size_t idx = (size_t)row * 256 + col;
        tile[ty + 8 * r][tx] = pk(wrl[idx], wil[idx]);
    }
    __syncthreads();
    #pragma unroll
    for (int r = 0; r < 4; r++) {
        int mm = tm * 32 + ty + 8 * r, io = tio * 32 + tx;
        g_W2[(((size_t)l * 256) + mm) * 4096 + io] = tile[tx][ty + 8 * r];
    }
}

// -------------------- spectral trio (proven) --------------------------------
__global__ __launch_bounds__(256, 2) void k_fwd_h() {
    extern __shared__ __align__(16) char smraw[];
    ull* Ts = (ull*)smraw;
    ull* fa = Ts + 4096;
    ull* fb = fa + 4096;
    int bc = blockIdx.x, t = threadIdx.x;
    const ull* Tg = g_T + (size_t)bc * 4096;
    for (int i = t; i < 4096; i += 256) { Ts[i] = Tg[i]; fa[i] = g_Fh2a[i]; fb[i] = g_Fh2b[i]; }
    __syncthreads();
    int kx = t >> 4, ky = t & 15;
    const ull* fak = fa + kx * 256;
    const ull* fbk = fb + kx * 256;
    ull acc = 0ull;
    for (int h = 0; h < Hh; h++) {
        float tr, ti; upk(Ts[h * MX + ky], tr, ti);
        acc = f2fma(pk(tr, tr), fak[h], acc);
        acc = f2fma(pk(ti, ti), fbk[h], acc);
    }
    g_Xf[(size_t)bc * 256 + t] = acc;
}
__global__ __launch_bounds__(512, 2) void k_modegemm(int l) {
    __shared__ __align__(16) ull ws[4096];
    __shared__ ull xA[512], xB[512];
    int m = blockIdx.x, t = threadIdx.x;
    const ull* W = g_W2 + (((size_t)l * 256) + m) * 4096;
    for (int i = t; i < 4096; i += 512) ws[i] = W[i];
    {
        int b = t >> 6, i = t & 63;
        float xr, xi; upk(g_Xf[((size_t)b * C0 + i) * 256 + m], xr, xi);
        xA[t] = pk(xr, xr);
        xB[t] = pk(-xi, xi);
    }
    __syncthreads();
    int b = t >> 6, o = t & 63;
    ull acc = 0ull;
    const ull* xa = xA + b * 64;
    const ull* xb = xB + b * 64;
    #pragma unroll 4
    for (int i = 0; i < C0; i++) {
        ull w2 = ws[i * 64 + o];
        float wr, wi; upk(w2, wr, wi);
        acc = f2fma(xa[i], w2, acc);
        acc = f2fma(xb[i], pk(wi, wr), acc);
    }
    g_G[(size_t)m * 512 + t] = acc;
}
__global__ __launch_bounds__(256, 2) void k_inv_h() {
    extern __shared__ __align__(16) char smraw[];
    ull* Gs = (ull*)smraw;
    ull* ea = Gs + 256;
    ull* eb = ea + 4096;
    int bo = blockIdx.x, t = threadIdx.x;
    for (int i = t; i < 256; i += 256) Gs[i] = g_G[(size_t)i * 512 + bo];
    for (int i = t; i < 4096; i += 256) { ea[i] = g_Eh2a[i]; eb[i] = g_Eh2b[i]; }
    __syncthreads();
    int hg = t >> 4, ky = t & 15;
    ull acc[16];
    #pragma unroll
    for (int i = 0; i < 16; i++) acc[i] = 0ull;
    #pragma unroll
    for (int kx = 0; kx < MX; kx++) {
        float gr, gi; upk(Gs[kx * MX + ky], gr, gi);
        ull gr2 = pk(gr, gr), gi2 = pk(gi, gi);
        #pragma unroll
        for (int hp = 0; hp < 16; hp++) {
            int h = hp * 16 + hg;
            acc[hp] = f2fma(gr2, ea[h * MX + kx], acc[hp]);
            acc[hp] = f2fma(gi2, eb[h * MX + kx], acc[hp]);
        }
    }
    ull* Qg = g_Q + (size_t)bo * 4096;
    #pragma unroll
    for (int hp = 0; hp < 16; hp++)
        Qg[(size_t)(hp * 16 + hg) * MX + ky] = acc[hp];
}

// -------------------- fused HMMA layer kernel -------------------------------
// smem (bytes):
#define AHI 0          // 26624 = 128*104*2
#define ALO 26624      // 26624
#define BHI 53248      // 13312 = 64*104*2
#define BLO 66560      // 13312
#define FWH 79872      // 8704 = 32*136*2
#define FWL 88576      // 8704
#define MSC 97280      // 3072
#define SMEM_G 100352

// MODE: 0 = lift, 1 = mid layer, 2 = last layer (+head)
template <int MODE>
__global__ __launch_bounds__(256, 2)
void k_gemm(const u32* __restrict__ actin, u32* __restrict__ actout,
            const float* __restrict__ pw_b, int l,
            const float* __restrict__ x, const float* __restrict__ in_w,
            const float* __restrict__ in_b,
            float* __restrict__ out,
            const float* __restrict__ o1w, const float* __restrict__ o1b,
            const float* __restrict__ o2w, const float* __restrict__ o2b) {
    extern __shared__ __align__(16) char sm[];
    int h = blockIdx.x, b = blockIdx.y, t = threadIdx.x;
    int warp = t >> 5, lane = t & 31;
    u16* aH = (u16*)(sm + AHI);
    u16* aL = (u16*)(sm + ALO);
    u16* bHs = (u16*)(sm + BHI);
    u16* bLs = (u16*)(sm + BLO);
    u16* fwh = (u16*)(sm + FWH);
    u16* fwl = (u16*)(sm + FWL);
    float* bias = (float*)(sm + MSC);
    float* iwS  = (float*)(sm + MSC + 256);
    float* ibS  = (float*)(sm + MSC + 768);
    float* x0s  = (float*)(sm + MSC + 1024);
    float* x1s  = (float*)(sm + MSC + 1536);
    float* psum = (float*)(sm + MSC + 2048);
    u32 sa = smem_u32(sm);

    // ---- pre-loop staging ----
    if (MODE == 0) {
        if (t < 128) iwS[t] = in_w[t];
        if (t < 64) ibS[t] = in_b[t];
    } else {
        for (int i = t; i < 4096; i += 256) {
            int o = i >> 6, c = i & 63;
            bHs[o * LDA + c] = g_PwH[l * 4096 + i];
            bLs[o * LDA + c] = g_PwL[l * 4096 + i];
        }
        const ull* Qg = g_Q + ((size_t)(b * 64)) * 4096 + h * 16;
        for (int i = t; i < 1024; i += 256) {
            int o = i >> 4, ky = i & 15;
            float re, im; upk(Qg[(size_t)o * 4096 + ky], re, im);
            u16 rh, rl, ih, il;
            split1(re, rh, rl);
            split1(-im, ih, il);
            bHs[o * LDA + 64 + 2 * ky] = rh;  bLs[o * LDA + 64 + 2 * ky] = rl;
            bHs[o * LDA + 65 + 2 * ky] = ih;  bLs[o * LDA + 65 + 2 * ky] = il;
        }
        if (t < 64) bias[t] = pw_b[t];
        if (MODE == 2) {
            float* w1s = (float*)(sm + FWH);
            float* b1s = (float*)(sm + FWH + 8192);
            float* w2s = (float*)(sm + FWH + 8320);
            for (int i = t; i < 2048; i += 256) w1s[i] = o1w[i];
            if (t < 32) { b1s[t] = o1b[t]; w2s[t] = o2w[t]; }
        }
    }

    int mg = warp & 3, ng = warp >> 2;
    int aRow = (lane & 7) + ((lane >> 3) & 1) * 8;
    int aKq = (lane >> 4) * 8;
    int bSel = (lane >> 4) & 1, bN = lane & 7, bKq = ((lane >> 3) & 1) * 8;
    int mt2 = warp & 1, ng2 = warp >> 1;
    int trow = lane & 7, khalf = (lane >> 3) & 1, chalf = (lane >> 4) & 1;

    float dT[2][4];
    if (MODE != 2) {
        #pragma unroll
        for (int i1 = 0; i1 < 2; i1++)
            #pragma unroll
            for (int i2 = 0; i2 < 4; i2++) dT[i1][i2] = 0.0f;
    }

    for (int wv = 0; wv < 2; wv++) {
        // ---- A staging ----
        if (MODE == 0) {
            if (t < 128) x0s[t] = x[(((size_t)(b * 2)) * 256 + h) * 256 + wv * 128 + t];
            else x1s[t - 128] = x[(((size_t)(b * 2 + 1)) * 256 + h) * 256 + wv * 128 + (t - 128)];
            __syncthreads();
            for (int i = t; i < 8192; i += 256) {
                int w = i >> 6, c = i & 63;
                float v = fmaf(iwS[2 * c], x0s[w], fmaf(iwS[2 * c + 1], x1s[w], ibS[c]));
                u16 hi, lo; split1(v, hi, lo);
                aH[w * LDA + c] = hi; aL[w * LDA + c] = lo;
            }
        } else {
            const u32* src = actin + ((size_t)(b * 256 + h)) * 16384 + wv * 8192;
            for (int i = t; i < 8192; i += 256) {
                u32 v = src[i];
                int w = i >> 6, c = i & 63;
                aH[w * LDA + c] = (u16)v;
                aL[w * LDA + c] = (u16)(v >> 16);
            }
            for (int i = t; i < 4096; i += 256) {
                int w = i >> 5, j = i & 31;
                aH[w * LDA + 64 + j] = g_SynH[(wv * 128 + w) * 32 + j];
                aL[w * LDA + 64 + j] = g_SynL[(wv * 128 + w) * 32 + j];
            }
        }
        if (MODE != 2) {
            for (int i = t; i < 4096; i += 256) {
                int r = i >> 7, kc = i & 127;
                fwh[r * 136 + kc] = g_FwAh[r * 256 + wv * 128 + kc];
                fwl[r * 136 + kc] = g_FwAl[r * 256 + wv * 128 + kc];
            }
        }
        __syncthreads();   // S1: tiles ready

        if (MODE >= 1) {
            // ---- main MMA: D[128w x 64o], K=96, 3-pass hi/lo ----
            float d[2][4][4];
            #pragma unroll
            for (int i1 = 0; i1 < 2; i1++)
                #pragma unroll
                for (int i2 = 0; i2 < 4; i2++)
                    #pragma unroll
                    for (int i3 = 0; i3 < 4; i3++) d[i1][i2][i3] = 0.0f;
            #pragma unroll
            for (int k6 = 0; k6 < 6; k6++) {
                int k0 = k6 * 16;
                u32 ah[2][4], al[2][4];
                #pragma unroll
                for (int mt = 0; mt < 2; mt++) {
                    u32 ad = (u32)((32 * mg + mt * 16 + aRow) * LDA + k0 + aKq) * 2;
                    ldmx4(ah[mt], sa + AHI + ad);
                    ldmx4(al[mt], sa + ALO + ad);
                }
                #pragma unroll
                for (int np = 0; np < 2; np++) {
                    int q0 = ng * 4 + np * 2;
                    u32 bd = (u32)(((q0 + bSel) * 8 + bN) * LDA + k0 + bKq) * 2;
                    u32 bh4[4], bl4[4];
                    ldmx4(bh4, sa + BHI + bd);
                    ldmx4(bl4, sa + BLO + bd);
                    #pragma unroll
                    for (int sub = 0; sub < 2; sub++) {
                        int nt = np * 2 + sub;
                        #pragma unroll
                        for (int mt = 0; mt < 2; mt++) {
                            mma16816(d[mt][nt], ah[mt], bh4[2 * sub], bh4[2 * sub + 1]);
                            mma16816(d[mt][nt], ah[mt], bl4[2 * sub], bl4[2 * sub + 1]);
                            mma16816(d[mt][nt], al[mt], bh4[2 * sub], bh4[2 * sub + 1]);
                        }
                    }
                }
            }
            __syncthreads();   // S2: A input consumed

            // ---- epilogue ----
            int g = lane >> 2, c2 = lane & 3;
            if (MODE == 1) {
                #pragma unroll
                for (int mt = 0; mt < 2; mt++) {
                    int wl = 32 * mg + mt * 16 + g;
                    #pragma unroll
                    for (int nt = 0; nt < 4; nt++) {
                        int ob = (ng * 4 + nt) * 8 + 2 * c2;
                        float v0 = gelu_exact(d[mt][nt][0] + bias[ob]);
                        float v1 = gelu_exact(d[mt][nt][1] + bias[ob + 1]);
                        float v2 = gelu_exact(d[mt][nt][2] + bias[ob]);
                        float v3 = gelu_exact(d[mt][nt][3] + bias[ob + 1]);
                        u16 hi, lo;
                        split1(v0, hi, lo); aH[wl * LDA + ob] = hi;           aL[wl * LDA + ob] = lo;
                        split1(v1, hi, lo); aH[wl * LDA + ob + 1] = hi;       aL[wl * LDA + ob + 1] = lo;
                        split1(v2, hi, lo); aH[(wl + 8) * LDA + ob] = hi;     aL[(wl + 8) * LDA + ob] = lo;
                        split1(v3, hi, lo); aH[(wl + 8) * LDA + ob + 1] = hi; aL[(wl + 8) * LDA + ob + 1] = lo;
                    }
                }
            } else {
                float* stagf = (float*)(sm + AHI);   // [128][68]
                #pragma unroll
                for (int mt = 0; mt < 2; mt++) {
                    int wl = 32 * mg + mt * 16 + g;
                    #pragma unroll
                    for (int nt = 0; nt < 4; nt++) {
                        int ob = (ng * 4 + nt) * 8 + 2 * c2;
                        stagf[wl * 68 + ob]           = gelu_exact(d[mt][nt][0] + bias[ob]);
                        stagf[wl * 68 + ob + 1]       = gelu_exact(d[mt][nt][1] + bias[ob + 1]);
                        stagf[(wl + 8) * 68 + ob]     = gelu_exact(d[mt][nt][2] + bias[ob]);
                        stagf[(wl + 8) * 68 + ob + 1] = gelu_exact(d[mt][nt][3] + bias[ob + 1]);
                    }
                }
            }
            __syncthreads();   // S3: outputs staged
        }

        if (MODE != 2) {
            // ---- act gmem store ----
            u32* dst = actout + ((size_t)(b * 256 + h)) * 16384 + wv * 8192;
            for (int i = t; i < 8192; i += 256) {
                int w = i >> 6, c = i & 63;
                dst[i] = (u32)aH[w * LDA + c] | ((u32)aL[w * LDA + c] << 16);
            }
            // ---- fwd-w DFT GEMM: dT[32][64] += Fw[32][128] . act[128][64] ----
            #pragma unroll
            for (int ks = 0; ks < 8; ks++) {
                int k0 = ks * 16;
                u32 fh[4], fl[4], bh[4], bl[4];
                u32 fad = (u32)((mt2 * 16 + aRow) * 136 + k0 + aKq) * 2;
                ldmx4(fh, sa + FWH + fad);
                ldmx4(fl, sa + FWL + fad);
                u32 bad = (u32)((k0 + khalf * 8 + trow) * LDA + ng2 * 16 + chalf * 8) * 2;
                ldmx4t(bh, sa + AHI + bad);
                ldmx4t(bl, sa + ALO + bad);
                #pragma unroll
                for (int nt = 0; nt < 2; nt++) {
                    u32 b0 = bh[2 * nt], b1 = bh[2 * nt + 1];
                    u32 c0 = bl[2 * nt], c1 = bl[2 * nt + 1];
                    mma16816(dT[nt], fh, b0, b1);
                    mma16816(dT[nt], fh, c0, c1);
                    mma16816(dT[nt], fl, b0, b1);
                }
            }
            __syncthreads();   // S4: A consumed, safe for next wave
        } else {
            // ---- head ----
            float* stagf = (float*)(sm + AHI);
            float* w1s = (float*)(sm + FWH);
            float* b1s = (float*)(sm + FWH + 8192);
            float* w2s = (float*)(sm + FWH + 8320);
            int p = t & 127, hf = t >> 7;
            ull x2[32];
            const float2* xr = (const float2*)(stagf + p * 68);
            #pragma unroll
            for (int j = 0; j < 32; j++) {
                float2 xx = xr[j];
                x2[j] = pk(xx.x, xx.y);
            }
            float acc = hf ? 0.0f : __ldg(o2b);
            for (int o2 = hf * 16; o2 < hf * 16 + 16; o2++) {
                ull s = pk(b1s[o2], 0.0f);
                const ulonglong2* wv2 = (const ulonglong2*)(w1s + o2 * 64);
                #pragma unroll
                for (int j = 0; j < 16; j++) {
                    ulonglong2 p4 = wv2[j];
                    s = f2fma(p4.x, x2[2 * j], s);
                    s = f2fma(p4.y, x2[2 * j + 1], s);
                }
                float lo, hi; upk(s, lo, hi);
                acc = fmaf(w2s[o2], gelu_exact(lo + hi), acc);
            }
            psum[hf * 128 + p] = acc;
            __syncthreads();   // S4
            if (t < 128)
                out[((size_t)(b * 256 + h)) * 256 + wv * 128 + t] = psum[t] + psum[128 + t];
            __syncthreads();   // S5: psum/stagf free for next wave
        }
    }

    if (MODE != 2) {
        // ---- store T ----
        float* Tf = (float*)g_T;
        int g = lane >> 2, c2 = lane & 3;
        #pragma unroll
        for (int nt = 0; nt < 2; nt++) {
            #pragma unroll
            for (int pr = 0; pr < 2; pr++) {
                int row = mt2 * 16 + g + pr * 8;
                int ky = row >> 1, ri = row & 1;
                int c = ng2 * 16 + nt * 8 + 2 * c2;
                size_t bse = (((size_t)(b * 64 + c)) * 256 + h) * 32 + ky * 2 + ri;
                Tf[bse] = dT[nt][pr * 2 + 0];
                Tf[bse + 8192] = dT[nt][pr * 2 + 1];
            }
        }
    }
}

// ---------------------------------------------------------------------------
extern "C" void kernel_launch(void* const* d_in, const int* in_sizes, int n_in,
                              void* d_out, int out_size) {
    const float* x       = (const float*)d_in[0];
    const float* in_w    = (const float*)d_in[1];
    const float* in_b    = (const float*)d_in[2];
    const float* spec_wr = (const float*)d_in[3];
    const float* spec_wi = (const float*)d_in[4];
    const float* pw_w    = (const float*)d_in[5];
    const float* pw_b    = (const float*)d_in[6];
    const float* o1w     = (const float*)d_in[7];
    const float* o1b     = (const float*)d_in[8];
    const float* o2w     = (const float*)d_in[9];
    const float* o2b     = (const float*)d_in[10];
    float* out = (float*)d_out;

    const int SMEM_FH = 98304;
    const int SMEM_IH = 67584;
    cudaFuncSetAttribute(k_gemm<0>, cudaFuncAttributeMaxDynamicSharedMemorySize, SMEM_G);
    cudaFuncSetAttribute(k_gemm<1>, cudaFuncAttributeMaxDynamicSharedMemorySize, SMEM_G);
    cudaFuncSetAttribute(k_gemm<2>, cudaFuncAttributeMaxDynamicSharedMemorySize, SMEM_G);
    cudaFuncSetAttribute(k_fwd_h, cudaFuncAttributeMaxDynamicSharedMemorySize, SMEM_FH);
    cudaFuncSetAttribute(k_inv_h, cudaFuncAttributeMaxDynamicSharedMemorySize, SMEM_IH);

    u32 *actA, *actB;
    cudaGetSymbolAddress((void**)&actA, g_actA);
    cudaGetSymbolAddress((void**)&actB, g_actB);

    k_tables<<<16, 256>>>();
    k_prep_pw<<<64, 256>>>(pw_w);
    k_prep_syn<<<32, 256>>>();
    k_prep_fwa<<<32, 256>>>();
    k_twt<<<dim3(128, 8, NL4), dim3(32, 8)>>>(spec_wr, spec_wi);

    dim3 grid(Hh, Bb);
    k_gemm<0><<<grid, 256, SMEM_G>>>(nullptr, actA, nullptr, 0,
                                     x, in_w, in_b, nullptr,
                                     nullptr, nullptr, nullptr, nullptr);

    const u32* cur = actA;
    u32* nxt = actB;
    for (int l = 0; l < NL4; l++) {
        k_fwd_h<<<Bb * C0, 256, SMEM_FH>>>();
        k_modegemm<<<256, 512>>>(l);
        k_inv_h<<<Bb * C0, 256, SMEM_IH>>>();
        if (l < NL4 - 1) {
            k_gemm<1><<<grid, 256, SMEM_G>>>(cur, nxt, pw_b + l * 64, l,
                                             nullptr, nullptr, nullptr, nullptr,
                                             nullptr, nullptr, nullptr, nullptr);
            const u32* tmp = cur; cur = nxt; nxt = (u32*)tmp;
        } else {
            k_gemm<2><<<grid, 256, SMEM_G>>>(cur, nullptr, pw_b + l * 64, l,
                                             nullptr, nullptr, nullptr, out,
                                             o1w, o1b, o2w, o2b);
        }
    }
}

// round 7
// speedup vs baseline: 2.4121x; 1.3264x over previous
#include <cuda_runtime.h>
#include <cuda_bf16.h>
#include <math.h>
#include <stdint.h>

#define Bb 8
#define C0 64
#define Hh 256
#define Ww 256
#define MX 16
#define NL4 4
#define HW 65536
#define LDA 104

typedef unsigned long long ull;
typedef unsigned int u32;
typedef unsigned short u16;

// -------------------- helpers ----------------------------------------------
__device__ __forceinline__ ull pk(float lo, float hi) {
    ull r; asm("mov.b64 %0,{%1,%2};" : "=l"(r) : "f"(lo), "f"(hi)); return r;
}
__device__ __forceinline__ void upk(ull v, float& lo, float& hi) {
    asm("mov.b64 {%0,%1},%2;" : "=f"(lo), "=f"(hi) : "l"(v));
}
__device__ __forceinline__ ull f2fma(ull a, ull b, ull c) {
    ull d; asm("fma.rn.f32x2 %0,%1,%2,%3;" : "=l"(d) : "l"(a), "l"(b), "l"(c)); return d;
}
__device__ __forceinline__ void split1(float v, u16& hi, u16& lo) {
    __nv_bfloat16 h = __float2bfloat16(v);
    hi = __bfloat16_as_ushort(h);
    lo = __bfloat16_as_ushort(__float2bfloat16(v - __bfloat162float(h)));
}
__device__ __forceinline__ u32 smem_u32(const void* p) {
    u32 a; asm("{ .reg .u64 t; cvta.to.shared.u64 t, %1; cvt.u32.u64 %0, t; }" : "=r"(a) : "l"(p));
    return a;
}
__device__ __forceinline__ void ldmx4(u32* r, u32 addr) {
    asm volatile("ldmatrix.sync.aligned.m8n8.x4.shared.b16 {%0,%1,%2,%3},[%4];"
        : "=r"(r[0]), "=r"(r[1]), "=r"(r[2]), "=r"(r[3]) : "r"(addr));
}
__device__ __forceinline__ void ldmx4t(u32* r, u32 addr) {
    asm volatile("ldmatrix.sync.aligned.m8n8.x4.trans.shared.b16 {%0,%1,%2,%3},[%4];"
        : "=r"(r[0]), "=r"(r[1]), "=r"(r[2]), "=r"(r[3]) : "r"(addr));
}
__device__ __forceinline__ void mma16816(float* d, const u32* a, u32 b0, u32 b1) {
    asm volatile("mma.sync.aligned.m16n8k16.row.col.f32.bf16.bf16.f32 "
        "{%0,%1,%2,%3},{%4,%5,%6,%7},{%8,%9},{%0,%1,%2,%3};"
        : "+f"(d[0]), "+f"(d[1]), "+f"(d[2]), "+f"(d[3])
        : "r"(a[0]), "r"(a[1]), "r"(a[2]), "r"(a[3]), "r"(b0), "r"(b1));
}
__device__ __forceinline__ float gelu_exact(float z) {
    return 0.5f * z * (1.0f + erff(z * 0.70710678118654752f));
}

// -------------------- globals -----------------------------------------------
__device__ u16 g_actAH[(size_t)Bb * HW * C0];   // bf16 hi plane [b][h][w][c]
__device__ u16 g_actAL[(size_t)Bb * HW * C0];   // bf16 lo plane
__device__ u16 g_actBH[(size_t)Bb * HW * C0];
__device__ u16 g_actBL[(size_t)Bb * HW * C0];
__device__ ull g_T [(size_t)Bb * C0 * Hh * MX];
__device__ ull g_Xf[(size_t)Bb * C0 * 256];
__device__ ull g_G [(size_t)256 * Bb * C0];
__device__ u32 g_Qh32[(size_t)Bb * Hh * 1024];  // [(b*256+h)][o][ky]: (reh|imh<<16)
__device__ u32 g_Ql32[(size_t)Bb * Hh * 1024];
__device__ ull g_W2[(size_t)NL4 * 256 * 4096];
__device__ ull g_Fh2a[MX * Hh], g_Fh2b[MX * Hh];
__device__ ull g_Eh2a[Hh * MX], g_Eh2b[Hh * MX];
__device__ u16 g_PwH[NL4 * 4096], g_PwL[NL4 * 4096];
__device__ u16 g_SynH[256 * 32], g_SynL[256 * 32];
__device__ u16 g_FwAh[32 * 256], g_FwAl[32 * 256];

// -------------------- merged prep -------------------------------------------
__global__ void k_prep(const float* __restrict__ pw_w) {
    int idx = blockIdx.x * 256 + threadIdx.x;   // 0..16383
    { u16 h, l; split1(pw_w[idx], h, l); g_PwH[idx] = h; g_PwL[idx] = l; }
    if (idx < 4096) {
        int a = idx >> 8, p = idx & 255, m = (a * p) & 255;
        float s, c; sincospif((float)m * (1.0f / 128.0f), &s, &c);
        g_Fh2a[idx] = pk(c, -s);  g_Fh2b[idx] = pk(s, c);
        g_Eh2a[p * MX + a] = pk(c, s);  g_Eh2b[p * MX + a] = pk(-s, c);
    }
    if (idx < 8192) {
        {   // syn: [w][2ky+ri]
            int w = idx >> 5, j = idx & 31, ky = j >> 1, ri = j & 1;
            float s, c; sincospif((float)((ky * w) & 255) * (1.0f / 128.0f), &s, &c);
            float ck = ((ky == 0) ? 1.0f : 2.0f) * (1.0f / 256.0f);
            float v = ri ? s * ck : c * ck;
            u16 h, l; split1(v, h, l);
            g_SynH[idx] = h; g_SynL[idx] = l;
        }
        {   // fwd-DFT A: [2ky+ri][w]
            int row = idx >> 8, w = idx & 255, ky = row >> 1, ri = row & 1;
            float s, c; sincospif((float)((ky * w) & 255) * (1.0f / 128.0f), &s, &c);
            float v = (ri ? -s : c) * (1.0f / 256.0f);
            u16 h, l; split1(v, h, l);
            g_FwAh[idx] = h; g_FwAl[idx] = l;
        }
    }
}
__global__ void k_twt(const float* __restrict__ wr, const float* __restrict__ wi) {
    __shared__ ull tile[32][33];
    int l = blockIdx.z, tio = blockIdx.x, tm = blockIdx.y;
    int tx = threadIdx.x, ty = threadIdx.y;
    const float* wrl = wr + (size_t)l * 4096 * 256;
    const float* wil = wi + (size_t)l * 4096 * 256;
    #pragma unroll
    for (int r = 0; r < 4; r++) {
        int row = tio * 32 + ty + 8 * r, col = tm * 32 + tx;
        size_t idx = (size_t)row * 256 + col;
        tile[ty + 8 * r][tx] = pk(wrl[idx], wil[idx]);
    }
    __syncthreads();
    #pragma unroll
    for (int r = 0; r < 4; r++) {
        int mm = tm * 32 + ty + 8 * r, io = tio * 32 + tx;
        g_W2[(((size_t)l * 256) + mm) * 4096 + io] = tile[tx][ty + 8 * r];
    }
}

// -------------------- spectral trio -----------------------------------------
__global__ __launch_bounds__(256, 2) void k_fwd_h() {
    extern __shared__ __align__(16) char smraw[];
    ull* Ts = (ull*)smraw;
    ull* fa = Ts + 4096;
    ull* fb = fa + 4096;
    int bc = blockIdx.x, t = threadIdx.x;
    const ull* Tg = g_T + (size_t)bc * 4096;
    for (int i = t; i < 4096; i += 256) { Ts[i] = Tg[i]; fa[i] = g_Fh2a[i]; fb[i] = g_Fh2b[i]; }
    __syncthreads();
    int kx = t >> 4, ky = t & 15;
    const ull* fak = fa + kx * 256;
    const ull* fbk = fb + kx * 256;
    ull acc = 0ull;
    for (int h = 0; h < Hh; h++) {
        float tr, ti; upk(Ts[h * MX + ky], tr, ti);
        acc = f2fma(pk(tr, tr), fak[h], acc);
        acc = f2fma(pk(ti, ti), fbk[h], acc);
    }
    g_Xf[(size_t)bc * 256 + t] = acc;
}
__global__ __launch_bounds__(512, 2) void k_modegemm(int l) {
    __shared__ __align__(16) ull ws[4096];
    __shared__ ull xA[512], xB[512];
    int m = blockIdx.x, t = threadIdx.x;
    const ull* W = g_W2 + (((size_t)l * 256) + m) * 4096;
    for (int i = t; i < 4096; i += 512) ws[i] = W[i];
    {
        int b = t >> 6, i = t & 63;
        float xr, xi; upk(g_Xf[((size_t)b * C0 + i) * 256 + m], xr, xi);
        xA[t] = pk(xr, xr);
        xB[t] = pk(-xi, xi);
    }
    __syncthreads();
    int b = t >> 6, o = t & 63;
    ull acc = 0ull;
    const ull* xa = xA + b * 64;
    const ull* xb = xB + b * 64;
    #pragma unroll 4
    for (int i = 0; i < C0; i++) {
        ull w2 = ws[i * 64 + o];
        float wr, wi; upk(w2, wr, wi);
        acc = f2fma(xa[i], w2, acc);
        acc = f2fma(xb[i], pk(wi, wr), acc);
    }
    g_G[(size_t)m * 512 + t] = acc;
}
__global__ __launch_bounds__(256, 2) void k_inv_h() {
    extern __shared__ __align__(16) char smraw[];
    ull* Gs = (ull*)smraw;
    ull* ea = Gs + 256;
    ull* eb = ea + 4096;
    int bo = blockIdx.x, t = threadIdx.x;
    int b = bo >> 6, o = bo & 63;
    for (int i = t; i < 256; i += 256) Gs[i] = g_G[(size_t)i * 512 + bo];
    for (int i = t; i < 4096; i += 256) { ea[i] = g_Eh2a[i]; eb[i] = g_Eh2b[i]; }
    __syncthreads();
    int hg = t >> 4, ky = t & 15;
    ull acc[16];
    #pragma unroll
    for (int i = 0; i < 16; i++) acc[i] = 0ull;
    #pragma unroll
    for (int kx = 0; kx < MX; kx++) {
        float gr, gi; upk(Gs[kx * MX + ky], gr, gi);
        ull gr2 = pk(gr, gr), gi2 = pk(gi, gi);
        #pragma unroll
        for (int hp = 0; hp < 16; hp++) {
            int h = hp * 16 + hg;
            acc[hp] = f2fma(gr2, ea[h * MX + kx], acc[hp]);
            acc[hp] = f2fma(gi2, eb[h * MX + kx], acc[hp]);
        }
    }
    // write pre-split packed Q planes: [(b*256+h)][o][ky] = (re_hi | (-im)_hi<<16)
    #pragma unroll
    for (int hp = 0; hp < 16; hp++) {
        int h = hp * 16 + hg;
        float re, im; upk(acc[hp], re, im);
        u16 rh, rl, ih2, il2;
        split1(re, rh, rl);
        split1(-im, ih2, il2);
        u32 idx = (((u32)b * 256 + h) * 64 + o) * 16 + ky;
        g_Qh32[idx] = (u32)rh | ((u32)ih2 << 16);
        g_Ql32[idx] = (u32)rl | ((u32)il2 << 16);
    }
}

// -------------------- fused HMMA layer kernel -------------------------------
#define AHI 0          // 26624 = 128*104*2
#define ALO 26624
#define BHI 53248      // 13312 = 64*104*2
#define BLO 66560
#define FWH 79872      // 8704 = 32*136*2
#define FWL 88576
#define MSC 97280
#define SMEM_G 100352

// MODE: 0 = lift, 1 = mid layer, 2 = last layer (+head)
template <int MODE>
__global__ __launch_bounds__(256, 2)
void k_gemm(const u16* __restrict__ ainH, const u16* __restrict__ ainL,
            u16* __restrict__ aoutH, u16* __restrict__ aoutL,
            const float* __restrict__ pw_b, int l,
            const float* __restrict__ x, const float* __restrict__ in_w,
            const float* __restrict__ in_b,
            float* __restrict__ out,
            const float* __restrict__ o1w, const float* __restrict__ o1b,
            const float* __restrict__ o2w, const float* __restrict__ o2b) {
    extern __shared__ __align__(16) char sm[];
    int h = blockIdx.x, b = blockIdx.y, t = threadIdx.x;
    int warp = t >> 5, lane = t & 31;
    u16* aH = (u16*)(sm + AHI);
    u16* aL = (u16*)(sm + ALO);
    u16* bHs = (u16*)(sm + BHI);
    u16* bLs = (u16*)(sm + BLO);
    u16* fwh = (u16*)(sm + FWH);
    u16* fwl = (u16*)(sm + FWL);
    float* bias = (float*)(sm + MSC);
    float* iwS  = (float*)(sm + MSC + 256);
    float* ibS  = (float*)(sm + MSC + 768);
    float* x0s  = (float*)(sm + MSC + 1024);
    float* x1s  = (float*)(sm + MSC + 1536);
    float* psum = (float*)(sm + MSC + 2048);
    u32 sa = smem_u32(sm);

    // ---- pre-loop staging ----
    if (MODE == 0) {
        if (t < 128) iwS[t] = in_w[t];
        if (t < 64) ibS[t] = in_b[t];
    } else {
        // pointwise weights (cols 0..63): 512 uint4 per plane
        {
            const uint4* pH = (const uint4*)(g_PwH + l * 4096);
            const uint4* pL = (const uint4*)(g_PwL + l * 4096);
            for (int i = t; i < 512; i += 256) {
                int o = i >> 3, q = i & 7;
                *(uint4*)(bHs + o * LDA + q * 8) = pH[i];
                *(uint4*)(bLs + o * LDA + q * 8) = pL[i];
            }
        }
        // Q (cols 64..95): 256 uint4 per plane
        {
            const uint4* qH = (const uint4*)(g_Qh32 + ((size_t)(b * 256 + h)) * 1024);
            const uint4* qL = (const uint4*)(g_Ql32 + ((size_t)(b * 256 + h)) * 1024);
            for (int i = t; i < 256; i += 256) {
                int o = i >> 2, q = i & 3;
                *(uint4*)(bHs + o * LDA + 64 + q * 8) = qH[i];
                *(uint4*)(bLs + o * LDA + 64 + q * 8) = qL[i];
            }
        }
        if (t < 64) bias[t] = pw_b[t];
        if (MODE == 2) {
            float* w1s = (float*)(sm + FWH);
            float* b1s = (float*)(sm + FWH + 8192);
            float* w2s = (float*)(sm + FWH + 8320);
            for (int i = t; i < 2048; i += 256) w1s[i] = o1w[i];
            if (t < 32) { b1s[t] = o1b[t]; w2s[t] = o2w[t]; }
        }
    }

    int mg = warp & 3, ng = warp >> 2;
    int aRow = (lane & 7) + ((lane >> 3) & 1) * 8;
    int aKq = (lane >> 4) * 8;
    int bSel = (lane >> 4) & 1, bN = lane & 7, bKq = ((lane >> 3) & 1) * 8;
    int mt2 = warp & 1, ng2 = warp >> 1;
    int trow = lane & 7, khalf = (lane >> 3) & 1, chalf = (lane >> 4) & 1;

    float dT[2][4];
    if (MODE != 2) {
        #pragma unroll
        for (int i1 = 0; i1 < 2; i1++)
            #pragma unroll
            for (int i2 = 0; i2 < 4; i2++) dT[i1][i2] = 0.0f;
    }

    for (int wv = 0; wv < 2; wv++) {
        // ---- A staging ----
        if (MODE == 0) {
            if (t < 128) x0s[t] = x[(((size_t)(b * 2)) * 256 + h) * 256 + wv * 128 + t];
            else x1s[t - 128] = x[(((size_t)(b * 2 + 1)) * 256 + h) * 256 + wv * 128 + (t - 128)];
            __syncthreads();
            for (int i = t; i < 8192; i += 256) {
                int w = i >> 6, c = i & 63;
                float v = fmaf(iwS[2 * c], x0s[w], fmaf(iwS[2 * c + 1], x1s[w], ibS[c]));
                u16 hi, lo; split1(v, hi, lo);
                aH[w * LDA + c] = hi; aL[w * LDA + c] = lo;
            }
        } else {
            // act: 1024 uint4 per plane
            const uint4* sH = (const uint4*)(ainH + (((size_t)(b * 256 + h)) * 256 + wv * 128) * 64);
            const uint4* sL = (const uint4*)(ainL + (((size_t)(b * 256 + h)) * 256 + wv * 128) * 64);
            for (int i = t; i < 1024; i += 256) {
                int w = i >> 3, q = i & 7;
                ((uint4*)aH)[w * 13 + q] = sH[i];
                ((uint4*)aL)[w * 13 + q] = sL[i];
            }
            // syn (cols 64..95): 512 uint4 per plane
            const uint4* yH = (const uint4*)(g_SynH + wv * 128 * 32);
            const uint4* yL = (const uint4*)(g_SynL + wv * 128 * 32);
            for (int i = t; i < 512; i += 256) {
                int w = i >> 2, q = i & 3;
                *(uint4*)(aH + w * LDA + 64 + q * 8) = yH[i];
                *(uint4*)(aL + w * LDA + 64 + q * 8) = yL[i];
            }
        }
        if (MODE != 2) {
            const uint4* fH = (const uint4*)(g_FwAh + wv * 128);
            const uint4* fL = (const uint4*)(g_FwAl + wv * 128);
            for (int i = t; i < 512; i += 256) {
                int r = i >> 4, q = i & 15;
                *(uint4*)(fwh + r * 136 + q * 8) = fH[r * 32 + q];
                *(uint4*)(fwl + r * 136 + q * 8) = fL[r * 32 + q];
            }
        }
        __syncthreads();   // S1

        if (MODE >= 1) {
            // ---- main MMA: D[128w x 64o], K=96, 3-pass hi/lo ----
            float d[2][4][4];
            #pragma unroll
            for (int i1 = 0; i1 < 2; i1++)
                #pragma unroll
                for (int i2 = 0; i2 < 4; i2++)
                    #pragma unroll
                    for (int i3 = 0; i3 < 4; i3++) d[i1][i2][i3] = 0.0f;
            #pragma unroll
            for (int k6 = 0; k6 < 6; k6++) {
                int k0 = k6 * 16;
                u32 ah[2][4], al[2][4];
                #pragma unroll
                for (int mt = 0; mt < 2; mt++) {
                    u32 ad = (u32)((32 * mg + mt * 16 + aRow) * LDA + k0 + aKq) * 2;
                    ldmx4(ah[mt], sa + AHI + ad);
                    ldmx4(al[mt], sa + ALO + ad);
                }
                #pragma unroll
                for (int np = 0; np < 2; np++) {
                    int q0 = ng * 4 + np * 2;
                    u32 bd = (u32)(((q0 + bSel) * 8 + bN) * LDA + k0 + bKq) * 2;
                    u32 bh4[4], bl4[4];
                    ldmx4(bh4, sa + BHI + bd);
                    ldmx4(bl4, sa + BLO + bd);
                    #pragma unroll
                    for (int sub = 0; sub < 2; sub++) {
                        int nt = np * 2 + sub;
                        #pragma unroll
                        for (int mt = 0; mt < 2; mt++) {
                            mma16816(d[mt][nt], ah[mt], bh4[2 * sub], bh4[2 * sub + 1]);
                            mma16816(d[mt][nt], ah[mt], bl4[2 * sub], bl4[2 * sub + 1]);
                            mma16816(d[mt][nt], al[mt], bh4[2 * sub], bh4[2 * sub + 1]);
                        }
                    }
                }
            }
            __syncthreads();   // S2

            // ---- epilogue ----
            int g = lane >> 2, c2 = lane & 3;
            if (MODE == 1) {
                #pragma unroll
                for (int mt = 0; mt < 2; mt++) {
                    int wl = 32 * mg + mt * 16 + g;
                    #pragma unroll
                    for (int nt = 0; nt < 4; nt++) {
                        int ob = (ng * 4 + nt) * 8 + 2 * c2;
                        float v0 = gelu_exact(d[mt][nt][0] + bias[ob]);
                        float v1 = gelu_exact(d[mt][nt][1] + bias[ob + 1]);
                        float v2 = gelu_exact(d[mt][nt][2] + bias[ob]);
                        float v3 = gelu_exact(d[mt][nt][3] + bias[ob + 1]);
                        u16 h0, l0, h1, l1;
                        split1(v0, h0, l0); split1(v1, h1, l1);
                        *(u32*)(aH + wl * LDA + ob) = (u32)h0 | ((u32)h1 << 16);
                        *(u32*)(aL + wl * LDA + ob) = (u32)l0 | ((u32)l1 << 16);
                        split1(v2, h0, l0); split1(v3, h1, l1);
                        *(u32*)(aH + (wl + 8) * LDA + ob) = (u32)h0 | ((u32)h1 << 16);
                        *(u32*)(aL + (wl + 8) * LDA + ob) = (u32)l0 | ((u32)l1 << 16);
                    }
                }
            } else {
                float* stagf = (float*)(sm + AHI);   // [128][68]
                #pragma unroll
                for (int mt = 0; mt < 2; mt++) {
                    int wl = 32 * mg + mt * 16 + g;
                    #pragma unroll
                    for (int nt = 0; nt < 4; nt++) {
                        int ob = (ng * 4 + nt) * 8 + 2 * c2;
                        stagf[wl * 68 + ob]           = gelu_exact(d[mt][nt][0] + bias[ob]);
                        stagf[wl * 68 + ob + 1]       = gelu_exact(d[mt][nt][1] + bias[ob + 1]);
                        stagf[(wl + 8) * 68 + ob]     = gelu_exact(d[mt][nt][2] + bias[ob]);
                        stagf[(wl + 8) * 68 + ob + 1] = gelu_exact(d[mt][nt][3] + bias[ob + 1]);
                    }
                }
            }
            __syncthreads();   // S3
        }

        if (MODE != 2) {
            // ---- act gmem store: uint4 from tiles ----
            uint4* dH = (uint4*)(aoutH + (((size_t)(b * 256 + h)) * 256 + wv * 128) * 64);
            uint4* dL = (uint4*)(aoutL + (((size_t)(b * 256 + h)) * 256 + wv * 128) * 64);
            for (int i = t; i < 1024; i += 256) {
                int w = i >> 3, q = i & 7;
                dH[i] = ((uint4*)aH)[w * 13 + q];
                dL[i] = ((uint4*)aL)[w * 13 + q];
            }
            // ---- fwd-w DFT GEMM: dT[32][64] += Fw[32][128] . act[128][64] ----
            #pragma unroll
            for (int ks = 0; ks < 8; ks++) {
                int k0 = ks * 16;
                u32 fh[4], fl[4], bh[4], bl[4];
                u32 fad = (u32)((mt2 * 16 + aRow) * 136 + k0 + aKq) * 2;
                ldmx4(fh, sa + FWH + fad);
                ldmx4(fl, sa + FWL + fad);
                u32 bad = (u32)((k0 + khalf * 8 + trow) * LDA + ng2 * 16 + chalf * 8) * 2;
                ldmx4t(bh, sa + AHI + bad);
                ldmx4t(bl, sa + ALO + bad);
                #pragma unroll
                for (int nt = 0; nt < 2; nt++) {
                    u32 b0 = bh[2 * nt], b1 = bh[2 * nt + 1];
                    u32 c0 = bl[2 * nt], c1 = bl[2 * nt + 1];
                    mma16816(dT[nt], fh, b0, b1);
                    mma16816(dT[nt], fh, c0, c1);
                    mma16816(dT[nt], fl, b0, b1);
                }
            }
            __syncthreads();   // S4
        } else {
            // ---- head ----
            float* stagf = (float*)(sm + AHI);
            float* w1s = (float*)(sm + FWH);
            float* b1s = (float*)(sm + FWH + 8192);
            float* w2s = (float*)(sm + FWH + 8320);
            int p = t & 127, hf = t >> 7;
            ull x2[32];
            const float2* xr = (const float2*)(stagf + p * 68);
            #pragma unroll
            for (int j = 0; j < 32; j++) {
                float2 xx = xr[j];
                x2[j] = pk(xx.x, xx.y);
            }
            float acc = hf ? 0.0f : __ldg(o2b);
            for (int o2 = hf * 16; o2 < hf * 16 + 16; o2++) {
                ull s = pk(b1s[o2], 0.0f);
                const ulonglong2* wv2 = (const ulonglong2*)(w1s + o2 * 64);
                #pragma unroll
                for (int j = 0; j < 16; j++) {
                    ulonglong2 p4 = wv2[j];
                    s = f2fma(p4.x, x2[2 * j], s);
                    s = f2fma(p4.y, x2[2 * j + 1], s);
                }
                float lo, hi; upk(s, lo, hi);
                acc = fmaf(w2s[o2], gelu_exact(lo + hi), acc);
            }
            psum[hf * 128 + p] = acc;
            __syncthreads();   // S4
            if (t < 128)
                out[((size_t)(b * 256 + h)) * 256 + wv * 128 + t] = psum[t] + psum[128 + t];
            __syncthreads();   // S5
        }
    }

    if (MODE != 2) {
        // ---- store T ----
        float* Tf = (float*)g_T;
        int g = lane >> 2, c2 = lane & 3;
        #pragma unroll
        for (int nt = 0; nt < 2; nt++) {
            #pragma unroll
            for (int pr = 0; pr < 2; pr++) {
                int row = mt2 * 16 + g + pr * 8;
                int ky = row >> 1, ri = row & 1;
                int c = ng2 * 16 + nt * 8 + 2 * c2;
                size_t bse = (((size_t)(b * 64 + c)) * 256 + h) * 32 + ky * 2 + ri;
                Tf[bse] = dT[nt][pr * 2 + 0];
                Tf[bse + 8192] = dT[nt][pr * 2 + 1];
            }
        }
    }
}

// ---------------------------------------------------------------------------
extern "C" void kernel_launch(void* const* d_in, const int* in_sizes, int n_in,
                              void* d_out, int out_size) {
    const float* x       = (const float*)d_in[0];
    const float* in_w    = (const float*)d_in[1];
    const float* in_b    = (const float*)d_in[2];
    const float* spec_wr = (const float*)d_in[3];
    const float* spec_wi = (const float*)d_in[4];
    const float* pw_w    = (const float*)d_in[5];
    const float* pw_b    = (const float*)d_in[6];
    const float* o1w     = (const float*)d_in[7];
    const float* o1b     = (const float*)d_in[8];
    const float* o2w     = (const float*)d_in[9];
    const float* o2b     = (const float*)d_in[10];
    float* out = (float*)d_out;

    const int SMEM_FH = 98304;
    const int SMEM_IH = 67584;
    cudaFuncSetAttribute(k_gemm<0>, cudaFuncAttributeMaxDynamicSharedMemorySize, SMEM_G);
    cudaFuncSetAttribute(k_gemm<1>, cudaFuncAttributeMaxDynamicSharedMemorySize, SMEM_G);
    cudaFuncSetAttribute(k_gemm<2>, cudaFuncAttributeMaxDynamicSharedMemorySize, SMEM_G);
    cudaFuncSetAttribute(k_fwd_h, cudaFuncAttributeMaxDynamicSharedMemorySize, SMEM_FH);
    cudaFuncSetAttribute(k_inv_h, cudaFuncAttributeMaxDynamicSharedMemorySize, SMEM_IH);

    u16 *aAH, *aAL, *aBH, *aBL;
    cudaGetSymbolAddress((void**)&aAH, g_actAH);
    cudaGetSymbolAddress((void**)&aAL, g_actAL);
    cudaGetSymbolAddress((void**)&aBH, g_actBH);
    cudaGetSymbolAddress((void**)&aBL, g_actBL);

    k_prep<<<64, 256>>>(pw_w);
    k_twt<<<dim3(128, 8, NL4), dim3(32, 8)>>>(spec_wr, spec_wi);

    dim3 grid(Hh, Bb);
    k_gemm<0><<<grid, 256, SMEM_G>>>(nullptr, nullptr, aAH, aAL, nullptr, 0,
                                     x, in_w, in_b, nullptr,
                                     nullptr, nullptr, nullptr, nullptr);

    const u16 *curH = aAH, *curL = aAL;
    u16 *nxtH = aBH, *nxtL = aBL;
    for (int l = 0; l < NL4; l++) {
        k_fwd_h<<<Bb * C0, 256, SMEM_FH>>>();
        k_modegemm<<<256, 512>>>(l);
        k_inv_h<<<Bb * C0, 256, SMEM_IH>>>();
        if (l < NL4 - 1) {
            k_gemm<1><<<grid, 256, SMEM_G>>>(curH, curL, nxtH, nxtL, pw_b + l * 64, l,
                                             nullptr, nullptr, nullptr, nullptr,
                                             nullptr, nullptr, nullptr, nullptr);
            const u16* th = curH; const u16* tl = curL;
            curH = nxtH; curL = nxtL; nxtH = (u16*)th; nxtL = (u16*)tl;
        } else {
            k_gemm<2><<<grid, 256, SMEM_G>>>(curH, curL, nullptr, nullptr, pw_b + l * 64, l,
                                             nullptr, nullptr, nullptr, out,
                                             o1w, o1b, o2w, o2b);
        }
    }
}

// round 8
// speedup vs baseline: 2.7780x; 1.1517x over previous
#include <cuda_runtime.h>
#include <cuda_fp16.h>
#include <math.h>
#include <stdint.h>

#define Bb 8
#define C0 64
#define Hh 256
#define Ww 256
#define MX 16
#define NL4 4
#define HW 65536
#define LDA 104

typedef unsigned long long ull;
typedef unsigned int u32;
typedef unsigned short u16;

// -------------------- helpers ----------------------------------------------
__device__ __forceinline__ ull pk(float lo, float hi) {
    ull r; asm("mov.b64 %0,{%1,%2};" : "=l"(r) : "f"(lo), "f"(hi)); return r;
}
__device__ __forceinline__ void upk(ull v, float& lo, float& hi) {
    asm("mov.b64 {%0,%1},%2;" : "=f"(lo), "=f"(hi) : "l"(v));
}
__device__ __forceinline__ ull f2fma(ull a, ull b, ull c) {
    ull d; asm("fma.rn.f32x2 %0,%1,%2,%3;" : "=l"(d) : "l"(a), "l"(b), "l"(c)); return d;
}
__device__ __forceinline__ void splitH(float v, u16& hi, u16& lo) {
    __half h = __float2half_rn(v);
    hi = __half_as_ushort(h);
    lo = __half_as_ushort(__float2half_rn(v - __half2float(h)));
}
__device__ __forceinline__ u16 h16(float v) {
    return __half_as_ushort(__float2half_rn(v));
}
__device__ __forceinline__ u32 pkh2(float lo, float hi) {   // lo in bits 0..15
    u32 r; asm("cvt.rn.f16x2.f32 %0,%2,%1;" : "=r"(r) : "f"(lo), "f"(hi)); return r;
}
__device__ __forceinline__ u32 smem_u32(const void* p) {
    u32 a; asm("{ .reg .u64 t; cvta.to.shared.u64 t, %1; cvt.u32.u64 %0, t; }" : "=r"(a) : "l"(p));
    return a;
}
__device__ __forceinline__ void ldmx4(u32* r, u32 addr) {
    asm volatile("ldmatrix.sync.aligned.m8n8.x4.shared.b16 {%0,%1,%2,%3},[%4];"
        : "=r"(r[0]), "=r"(r[1]), "=r"(r[2]), "=r"(r[3]) : "r"(addr));
}
__device__ __forceinline__ void ldmx4t(u32* r, u32 addr) {
    asm volatile("ldmatrix.sync.aligned.m8n8.x4.trans.shared.b16 {%0,%1,%2,%3},[%4];"
        : "=r"(r[0]), "=r"(r[1]), "=r"(r[2]), "=r"(r[3]) : "r"(addr));
}
__device__ __forceinline__ void mma16816(float* d, const u32* a, u32 b0, u32 b1) {
    asm volatile("mma.sync.aligned.m16n8k16.row.col.f32.f16.f16.f32 "
        "{%0,%1,%2,%3},{%4,%5,%6,%7},{%8,%9},{%0,%1,%2,%3};"
        : "+f"(d[0]), "+f"(d[1]), "+f"(d[2]), "+f"(d[3])
        : "r"(a[0]), "r"(a[1]), "r"(a[2]), "r"(a[3]), "r"(b0), "r"(b1));
}
__device__ __forceinline__ float gelu_exact(float z) {
    return 0.5f * z * (1.0f + erff(z * 0.70710678118654752f));
}

// -------------------- globals -----------------------------------------------
__device__ u16 g_actA[(size_t)Bb * HW * C0];   // fp16 act plane [b][h][w][c]
__device__ u16 g_actB[(size_t)Bb * HW * C0];
__device__ ull g_T [(size_t)Bb * C0 * Hh * MX];
__device__ ull g_Xf[(size_t)Bb * C0 * 256];
__device__ ull g_G [(size_t)256 * Bb * C0];
__device__ u32 g_Qh32[(size_t)Bb * Hh * 1024];  // [(b*256+h)][o][ky]: fp16 (reh|imh<<16)
__device__ u32 g_Ql32[(size_t)Bb * Hh * 1024];
__device__ ull g_W2[(size_t)NL4 * 256 * 4096];
__device__ ull g_Fh2a[MX * Hh], g_Fh2b[MX * Hh];
__device__ ull g_Eh2a[Hh * MX], g_Eh2b[Hh * MX];
__device__ u16 g_PwH[NL4 * 4096], g_PwL[NL4 * 4096];  // fp16 hi/lo [l][o][c]
__device__ u16 g_SynF[256 * 32];                      // fp16 single [w][2ky+ri]
__device__ u16 g_FwAh[32 * 256], g_FwAl[32 * 256];    // fp16 hi/lo [2ky+ri][w]

// -------------------- merged prep -------------------------------------------
__global__ void k_prep(const float* __restrict__ pw_w) {
    int idx = blockIdx.x * 256 + threadIdx.x;   // 0..16383
    { u16 h, l; splitH(pw_w[idx], h, l); g_PwH[idx] = h; g_PwL[idx] = l; }
    if (idx < 4096) {
        int a = idx >> 8, p = idx & 255, m = (a * p) & 255;
        float s, c; sincospif((float)m * (1.0f / 128.0f), &s, &c);
        g_Fh2a[idx] = pk(c, -s);  g_Fh2b[idx] = pk(s, c);
        g_Eh2a[p * MX + a] = pk(c, s);  g_Eh2b[p * MX + a] = pk(-s, c);
    }
    if (idx < 8192) {
        {   // syn single fp16: [w][2ky+ri]
            int w = idx >> 5, j = idx & 31, ky = j >> 1, ri = j & 1;
            float s, c; sincospif((float)((ky * w) & 255) * (1.0f / 128.0f), &s, &c);
            float ck = ((ky == 0) ? 1.0f : 2.0f) * (1.0f / 256.0f);
            g_SynF[idx] = h16(ri ? s * ck : c * ck);
        }
        {   // fwd-DFT A hi/lo: [2ky+ri][w]
            int row = idx >> 8, w = idx & 255, ky = row >> 1, ri = row & 1;
            float s, c; sincospif((float)((ky * w) & 255) * (1.0f / 128.0f), &s, &c);
            float v = (ri ? -s : c) * (1.0f / 256.0f);
            u16 h, l; splitH(v, h, l);
            g_FwAh[idx] = h; g_FwAl[idx] = l;
        }
    }
}
__global__ void k_twt(const float* __restrict__ wr, const float* __restrict__ wi) {
    __shared__ ull tile[32][33];
    int l = blockIdx.z, tio = blockIdx.x, tm = blockIdx.y;
    int tx = threadIdx.x, ty = threadIdx.y;
    const float* wrl = wr + (size_t)l * 4096 * 256;
    const float* wil = wi + (size_t)l * 4096 * 256;
    #pragma unroll
    for (int r = 0; r < 4; r++) {
        int row = tio * 32 + ty + 8 * r, col = tm * 32 + tx;
        size_t idx = (size_t)row * 256 + col;
        tile[ty + 8 * r][tx] = pk(wrl[idx], wil[idx]);
    }
    __syncthreads();
    #pragma unroll
    for (int r = 0; r < 4; r++) {
        int mm = tm * 32 + ty + 8 * r, io = tio * 32 + tx;
        g_W2[(((size_t)l * 256) + mm) * 4096 + io] = tile[tx][ty + 8 * r];
    }
}

// -------------------- spectral trio -----------------------------------------
__global__ __launch_bounds__(256, 4) void k_fwd_h() {
    __shared__ ull Ts[4096];
    int bc = blockIdx.x, t = threadIdx.x;
    const ull* Tg = g_T + (size_t)bc * 4096;
    for (int i = t; i < 4096; i += 256) Ts[i] = Tg[i];
    __syncthreads();
    int kx = t >> 4, ky = t & 15;
    const ull* fak = g_Fh2a + kx * 256;
    const ull* fbk = g_Fh2b + kx * 256;
    ull a0 = 0ull, a1 = 0ull;
    #pragma unroll 8
    for (int h = 0; h < 256; h += 2) {
        float tr, ti;
        upk(Ts[h * 16 + ky], tr, ti);
        a0 = f2fma(pk(tr, tr), __ldg(fak + h), a0);
        a0 = f2fma(pk(ti, ti), __ldg(fbk + h), a0);
        upk(Ts[(h + 1) * 16 + ky], tr, ti);
        a1 = f2fma(pk(tr, tr), __ldg(fak + h + 1), a1);
        a1 = f2fma(pk(ti, ti), __ldg(fbk + h + 1), a1);
    }
    float x0, y0, x1, y1; upk(a0, x0, y0); upk(a1, x1, y1);
    g_Xf[(size_t)bc * 256 + t] = pk(x0 + x1, y0 + y1);
}
__global__ __launch_bounds__(512, 2) void k_modegemm(int l) {
    __shared__ __align__(16) ull ws[4096];
    __shared__ ull xA[512], xB[512];
    int m = blockIdx.x, t = threadIdx.x;
    const ull* W = g_W2 + (((size_t)l * 256) + m) * 4096;
    for (int i = t; i < 4096; i += 512) ws[i] = W[i];
    {
        int b = t >> 6, i = t & 63;
        float xr, xi; upk(g_Xf[((size_t)b * C0 + i) * 256 + m], xr, xi);
        xA[t] = pk(xr, xr);
        xB[t] = pk(-xi, xi);
    }
    __syncthreads();
    int b = t >> 6, o = t & 63;
    ull acc = 0ull;
    const ull* xa = xA + b * 64;
    const ull* xb = xB + b * 64;
    #pragma unroll 4
    for (int i = 0; i < C0; i++) {
        ull w2 = ws[i * 64 + o];
        float wr, wi; upk(w2, wr, wi);
        acc = f2fma(xa[i], w2, acc);
        acc = f2fma(xb[i], pk(wi, wr), acc);
    }
    g_G[(size_t)m * 512 + t] = acc;
}
__global__ __launch_bounds__(256, 2) void k_inv_h() {
    extern __shared__ __align__(16) char smraw[];
    ull* Gs = (ull*)smraw;
    ull* ea = Gs + 256;
    ull* eb = ea + 4096;
    int bo = blockIdx.x, t = threadIdx.x;
    int b = bo >> 6, o = bo & 63;
    for (int i = t; i < 256; i += 256) Gs[i] = g_G[(size_t)i * 512 + bo];
    for (int i = t; i < 4096; i += 256) { ea[i] = g_Eh2a[i]; eb[i] = g_Eh2b[i]; }
    __syncthreads();
    int hg = t >> 4, ky = t & 15;
    ull acc[16];
    #pragma unroll
    for (int i = 0; i < 16; i++) acc[i] = 0ull;
    #pragma unroll
    for (int kx = 0; kx < MX; kx++) {
        float gr, gi; upk(Gs[kx * MX + ky], gr, gi);
        ull gr2 = pk(gr, gr), gi2 = pk(gi, gi);
        #pragma unroll
        for (int hp = 0; hp < 16; hp++) {
            int h = hp * 16 + hg;
            acc[hp] = f2fma(gr2, ea[h * MX + kx], acc[hp]);
            acc[hp] = f2fma(gi2, eb[h * MX + kx], acc[hp]);
        }
    }
    #pragma unroll
    for (int hp = 0; hp < 16; hp++) {
        int h = hp * 16 + hg;
        float re, im; upk(acc[hp], re, im);
        u16 rh, rl, ih2, il2;
        splitH(re, rh, rl);
        splitH(-im, ih2, il2);
        u32 idx = (((u32)b * 256 + h) * 64 + o) * 16 + ky;
        g_Qh32[idx] = (u32)rh | ((u32)ih2 << 16);
        g_Ql32[idx] = (u32)rl | ((u32)il2 << 16);
    }
}

// -------------------- fused HMMA layer kernel -------------------------------
// smem (bytes):
#define AOF 0          // 26624 = 128*104*2  (fp16 act+syn tile)
#define BHI 26624      // 13312 = 64*104*2
#define BLO 39936      // 13312
#define FWH 53248      // 8704 = 32*136*2
#define FWL 61952      // 8704
#define MSC 70656      // 3072
#define STG 73728      // 34816 (MODE 2 f32 stag [128][68])
#define SMEM_G 108544

// MODE: 0 = lift, 1 = mid layer, 2 = last layer (+head)
template <int MODE>
__global__ __launch_bounds__(256, 2)
void k_gemm(const u16* __restrict__ ain, u16* __restrict__ aout,
            const float* __restrict__ pw_b, int l,
            const float* __restrict__ x, const float* __restrict__ in_w,
            const float* __restrict__ in_b,
            float* __restrict__ out,
            const float* __restrict__ o1w, const float* __restrict__ o1b,
            const float* __restrict__ o2w, const float* __restrict__ o2b) {
    extern __shared__ __align__(16) char sm[];
    int h = blockIdx.x, b = blockIdx.y, t = threadIdx.x;
    int warp = t >> 5, lane = t & 31;
    u16* aT  = (u16*)(sm + AOF);
    u16* bHs = (u16*)(sm + BHI);
    u16* bLs = (u16*)(sm + BLO);
    u16* fwh = (u16*)(sm + FWH);
    u16* fwl = (u16*)(sm + FWL);
    float* bias = (float*)(sm + MSC);
    float* iwS  = (float*)(sm + MSC + 256);
    float* ibS  = (float*)(sm + MSC + 768);
    float* x0s  = (float*)(sm + MSC + 1024);
    float* x1s  = (float*)(sm + MSC + 1536);
    float* psum = (float*)(sm + MSC + 2048);
    u32 sa = smem_u32(sm);

    // ---- pre-loop staging ----
    if (MODE == 0) {
        if (t < 128) iwS[t] = in_w[t];
        if (t < 64) ibS[t] = in_b[t];
    } else {
        {   // pointwise weights (cols 0..63)
            const uint4* pH = (const uint4*)(g_PwH + l * 4096);
            const uint4* pL = (const uint4*)(g_PwL + l * 4096);
            for (int i = t; i < 512; i += 256) {
                int o = i >> 3, q = i & 7;
                *(uint4*)(bHs + o * LDA + q * 8) = pH[i];
                *(uint4*)(bLs + o * LDA + q * 8) = pL[i];
            }
        }
        {   // Q (cols 64..95)
            const uint4* qH = (const uint4*)(g_Qh32 + ((size_t)(b * 256 + h)) * 1024);
            const uint4* qL = (const uint4*)(g_Ql32 + ((size_t)(b * 256 + h)) * 1024);
            for (int i = t; i < 256; i += 256) {
                int o = i >> 2, q = i & 3;
                *(uint4*)(bHs + o * LDA + 64 + q * 8) = qH[i];
                *(uint4*)(bLs + o * LDA + 64 + q * 8) = qL[i];
            }
        }
        if (t < 64) bias[t] = pw_b[t];
        if (MODE == 2) {
            float* w1s = (float*)(sm + FWH);
            float* b1s = (float*)(sm + FWH + 8192);
            float* w2s = (float*)(sm + FWH + 8320);
            for (int i = t; i < 2048; i += 256) w1s[i] = o1w[i];
            if (t < 32) { b1s[t] = o1b[t]; w2s[t] = o2w[t]; }
        }
    }

    int mg = warp & 3, ng = warp >> 2;
    int aRow = (lane & 7) + ((lane >> 3) & 1) * 8;
    int aKq = (lane >> 4) * 8;
    int bSel = (lane >> 4) & 1, bN = lane & 7, bKq = ((lane >> 3) & 1) * 8;
    int mt2 = warp & 1, ng2 = warp >> 1;
    int trow = lane & 7, khalf = (lane >> 3) & 1, chalf = (lane >> 4) & 1;

    float dT[2][4];
    if (MODE != 2) {
        #pragma unroll
        for (int i1 = 0; i1 < 2; i1++)
            #pragma unroll
            for (int i2 = 0; i2 < 4; i2++) dT[i1][i2] = 0.0f;
    }

    for (int wv = 0; wv < 2; wv++) {
        // ---- A staging ----
        if (MODE == 0) {
            if (t < 128) x0s[t] = x[(((size_t)(b * 2)) * 256 + h) * 256 + wv * 128 + t];
            else x1s[t - 128] = x[(((size_t)(b * 2 + 1)) * 256 + h) * 256 + wv * 128 + (t - 128)];
            __syncthreads();
            for (int i = t; i < 8192; i += 256) {
                int w = i >> 6, c = i & 63;
                float v = fmaf(iwS[2 * c], x0s[w], fmaf(iwS[2 * c + 1], x1s[w], ibS[c]));
                aT[w * LDA + c] = h16(v);
            }
        } else {
            const uint4* sA = (const uint4*)(ain + (((size_t)(b * 256 + h)) * 256 + wv * 128) * 64);
            for (int i = t; i < 1024; i += 256) {
                int w = i >> 3, q = i & 7;
                ((uint4*)aT)[w * 13 + q] = sA[i];
            }
            // syn (cols 64..95), single fp16
            const uint4* yF = (const uint4*)(g_SynF + wv * 128 * 32);
            for (int i = t; i < 512; i += 256) {
                int w = i >> 2, q = i & 3;
                *(uint4*)(aT + w * LDA + 64 + q * 8) = yF[i];
            }
        }
        if (MODE != 2) {
            const uint4* fH = (const uint4*)(g_FwAh + wv * 128);
            const uint4* fL = (const uint4*)(g_FwAl + wv * 128);
            for (int i = t; i < 512; i += 256) {
                int r = i >> 4, q = i & 15;
                *(uint4*)(fwh + r * 136 + q * 8) = fH[r * 32 + q];
                *(uint4*)(fwl + r * 136 + q * 8) = fL[r * 32 + q];
            }
        }
        __syncthreads();   // S1

        if (MODE >= 1) {
            // ---- main MMA: D[128w x 64o], K=96, 2-pass (A exact fp16) ----
            float d[2][4][4];
            #pragma unroll
            for (int i1 = 0; i1 < 2; i1++)
                #pragma unroll
                for (int i2 = 0; i2 < 4; i2++)
                    #pragma unroll
                    for (int i3 = 0; i3 < 4; i3++) d[i1][i2][i3] = 0.0f;
            #pragma unroll
            for (int k6 = 0; k6 < 6; k6++) {
                int k0 = k6 * 16;
                u32 af[2][4];
                #pragma unroll
                for (int mt = 0; mt < 2; mt++) {
                    u32 ad = (u32)((32 * mg + mt * 16 + aRow) * LDA + k0 + aKq) * 2;
                    ldmx4(af[mt], sa + AOF + ad);
                }
                #pragma unroll
                for (int np = 0; np < 2; np++) {
                    int q0 = ng * 4 + np * 2;
                    u32 bd = (u32)(((q0 + bSel) * 8 + bN) * LDA + k0 + bKq) * 2;
                    u32 bh4[4], bl4[4];
                    ldmx4(bh4, sa + BHI + bd);
                    ldmx4(bl4, sa + BLO + bd);
                    #pragma unroll
                    for (int sub = 0; sub < 2; sub++) {
                        int nt = np * 2 + sub;
                        #pragma unroll
                        for (int mt = 0; mt < 2; mt++) {
                            mma16816(d[mt][nt], af[mt], bh4[2 * sub], bh4[2 * sub + 1]);
                            mma16816(d[mt][nt], af[mt], bl4[2 * sub], bl4[2 * sub + 1]);
                        }
                    }
                }
            }
            __syncthreads();   // S2

            // ---- epilogue ----
            int g = lane >> 2, c2 = lane & 3;
            if (MODE == 1) {
                #pragma unroll
                for (int mt = 0; mt < 2; mt++) {
                    int wl = 32 * mg + mt * 16 + g;
                    #pragma unroll
                    for (int nt = 0; nt < 4; nt++) {
                        int ob = (ng * 4 + nt) * 8 + 2 * c2;
                        float v0 = gelu_exact(d[mt][nt][0] + bias[ob]);
                        float v1 = gelu_exact(d[mt][nt][1] + bias[ob + 1]);
                        float v2 = gelu_exact(d[mt][nt][2] + bias[ob]);
                        float v3 = gelu_exact(d[mt][nt][3] + bias[ob + 1]);
                        *(u32*)(aT + wl * LDA + ob) = pkh2(v0, v1);
                        *(u32*)(aT + (wl + 8) * LDA + ob) = pkh2(v2, v3);
                    }
                }
            } else {
                float* stagf = (float*)(sm + STG);   // [128][68]
                #pragma unroll
                for (int mt = 0; mt < 2; mt++) {
                    int wl = 32 * mg + mt * 16 + g;
                    #pragma unroll
                    for (int nt = 0; nt < 4; nt++) {
                        int ob = (ng * 4 + nt) * 8 + 2 * c2;
                        stagf[wl * 68 + ob]           = gelu_exact(d[mt][nt][0] + bias[ob]);
                        stagf[wl * 68 + ob + 1]       = gelu_exact(d[mt][nt][1] + bias[ob + 1]);
                        stagf[(wl + 8) * 68 + ob]     = gelu_exact(d[mt][nt][2] + bias[ob]);
                        stagf[(wl + 8) * 68 + ob + 1] = gelu_exact(d[mt][nt][3] + bias[ob + 1]);
                    }
                }
            }
            __syncthreads();   // S3
        }

        if (MODE != 2) {
            // ---- act gmem store ----
            uint4* dA = (uint4*)(aout + (((size_t)(b * 256 + h)) * 256 + wv * 128) * 64);
            for (int i = t; i < 1024; i += 256) {
                int w = i >> 3, q = i & 7;
                dA[i] = ((uint4*)aT)[w * 13 + q];
            }
            // ---- fwd-w DFT GEMM: dT[32][64] += Fw[32][128] . act[128][64] ----
            #pragma unroll
            for (int ks = 0; ks < 8; ks++) {
                int k0 = ks * 16;
                u32 fh[4], fl[4], bv[4];
                u32 fad = (u32)((mt2 * 16 + aRow) * 136 + k0 + aKq) * 2;
                ldmx4(fh, sa + FWH + fad);
                ldmx4(fl, sa + FWL + fad);
                u32 bad = (u32)((k0 + khalf * 8 + trow) * LDA + ng2 * 16 + chalf * 8) * 2;
                ldmx4t(bv, sa + AOF + bad);
                #pragma unroll
                for (int nt = 0; nt < 2; nt++) {
                    mma16816(dT[nt], fh, bv[2 * nt], bv[2 * nt + 1]);
                    mma16816(dT[nt], fl, bv[2 * nt], bv[2 * nt + 1]);
                }
            }
            __syncthreads();   // S4
        } else {
            // ---- head ----
            float* stagf = (float*)(sm + STG);
            float* w1s = (float*)(sm + FWH);
            float* b1s = (float*)(sm + FWH + 8192);
            float* w2s = (float*)(sm + FWH + 8320);
            int p = t & 127, hf = t >> 7;
            ull x2[32];
            const float2* xr = (const float2*)(stagf + p * 68);
            #pragma unroll
            for (int j = 0; j < 32; j++) {
                float2 xx = xr[j];
                x2[j] = pk(xx.x, xx.y);
            }
            float acc = hf ? 0.0f : __ldg(o2b);
            for (int o2 = hf * 16; o2 < hf * 16 + 16; o2++) {
                ull s = pk(b1s[o2], 0.0f);
                const ulonglong2* wv2 = (const ulonglong2*)(w1s + o2 * 64);
                #pragma unroll
                for (int j = 0; j < 16; j++) {
                    ulonglong2 p4 = wv2[j];
                    s = f2fma(p4.x, x2[2 * j], s);
                    s = f2fma(p4.y, x2[2 * j + 1], s);
                }
                float lo, hi; upk(s, lo, hi);
                acc = fmaf(w2s[o2], gelu_exact(lo + hi), acc);
            }
            psum[hf * 128 + p] = acc;
            __syncthreads();   // S4
            if (t < 128)
                out[((size_t)(b * 256 + h)) * 256 + wv * 128 + t] = psum[t] + psum[128 + t];
            __syncthreads();   // S5
        }
    }

    if (MODE != 2) {
        // ---- store T ----
        float* Tf = (float*)g_T;
        int g = lane >> 2, c2 = lane & 3;
        #pragma unroll
        for (int nt = 0; nt < 2; nt++) {
            #pragma unroll
            for (int pr = 0; pr < 2; pr++) {
                int row = mt2 * 16 + g + pr * 8;
                int ky = row >> 1, ri = row & 1;
                int c = ng2 * 16 + nt * 8 + 2 * c2;
                size_t bse = (((size_t)(b * 64 + c)) * 256 + h) * 32 + ky * 2 + ri;
                Tf[bse] = dT[nt][pr * 2 + 0];
                Tf[bse + 8192] = dT[nt][pr * 2 + 1];
            }
        }
    }
}

// ---------------------------------------------------------------------------
extern "C" void kernel_launch(void* const* d_in, const int* in_sizes, int n_in,
                              void* d_out, int out_size) {
    const float* x       = (const float*)d_in[0];
    const float* in_w    = (const float*)d_in[1];
    const float* in_b    = (const float*)d_in[2];
    const float* spec_wr = (const float*)d_in[3];
    const float* spec_wi = (const float*)d_in[4];
    const float* pw_w    = (const float*)d_in[5];
    const float* pw_b    = (const float*)d_in[6];
    const float* o1w     = (const float*)d_in[7];
    const float* o1b     = (const float*)d_in[8];
    const float* o2w     = (const float*)d_in[9];
    const float* o2b     = (const float*)d_in[10];
    float* out = (float*)d_out;

    const int SMEM_IH = 67584;
    cudaFuncSetAttribute(k_gemm<0>, cudaFuncAttributeMaxDynamicSharedMemorySize, SMEM_G);
    cudaFuncSetAttribute(k_gemm<1>, cudaFuncAttributeMaxDynamicSharedMemorySize, SMEM_G);
    cudaFuncSetAttribute(k_gemm<2>, cudaFuncAttributeMaxDynamicSharedMemorySize, SMEM_G);
    cudaFuncSetAttribute(k_inv_h, cudaFuncAttributeMaxDynamicSharedMemorySize, SMEM_IH);

    u16 *aA, *aB;
    cudaGetSymbolAddress((void**)&aA, g_actA);
    cudaGetSymbolAddress((void**)&aB, g_actB);

    k_prep<<<64, 256>>>(pw_w);
    k_twt<<<dim3(128, 8, NL4), dim3(32, 8)>>>(spec_wr, spec_wi);

    dim3 grid(Hh, Bb);
    k_gemm<0><<<grid, 256, SMEM_G>>>(nullptr, aA, nullptr, 0,
                                     x, in_w, in_b, nullptr,
                                     nullptr, nullptr, nullptr, nullptr);

    const u16* cur = aA;
    u16* nxt = aB;
    for (int l = 0; l < NL4; l++) {
        k_fwd_h<<<Bb * C0, 256>>>();
        k_modegemm<<<256, 512>>>(l);
        k_inv_h<<<Bb * C0, 256, SMEM_IH>>>();
        if (l < NL4 - 1) {
            k_gemm<1><<<grid, 256, SMEM_G>>>(cur, nxt, pw_b + l * 64, l,
                                             nullptr, nullptr, nullptr, nullptr,
                                             nullptr, nullptr, nullptr, nullptr);
            const u16* tmp = cur; cur = nxt; nxt = (u16*)tmp;
        } else {
            k_gemm<2><<<grid, 256, SMEM_G>>>(cur, nullptr, pw_b + l * 64, l,
                                             nullptr, nullptr, nullptr, out,
                                             o1w, o1b, o2w, o2b);
        }
    }
}

// round 9
// speedup vs baseline: 2.8235x; 1.0164x over previous
#include <cuda_runtime.h>
#include <cuda_fp16.h>
#include <math.h>
#include <stdint.h>

#define Bb 8
#define C0 64
#define Hh 256
#define Ww 256
#define MX 16
#define NL4 4
#define HW 65536
#define LDA 104

typedef unsigned long long ull;
typedef unsigned int u32;
typedef unsigned short u16;

// -------------------- helpers ----------------------------------------------
__device__ __forceinline__ ull pk(float lo, float hi) {
    ull r; asm("mov.b64 %0,{%1,%2};" : "=l"(r) : "f"(lo), "f"(hi)); return r;
}
__device__ __forceinline__ void upk(ull v, float& lo, float& hi) {
    asm("mov.b64 {%0,%1},%2;" : "=f"(lo), "=f"(hi) : "l"(v));
}
__device__ __forceinline__ ull f2fma(ull a, ull b, ull c) {
    ull d; asm("fma.rn.f32x2 %0,%1,%2,%3;" : "=l"(d) : "l"(a), "l"(b), "l"(c)); return d;
}
__device__ __forceinline__ void splitH(float v, u16& hi, u16& lo) {
    __half h = __float2half_rn(v);
    hi = __half_as_ushort(h);
    lo = __half_as_ushort(__float2half_rn(v - __half2float(h)));
}
__device__ __forceinline__ u16 h16(float v) {
    return __half_as_ushort(__float2half_rn(v));
}
__device__ __forceinline__ u32 pkh2(float lo, float hi) {   // lo in bits 0..15
    u32 r; asm("cvt.rn.f16x2.f32 %0,%2,%1;" : "=r"(r) : "f"(lo), "f"(hi)); return r;
}
__device__ __forceinline__ u32 smem_u32(const void* p) {
    u32 a; asm("{ .reg .u64 t; cvta.to.shared.u64 t, %1; cvt.u32.u64 %0, t; }" : "=r"(a) : "l"(p));
    return a;
}
__device__ __forceinline__ void ldmx4(u32* r, u32 addr) {
    asm volatile("ldmatrix.sync.aligned.m8n8.x4.shared.b16 {%0,%1,%2,%3},[%4];"
        : "=r"(r[0]), "=r"(r[1]), "=r"(r[2]), "=r"(r[3]) : "r"(addr));
}
__device__ __forceinline__ void ldmx4t(u32* r, u32 addr) {
    asm volatile("ldmatrix.sync.aligned.m8n8.x4.trans.shared.b16 {%0,%1,%2,%3},[%4];"
        : "=r"(r[0]), "=r"(r[1]), "=r"(r[2]), "=r"(r[3]) : "r"(addr));
}
__device__ __forceinline__ void mma16816(float* d, const u32* a, u32 b0, u32 b1) {
    asm volatile("mma.sync.aligned.m16n8k16.row.col.f32.f16.f16.f32 "
        "{%0,%1,%2,%3},{%4,%5,%6,%7},{%8,%9},{%0,%1,%2,%3};"
        : "+f"(d[0]), "+f"(d[1]), "+f"(d[2]), "+f"(d[3])
        : "r"(a[0]), "r"(a[1]), "r"(a[2]), "r"(a[3]), "r"(b0), "r"(b1));
}
__device__ __forceinline__ float gelu_exact(float z) {
    return 0.5f * z * (1.0f + erff(z * 0.70710678118654752f));
}

// -------------------- globals -----------------------------------------------
__device__ u16 g_actA[(size_t)Bb * HW * C0];   // fp16 act plane [b][h][w][c]
__device__ u16 g_actB[(size_t)Bb * HW * C0];
__device__ ull g_T [(size_t)Bb * C0 * Hh * MX];
__device__ ull g_Xf[(size_t)Bb * C0 * 256];
__device__ ull g_G [(size_t)256 * Bb * C0];
__device__ u32 g_Qh32[(size_t)Bb * Hh * 1024];  // [(b*256+h)][o][ky]: fp16 (reh|imh<<16)
__device__ u32 g_Ql32[(size_t)Bb * Hh * 1024];
__device__ ull g_W2[(size_t)NL4 * 256 * 4096];
__device__ ull g_Fh2a[MX * Hh], g_Fh2b[MX * Hh];
__device__ ull g_Eh2a[Hh * MX], g_Eh2b[Hh * MX];
__device__ u16 g_PwH[NL4 * 4096], g_PwL[NL4 * 4096];  // fp16 hi/lo [l][o][c]
__device__ u16 g_SynF[256 * 32];                      // fp16 single [w][2ky+ri]
__device__ u16 g_FwAh[32 * 256], g_FwAl[32 * 256];    // fp16 hi/lo [2ky+ri][w]

// -------------------- merged prep -------------------------------------------
__global__ void k_prep(const float* __restrict__ pw_w) {
    int idx = blockIdx.x * 256 + threadIdx.x;   // 0..16383
    { u16 h, l; splitH(pw_w[idx], h, l); g_PwH[idx] = h; g_PwL[idx] = l; }
    if (idx < 4096) {
        int a = idx >> 8, p = idx & 255, m = (a * p) & 255;
        float s, c; sincospif((float)m * (1.0f / 128.0f), &s, &c);
        g_Fh2a[idx] = pk(c, -s);  g_Fh2b[idx] = pk(s, c);
        g_Eh2a[p * MX + a] = pk(c, s);  g_Eh2b[p * MX + a] = pk(-s, c);
    }
    if (idx < 8192) {
        {   // syn single fp16: [w][2ky+ri]
            int w = idx >> 5, j = idx & 31, ky = j >> 1, ri = j & 1;
            float s, c; sincospif((float)((ky * w) & 255) * (1.0f / 128.0f), &s, &c);
            float ck = ((ky == 0) ? 1.0f : 2.0f) * (1.0f / 256.0f);
            g_SynF[idx] = h16(ri ? s * ck : c * ck);
        }
        {   // fwd-DFT A hi/lo: [2ky+ri][w]
            int row = idx >> 8, w = idx & 255, ky = row >> 1, ri = row & 1;
            float s, c; sincospif((float)((ky * w) & 255) * (1.0f / 128.0f), &s, &c);
            float v = (ri ? -s : c) * (1.0f / 256.0f);
            u16 h, l; splitH(v, h, l);
            g_FwAh[idx] = h; g_FwAl[idx] = l;
        }
    }
}
__global__ void k_twt(const float* __restrict__ wr, const float* __restrict__ wi) {
    __shared__ ull tile[32][33];
    int l = blockIdx.z, tio = blockIdx.x, tm = blockIdx.y;
    int tx = threadIdx.x, ty = threadIdx.y;
    const float* wrl = wr + (size_t)l * 4096 * 256;
    const float* wil = wi + (size_t)l * 4096 * 256;
    #pragma unroll
    for (int r = 0; r < 4; r++) {
        int row = tio * 32 + ty + 8 * r, col = tm * 32 + tx;
        size_t idx = (size_t)row * 256 + col;
        tile[ty + 8 * r][tx] = pk(wrl[idx], wil[idx]);
    }
    __syncthreads();
    #pragma unroll
    for (int r = 0; r < 4; r++) {
        int mm = tm * 32 + ty + 8 * r, io = tio * 32 + tx;
        g_W2[(((size_t)l * 256) + mm) * 4096 + io] = tile[tx][ty + 8 * r];
    }
}

// -------------------- spectral trio -----------------------------------------
// fwd h-DFT: 512 threads, 2-way h-split, 4 indep chains, smem reduction.
__global__ __launch_bounds__(512, 3) void k_fwd_h() {
    __shared__ ull Ts[4096];
    __shared__ ull red[512];
    int bc = blockIdx.x, t = threadIdx.x;
    const ull* Tg = g_T + (size_t)bc * 4096;
    for (int i = t; i < 4096; i += 512) Ts[i] = Tg[i];
    __syncthreads();
    int hq = t >> 8;                 // 0..1
    int kx = (t >> 4) & 15, ky = t & 15;
    const ull* fak = g_Fh2a + kx * 256 + hq * 128;
    const ull* fbk = g_Fh2b + kx * 256 + hq * 128;
    const ull* Tp = Ts + hq * 2048 + ky;
    ull a0 = 0ull, a1 = 0ull, a2 = 0ull, a3 = 0ull;
    #pragma unroll 4
    for (int j = 0; j < 128; j += 4) {
        float tr, ti;
        upk(Tp[(j + 0) * 16], tr, ti);
        a0 = f2fma(pk(tr, tr), __ldg(fak + j + 0), a0);
        a0 = f2fma(pk(ti, ti), __ldg(fbk + j + 0), a0);
        upk(Tp[(j + 1) * 16], tr, ti);
        a1 = f2fma(pk(tr, tr), __ldg(fak + j + 1), a1);
        a1 = f2fma(pk(ti, ti), __ldg(fbk + j + 1), a1);
        upk(Tp[(j + 2) * 16], tr, ti);
        a2 = f2fma(pk(tr, tr), __ldg(fak + j + 2), a2);
        a2 = f2fma(pk(ti, ti), __ldg(fbk + j + 2), a2);
        upk(Tp[(j + 3) * 16], tr, ti);
        a3 = f2fma(pk(tr, tr), __ldg(fak + j + 3), a3);
        a3 = f2fma(pk(ti, ti), __ldg(fbk + j + 3), a3);
    }
    float x0, y0, x1, y1, x2, y2, x3, y3;
    upk(a0, x0, y0); upk(a1, x1, y1); upk(a2, x2, y2); upk(a3, x3, y3);
    red[t] = pk((x0 + x1) + (x2 + x3), (y0 + y1) + (y2 + y3));
    __syncthreads();
    if (t < 256) {
        float p0x, p0y, p1x, p1y;
        upk(red[t], p0x, p0y);
        upk(red[t + 256], p1x, p1y);
        g_Xf[(size_t)bc * 256 + t] = pk(p0x + p1x, p0y + p1y);
    }
}
__global__ __launch_bounds__(512, 2) void k_modegemm(int l) {
    __shared__ __align__(16) ull ws[4096];
    __shared__ ull xA[512], xB[512];
    int m = blockIdx.x, t = threadIdx.x;
    const ull* W = g_W2 + (((size_t)l * 256) + m) * 4096;
    for (int i = t; i < 4096; i += 512) ws[i] = W[i];
    {
        int b = t >> 6, i = t & 63;
        float xr, xi; upk(g_Xf[((size_t)b * C0 + i) * 256 + m], xr, xi);
        xA[t] = pk(xr, xr);
        xB[t] = pk(-xi, xi);
    }
    __syncthreads();
    int b = t >> 6, o = t & 63;
    ull acc = 0ull;
    const ull* xa = xA + b * 64;
    const ull* xb = xB + b * 64;
    #pragma unroll 4
    for (int i = 0; i < C0; i++) {
        ull w2 = ws[i * 64 + o];
        float wr, wi; upk(w2, wr, wi);
        acc = f2fma(xa[i], w2, acc);
        acc = f2fma(xb[i], pk(wi, wr), acc);
    }
    g_G[(size_t)m * 512 + t] = acc;
}
// inverse kx: 512 threads, 8 outputs each, tables via __ldg (smem = 2KB only)
__global__ __launch_bounds__(512, 3) void k_inv_h() {
    __shared__ ull Gs[256];
    int bo = blockIdx.x, t = threadIdx.x;
    int b = bo >> 6, o = bo & 63;
    if (t < 256) Gs[t] = g_G[(size_t)t * 512 + bo];
    __syncthreads();
    int hg = t >> 4, ky = t & 15;   // hg 0..31
    ull acc[8];
    #pragma unroll
    for (int i = 0; i < 8; i++) acc[i] = 0ull;
    #pragma unroll
    for (int kx = 0; kx < MX; kx++) {
        float gr, gi; upk(Gs[kx * 16 + ky], gr, gi);
        ull gr2 = pk(gr, gr), gi2 = pk(gi, gi);
        #pragma unroll
        for (int hp = 0; hp < 8; hp++) {
            int h = hp * 32 + hg;
            acc[hp] = f2fma(gr2, __ldg(g_Eh2a + h * 16 + kx), acc[hp]);
            acc[hp] = f2fma(gi2, __ldg(g_Eh2b + h * 16 + kx), acc[hp]);
        }
    }
    #pragma unroll
    for (int hp = 0; hp < 8; hp++) {
        int h = hp * 32 + hg;
        float re, im; upk(acc[hp], re, im);
        u16 rh, rl, ih2, il2;
        splitH(re, rh, rl);
        splitH(-im, ih2, il2);
        u32 idx = (((u32)b * 256 + h) * 64 + o) * 16 + ky;
        g_Qh32[idx] = (u32)rh | ((u32)ih2 << 16);
        g_Ql32[idx] = (u32)rl | ((u32)il2 << 16);
    }
}

// -------------------- fused HMMA layer kernel -------------------------------
// smem (bytes):
#define AOF 0          // 26624 = 128*104*2  (fp16 act+syn tile)
#define BHI 26624      // 13312 = 64*104*2
#define BLO 39936      // 13312
#define FWH 53248      // 8704 = 32*136*2
#define FWL 61952      // 8704
#define MSC 70656      // 3072
#define STG 73728      // 34816 (MODE 2 f32 stag [128][68])
#define SMEM_G 108544

// MODE: 0 = lift, 1 = mid layer, 2 = last layer (+head)
template <int MODE>
__global__ __launch_bounds__(256, 2)
void k_gemm(const u16* __restrict__ ain, u16* __restrict__ aout,
            const float* __restrict__ pw_b, int l,
            const float* __restrict__ x, const float* __restrict__ in_w,
            const float* __restrict__ in_b,
            float* __restrict__ out,
            const float* __restrict__ o1w, const float* __restrict__ o1b,
            const float* __restrict__ o2w, const float* __restrict__ o2b) {
    extern __shared__ __align__(16) char sm[];
    int h = blockIdx.x, b = blockIdx.y, t = threadIdx.x;
    int warp = t >> 5, lane = t & 31;
    u16* aT  = (u16*)(sm + AOF);
    u16* bHs = (u16*)(sm + BHI);
    u16* bLs = (u16*)(sm + BLO);
    u16* fwh = (u16*)(sm + FWH);
    u16* fwl = (u16*)(sm + FWL);
    float* bias = (float*)(sm + MSC);
    float* iwS  = (float*)(sm + MSC + 256);
    float* ibS  = (float*)(sm + MSC + 768);
    float* x0s  = (float*)(sm + MSC + 1024);
    float* x1s  = (float*)(sm + MSC + 1536);
    float* psum = (float*)(sm + MSC + 2048);
    u32 sa = smem_u32(sm);

    // ---- pre-loop staging ----
    if (MODE == 0) {
        if (t < 128) iwS[t] = in_w[t];
        if (t < 64) ibS[t] = in_b[t];
    } else {
        {   // pointwise weights (cols 0..63)
            const uint4* pH = (const uint4*)(g_PwH + l * 4096);
            const uint4* pL = (const uint4*)(g_PwL + l * 4096);
            for (int i = t; i < 512; i += 256) {
                int o = i >> 3, q = i & 7;
                *(uint4*)(bHs + o * LDA + q * 8) = pH[i];
                *(uint4*)(bLs + o * LDA + q * 8) = pL[i];
            }
        }
        {   // Q (cols 64..95)
            const uint4* qH = (const uint4*)(g_Qh32 + ((size_t)(b * 256 + h)) * 1024);
            const uint4* qL = (const uint4*)(g_Ql32 + ((size_t)(b * 256 + h)) * 1024);
            for (int i = t; i < 256; i += 256) {
                int o = i >> 2, q = i & 3;
                *(uint4*)(bHs + o * LDA + 64 + q * 8) = qH[i];
                *(uint4*)(bLs + o * LDA + 64 + q * 8) = qL[i];
            }
        }
        if (t < 64) bias[t] = pw_b[t];
        if (MODE == 2) {
            float* w1s = (float*)(sm + FWH);
            float* b1s = (float*)(sm + FWH + 8192);
            float* w2s = (float*)(sm + FWH + 8320);
            for (int i = t; i < 2048; i += 256) w1s[i] = o1w[i];
            if (t < 32) { b1s[t] = o1b[t]; w2s[t] = o2w[t]; }
        }
    }

    int mg = warp & 3, ng = warp >> 2;
    int aRow = (lane & 7) + ((lane >> 3) & 1) * 8;
    int aKq = (lane >> 4) * 8;
    int bSel = (lane >> 4) & 1, bN = lane & 7, bKq = ((lane >> 3) & 1) * 8;
    int mt2 = warp & 1, ng2 = warp >> 1;
    int trow = lane & 7, khalf = (lane >> 3) & 1, chalf = (lane >> 4) & 1;

    float dT[2][4];
    if (MODE != 2) {
        #pragma unroll
        for (int i1 = 0; i1 < 2; i1++)
            #pragma unroll
            for (int i2 = 0; i2 < 4; i2++) dT[i1][i2] = 0.0f;
    }

    for (int wv = 0; wv < 2; wv++) {
        // ---- A staging ----
        if (MODE == 0) {
            if (t < 128) x0s[t] = x[(((size_t)(b * 2)) * 256 + h) * 256 + wv * 128 + t];
            else x1s[t - 128] = x[(((size_t)(b * 2 + 1)) * 256 + h) * 256 + wv * 128 + (t - 128)];
            __syncthreads();
            for (int i = t; i < 8192; i += 256) {
                int w = i >> 6, c = i & 63;
                float v = fmaf(iwS[2 * c], x0s[w], fmaf(iwS[2 * c + 1], x1s[w], ibS[c]));
                aT[w * LDA + c] = h16(v);
            }
        } else {
            const uint4* sA = (const uint4*)(ain + (((size_t)(b * 256 + h)) * 256 + wv * 128) * 64);
            for (int i = t; i < 1024; i += 256) {
                int w = i >> 3, q = i & 7;
                ((uint4*)aT)[w * 13 + q] = sA[i];
            }
            // syn (cols 64..95), single fp16
            const uint4* yF = (const uint4*)(g_SynF + wv * 128 * 32);
            for (int i = t; i < 512; i += 256) {
                int w = i >> 2, q = i & 3;
                *(uint4*)(aT + w * LDA + 64 + q * 8) = yF[i];
            }
        }
        if (MODE != 2) {
            const uint4* fH = (const uint4*)(g_FwAh + wv * 128);
            const uint4* fL = (const uint4*)(g_FwAl + wv * 128);
            for (int i = t; i < 512; i += 256) {
                int r = i >> 4, q = i & 15;
                *(uint4*)(fwh + r * 136 + q * 8) = fH[r * 32 + q];
                *(uint4*)(fwl + r * 136 + q * 8) = fL[r * 32 + q];
            }
        }
        __syncthreads();   // S1

        if (MODE >= 1) {
            // ---- main MMA: D[128w x 64o], K=96, 2-pass (A exact fp16) ----
            float d[2][4][4];
            #pragma unroll
            for (int i1 = 0; i1 < 2; i1++)
                #pragma unroll
                for (int i2 = 0; i2 < 4; i2++)
                    #pragma unroll
                    for (int i3 = 0; i3 < 4; i3++) d[i1][i2][i3] = 0.0f;
            #pragma unroll
            for (int k6 = 0; k6 < 6; k6++) {
                int k0 = k6 * 16;
                u32 af[2][4];
                #pragma unroll
                for (int mt = 0; mt < 2; mt++) {
                    u32 ad = (u32)((32 * mg + mt * 16 + aRow) * LDA + k0 + aKq) * 2;
                    ldmx4(af[mt], sa + AOF + ad);
                }
                #pragma unroll
                for (int np = 0; np < 2; np++) {
                    int q0 = ng * 4 + np * 2;
                    u32 bd = (u32)(((q0 + bSel) * 8 + bN) * LDA + k0 + bKq) * 2;
                    u32 bh4[4], bl4[4];
                    ldmx4(bh4, sa + BHI + bd);
                    ldmx4(bl4, sa + BLO + bd);
                    #pragma unroll
                    for (int sub = 0; sub < 2; sub++) {
                        int nt = np * 2 + sub;
                        #pragma unroll
                        for (int mt = 0; mt < 2; mt++) {
                            mma16816(d[mt][nt], af[mt], bh4[2 * sub], bh4[2 * sub + 1]);
                            mma16816(d[mt][nt], af[mt], bl4[2 * sub], bl4[2 * sub + 1]);
                        }
                    }
                }
            }
            __syncthreads();   // S2

            // ---- epilogue ----
            int g = lane >> 2, c2 = lane & 3;
            if (MODE == 1) {
                #pragma unroll
                for (int mt = 0; mt < 2; mt++) {
                    int wl = 32 * mg + mt * 16 + g;
                    #pragma unroll
                    for (int nt = 0; nt < 4; nt++) {
                        int ob = (ng * 4 + nt) * 8 + 2 * c2;
                        float v0 = gelu_exact(d[mt][nt][0] + bias[ob]);
                        float v1 = gelu_exact(d[mt][nt][1] + bias[ob + 1]);
                        float v2 = gelu_exact(d[mt][nt][2] + bias[ob]);
                        float v3 = gelu_exact(d[mt][nt][3] + bias[ob + 1]);
                        *(u32*)(aT + wl * LDA + ob) = pkh2(v0, v1);
                        *(u32*)(aT + (wl + 8) * LDA + ob) = pkh2(v2, v3);
                    }
                }
            } else {
                float* stagf = (float*)(sm + STG);   // [128][68]
                #pragma unroll
                for (int mt = 0; mt < 2; mt++) {
                    int wl = 32 * mg + mt * 16 + g;
                    #pragma unroll
                    for (int nt = 0; nt < 4; nt++) {
                        int ob = (ng * 4 + nt) * 8 + 2 * c2;
                        stagf[wl * 68 + ob]           = gelu_exact(d[mt][nt][0] + bias[ob]);
                        stagf[wl * 68 + ob + 1]       = gelu_exact(d[mt][nt][1] + bias[ob + 1]);
                        stagf[(wl + 8) * 68 + ob]     = gelu_exact(d[mt][nt][2] + bias[ob]);
                        stagf[(wl + 8) * 68 + ob + 1] = gelu_exact(d[mt][nt][3] + bias[ob + 1]);
                    }
                }
            }
            __syncthreads();   // S3
        }

        if (MODE != 2) {
            // ---- act gmem store ----
            uint4* dA = (uint4*)(aout + (((size_t)(b * 256 + h)) * 256 + wv * 128) * 64);
            for (int i = t; i < 1024; i += 256) {
                int w = i >> 3, q = i & 7;
                dA[i] = ((uint4*)aT)[w * 13 + q];
            }
            // ---- fwd-w DFT GEMM: dT[32][64] += Fw[32][128] . act[128][64] ----
            #pragma unroll
            for (int ks = 0; ks < 8; ks++) {
                int k0 = ks * 16;
                u32 fh[4], fl[4], bv[4];
                u32 fad = (u32)((mt2 * 16 + aRow) * 136 + k0 + aKq) * 2;
                ldmx4(fh, sa + FWH + fad);
                ldmx4(fl, sa + FWL + fad);
                u32 bad = (u32)((k0 + khalf * 8 + trow) * LDA + ng2 * 16 + chalf * 8) * 2;
                ldmx4t(bv, sa + AOF + bad);
                #pragma unroll
                for (int nt = 0; nt < 2; nt++) {
                    mma16816(dT[nt], fh, bv[2 * nt], bv[2 * nt + 1]);
                    mma16816(dT[nt], fl, bv[2 * nt], bv[2 * nt + 1]);
                }
            }
            __syncthreads();   // S4
        } else {
            // ---- head ----
            float* stagf = (float*)(sm + STG);
            float* w1s = (float*)(sm + FWH);
            float* b1s = (float*)(sm + FWH + 8192);
            float* w2s = (float*)(sm + FWH + 8320);
            int p = t & 127, hf = t >> 7;
            ull x2[32];
            const float2* xr = (const float2*)(stagf + p * 68);
            #pragma unroll
            for (int j = 0; j < 32; j++) {
                float2 xx = xr[j];
                x2[j] = pk(xx.x, xx.y);
            }
            float acc = hf ? 0.0f : __ldg(o2b);
            for (int o2 = hf * 16; o2 < hf * 16 + 16; o2++) {
                ull s = pk(b1s[o2], 0.0f);
                const ulonglong2* wv2 = (const ulonglong2*)(w1s + o2 * 64);
                #pragma unroll
                for (int j = 0; j < 16; j++) {
                    ulonglong2 p4 = wv2[j];
                    s = f2fma(p4.x, x2[2 * j], s);
                    s = f2fma(p4.y, x2[2 * j + 1], s);
                }
                float lo, hi; upk(s, lo, hi);
                acc = fmaf(w2s[o2], gelu_exact(lo + hi), acc);
            }
            psum[hf * 128 + p] = acc;
            __syncthreads();   // S4
            if (t < 128)
                out[((size_t)(b * 256 + h)) * 256 + wv * 128 + t] = psum[t] + psum[128 + t];
            __syncthreads();   // S5
        }
    }

    if (MODE != 2) {
        // ---- store T ----
        float* Tf = (float*)g_T;
        int g = lane >> 2, c2 = lane & 3;
        #pragma unroll
        for (int nt = 0; nt < 2; nt++) {
            #pragma unroll
            for (int pr = 0; pr < 2; pr++) {
                int row = mt2 * 16 + g + pr * 8;
                int ky = row >> 1, ri = row & 1;
                int c = ng2 * 16 + nt * 8 + 2 * c2;
                size_t bse = (((size_t)(b * 64 + c)) * 256 + h) * 32 + ky * 2 + ri;
                Tf[bse] = dT[nt][pr * 2 + 0];
                Tf[bse + 8192] = dT[nt][pr * 2 + 1];
            }
        }
    }
}

// ---------------------------------------------------------------------------
extern "C" void kernel_launch(void* const* d_in, const int* in_sizes, int n_in,
                              void* d_out, int out_size) {
    const float* x       = (const float*)d_in[0];
    const float* in_w    = (const float*)d_in[1];
    const float* in_b    = (const float*)d_in[2];
    const float* spec_wr = (const float*)d_in[3];
    const float* spec_wi = (const float*)d_in[4];
    const float* pw_w    = (const float*)d_in[5];
    const float* pw_b    = (const float*)d_in[6];
    const float* o1w     = (const float*)d_in[7];
    const float* o1b     = (const float*)d_in[8];
    const float* o2w     = (const float*)d_in[9];
    const float* o2b     = (const float*)d_in[10];
    float* out = (float*)d_out;

    cudaFuncSetAttribute(k_gemm<0>, cudaFuncAttributeMaxDynamicSharedMemorySize, SMEM_G);
    cudaFuncSetAttribute(k_gemm<1>, cudaFuncAttributeMaxDynamicSharedMemorySize, SMEM_G);
    cudaFuncSetAttribute(k_gemm<2>, cudaFuncAttributeMaxDynamicSharedMemorySize, SMEM_G);

    u16 *aA, *aB;
    cudaGetSymbolAddress((void**)&aA, g_actA);
    cudaGetSymbolAddress((void**)&aB, g_actB);

    k_prep<<<64, 256>>>(pw_w);
    k_twt<<<dim3(128, 8, NL4), dim3(32, 8)>>>(spec_wr, spec_wi);

    dim3 grid(Hh, Bb);
    k_gemm<0><<<grid, 256, SMEM_G>>>(nullptr, aA, nullptr, 0,
                                     x, in_w, in_b, nullptr,
                                     nullptr, nullptr, nullptr, nullptr);

    const u16* cur = aA;
    u16* nxt = aB;
    for (int l = 0; l < NL4; l++) {
        k_fwd_h<<<Bb * C0, 512>>>();
        k_modegemm<<<256, 512>>>(l);
        k_inv_h<<<Bb * C0, 512>>>();
        if (l < NL4 - 1) {
            k_gemm<1><<<grid, 256, SMEM_G>>>(cur, nxt, pw_b + l * 64, l,
                                             nullptr, nullptr, nullptr, nullptr,
                                             nullptr, nullptr, nullptr, nullptr);
            const u16* tmp = cur; cur = nxt; nxt = (u16*)tmp;
        } else {
            k_gemm<2><<<grid, 256, SMEM_G>>>(cur, nullptr, pw_b + l * 64, l,
                                             nullptr, nullptr, nullptr, out,
                                             o1w, o1b, o2w, o2b);
        }
    }
}

// round 11
// speedup vs baseline: 3.1057x; 1.1000x over previous
#include <cuda_runtime.h>
#include <cuda_fp16.h>
#include <math.h>
#include <stdint.h>

#define Bb 8
#define C0 64
#define Hh 256
#define Ww 256
#define MX 16
#define NL4 4
#define HW 65536
#define LDA 104

typedef unsigned long long ull;
typedef unsigned int u32;
typedef unsigned short u16;

// -------------------- helpers ----------------------------------------------
__device__ __forceinline__ ull pk(float lo, float hi) {
    ull r; asm("mov.b64 %0,{%1,%2};" : "=l"(r) : "f"(lo), "f"(hi)); return r;
}
__device__ __forceinline__ void upk(ull v, float& lo, float& hi) {
    asm("mov.b64 {%0,%1},%2;" : "=f"(lo), "=f"(hi) : "l"(v));
}
__device__ __forceinline__ ull f2fma(ull a, ull b, ull c) {
    ull d; asm("fma.rn.f32x2 %0,%1,%2,%3;" : "=l"(d) : "l"(a), "l"(b), "l"(c)); return d;
}
__device__ __forceinline__ void splitH(float v, u16& hi, u16& lo) {
    __half h = __float2half_rn(v);
    hi = __half_as_ushort(h);
    lo = __half_as_ushort(__float2half_rn(v - __half2float(h)));
}
__device__ __forceinline__ u16 h16(float v) {
    return __half_as_ushort(__float2half_rn(v));
}
__device__ __forceinline__ u32 pkh2(float lo, float hi) {   // lo in bits 0..15
    u32 r; asm("cvt.rn.f16x2.f32 %0,%2,%1;" : "=r"(r) : "f"(lo), "f"(hi)); return r;
}
__device__ __forceinline__ u32 smem_u32(const void* p) {
    u32 a; asm("{ .reg .u64 t; cvta.to.shared.u64 t, %1; cvt.u32.u64 %0, t; }" : "=r"(a) : "l"(p));
    return a;
}
__device__ __forceinline__ void ldmx4(u32* r, u32 addr) {
    asm volatile("ldmatrix.sync.aligned.m8n8.x4.shared.b16 {%0,%1,%2,%3},[%4];"
        : "=r"(r[0]), "=r"(r[1]), "=r"(r[2]), "=r"(r[3]) : "r"(addr));
}
__device__ __forceinline__ void ldmx4t(u32* r, u32 addr) {
    asm volatile("ldmatrix.sync.aligned.m8n8.x4.trans.shared.b16 {%0,%1,%2,%3},[%4];"
        : "=r"(r[0]), "=r"(r[1]), "=r"(r[2]), "=r"(r[3]) : "r"(addr));
}
__device__ __forceinline__ void mma16816(float* d, const u32* a, u32 b0, u32 b1) {
    asm volatile("mma.sync.aligned.m16n8k16.row.col.f32.f16.f16.f32 "
        "{%0,%1,%2,%3},{%4,%5,%6,%7},{%8,%9},{%0,%1,%2,%3};"
        : "+f"(d[0]), "+f"(d[1]), "+f"(d[2]), "+f"(d[3])
        : "r"(a[0]), "r"(a[1]), "r"(a[2]), "r"(a[3]), "r"(b0), "r"(b1));
}
__device__ __forceinline__ float gelu_exact(float z) {
    return 0.5f * z * (1.0f + erff(z * 0.70710678118654752f));
}

// -------------------- globals -----------------------------------------------
__device__ u16 g_actA[(size_t)Bb * HW * C0];   // fp16 act plane [b][h][w][c]
__device__ u16 g_actB[(size_t)Bb * HW * C0];
__device__ ull g_T [(size_t)Bb * C0 * Hh * MX];  // [bc][h][ky] (re,im)
__device__ ull g_Xf[(size_t)Bb * C0 * 256];
__device__ ull g_G [(size_t)256 * Bb * C0];
__device__ u32 g_Qh32[(size_t)Bb * Hh * 1024];  // [(b*256+h)][o][ky]: fp16 (reh|imh<<16)
__device__ u32 g_Ql32[(size_t)Bb * Hh * 1024];
__device__ ull g_W2[(size_t)NL4 * 256 * 4096];
__device__ ull g_Fh2a[MX * Hh];                 // [kx][h] = (cos, -sin)
__device__ ull g_EaT[MX * Hh];                  // [kx][h] = (cos,  sin)
__device__ ull g_EbT[MX * Hh];                  // [kx][h] = (-sin, cos)
__device__ u16 g_PwH[NL4 * 4096], g_PwL[NL4 * 4096];  // fp16 hi/lo [l][o][c]
__device__ u16 g_SynF[256 * 32];                      // fp16 single [w][2ky+ri]
__device__ u16 g_FwAh[32 * 256], g_FwAl[32 * 256];    // fp16 hi/lo [2ky+ri][w]

// -------------------- merged prep -------------------------------------------
__global__ void k_prep(const float* __restrict__ pw_w) {
    int idx = blockIdx.x * 256 + threadIdx.x;   // 0..16383
    { u16 h, l; splitH(pw_w[idx], h, l); g_PwH[idx] = h; g_PwL[idx] = l; }
    if (idx < 4096) {
        int a = idx >> 8, p = idx & 255, m = (a * p) & 255;
        float s, c; sincospif((float)m * (1.0f / 128.0f), &s, &c);
        g_Fh2a[idx] = pk(c, -s);
        g_EaT[idx] = pk(c, s);
        g_EbT[idx] = pk(-s, c);
    }
    if (idx < 8192) {
        {   // syn single fp16: [w][2ky+ri]
            int w = idx >> 5, j = idx & 31, ky = j >> 1, ri = j & 1;
            float s, c; sincospif((float)((ky * w) & 255) * (1.0f / 128.0f), &s, &c);
            float ck = ((ky == 0) ? 1.0f : 2.0f) * (1.0f / 256.0f);
            g_SynF[idx] = h16(ri ? s * ck : c * ck);
        }
        {   // fwd-DFT A hi/lo: [2ky+ri][w]
            int row = idx >> 8, w = idx & 255, ky = row >> 1, ri = row & 1;
            float s, c; sincospif((float)((ky * w) & 255) * (1.0f / 128.0f), &s, &c);
            float v = (ri ? -s : c) * (1.0f / 256.0f);
            u16 h, l; splitH(v, h, l);
            g_FwAh[idx] = h; g_FwAl[idx] = l;
        }
    }
}
__global__ void k_twt(const float* __restrict__ wr, const float* __restrict__ wi) {
    __shared__ ull tile[32][33];
    int l = blockIdx.z, tio = blockIdx.x, tm = blockIdx.y;
    int tx = threadIdx.x, ty = threadIdx.y;
    const float* wrl = wr + (size_t)l * 4096 * 256;
    const float* wil = wi + (size_t)l * 4096 * 256;
    #pragma unroll
    for (int r = 0; r < 4; r++) {
        int row = tio * 32 + ty + 8 * r, col = tm * 32 + tx;
        size_t idx = (size_t)row * 256 + col;
        tile[ty + 8 * r][tx] = pk(wrl[idx], wil[idx]);
    }
    __syncthreads();
    #pragma unroll
    for (int r = 0; r < 4; r++) {
        int mm = tm * 32 + ty + 8 * r, io = tio * 32 + tx;
        g_W2[(((size_t)l * 256) + mm) * 4096 + io] = tile[tx][ty + 8 * r];
    }
}

// -------------------- spectral trio -----------------------------------------
// fwd h-DFT: thread = (kx, ky-pair, h-quarter); scalar 4-partial-sum form.
#define FWD_STEP(tv, cc, nn) \
    sA0 = fmaf(tv.x, cc, sA0); sB0 = fmaf(tv.y, nn, sB0); \
    sC0 = fmaf(tv.y, cc, sC0); sD0 = fmaf(tv.x, nn, sD0); \
    sA1 = fmaf(tv.z, cc, sA1); sB1 = fmaf(tv.w, nn, sB1); \
    sC1 = fmaf(tv.w, cc, sC1); sD1 = fmaf(tv.z, nn, sD1);

__global__ __launch_bounds__(512, 2) void k_fwd_h() {
    __shared__ ull Ts[4096];
    __shared__ ull red[1024];
    int bc = blockIdx.x, t = threadIdx.x;
    {
        const ulonglong2* Tg2 = (const ulonglong2*)(g_T + (size_t)bc * 4096);
        ulonglong2* Ts2 = (ulonglong2*)Ts;
        for (int i = t; i < 2048; i += 512) Ts2[i] = Tg2[i];
    }
    __syncthreads();
    int kyg = t & 7, kx = (t >> 3) & 15, hq = t >> 7;   // 8 ky-pairs, 16 kx, 4 hq
    const ulonglong2* fa2 = (const ulonglong2*)(g_Fh2a + kx * 256 + hq * 64);
    const float* Tp = (const float*)(Ts + (size_t)(hq * 64) * 16 + 2 * kyg);
    float sA0 = 0, sB0 = 0, sC0 = 0, sD0 = 0;
    float sA1 = 0, sB1 = 0, sC1 = 0, sD1 = 0;
    #pragma unroll 2
    for (int j = 0; j < 16; j++) {
        ulonglong2 fx = __ldg(fa2 + 2 * j);
        ulonglong2 fy = __ldg(fa2 + 2 * j + 1);
        float c0, n0, c1, n1, c2, n2, c3, n3;
        upk(fx.x, c0, n0); upk(fx.y, c1, n1);
        upk(fy.x, c2, n2); upk(fy.y, c3, n3);
        float4 t0 = *(const float4*)(Tp + (4 * j + 0) * 32);
        float4 t1 = *(const float4*)(Tp + (4 * j + 1) * 32);
        float4 t2 = *(const float4*)(Tp + (4 * j + 2) * 32);
        float4 t3 = *(const float4*)(Tp + (4 * j + 3) * 32);
        FWD_STEP(t0, c0, n0)
        FWD_STEP(t1, c1, n1)
        FWD_STEP(t2, c2, n2)
        FWD_STEP(t3, c3, n3)
    }
    // re = A - B, im = C + D
    *(ulonglong2*)(red + hq * 256 + kx * 16 + 2 * kyg) =
        make_ulonglong2(pk(sA0 - sB0, sC0 + sD0), pk(sA1 - sB1, sC1 + sD1));
    __syncthreads();
    if (t < 256) {
        float r0, i0, r1, i1, r2, i2, r3, i3;
        upk(red[t], r0, i0); upk(red[t + 256], r1, i1);
        upk(red[t + 512], r2, i2); upk(red[t + 768], r3, i3);
        g_Xf[(size_t)bc * 256 + t] = pk((r0 + r1) + (r2 + r3), (i0 + i1) + (i2 + i3));
    }
}

__global__ __launch_bounds__(512, 2) void k_modegemm(int l) {
    __shared__ __align__(16) ull ws[4096];
    __shared__ ull xA[512], xB[512];
    int m = blockIdx.x, t = threadIdx.x;
    {
        const ulonglong2* W2 = (const ulonglong2*)(g_W2 + (((size_t)l * 256) + m) * 4096);
        ulonglong2* ws2 = (ulonglong2*)ws;
        for (int i = t; i < 2048; i += 512) ws2[i] = W2[i];
    }
    {
        int b = t >> 6, i = t & 63;
        float xr, xi; upk(g_Xf[((size_t)b * C0 + i) * 256 + m], xr, xi);
        xA[t] = pk(xr, xr);
        xB[t] = pk(-xi, xi);
    }
    __syncthreads();
    int b = t >> 6, o = t & 63;
    ull acc = 0ull;
    const ull* xa = xA + b * 64;
    const ull* xb = xB + b * 64;
    #pragma unroll 4
    for (int i = 0; i < C0; i++) {
        ull w2 = ws[i * 64 + o];
        float wr, wi; upk(w2, wr, wi);
        acc = f2fma(xa[i], w2, acc);
        acc = f2fma(xb[i], pk(wi, wr), acc);
    }
    g_G[(size_t)m * 512 + t] = acc;
}

// inverse kx: thread = (ky-pair, contiguous 4-h range); vector twiddle loads.
__global__ __launch_bounds__(512, 2) void k_inv_h() {
    __shared__ ull Gs[256];
    int bo = blockIdx.x, t = threadIdx.x;
    int b = bo >> 6, o = bo & 63;
    if (t < 256) Gs[t] = g_G[(size_t)t * 512 + bo];
    __syncthreads();
    int kyg = t & 7, hg = t >> 3;        // 8 ky-pairs, hg 0..63, h = hg*4+hp
    ull a00 = 0, a01 = 0, a02 = 0, a03 = 0;
    ull a10 = 0, a11 = 0, a12 = 0, a13 = 0;
    #pragma unroll
    for (int kx = 0; kx < 16; kx++) {
        ulonglong2 g2 = *(const ulonglong2*)(Gs + kx * 16 + 2 * kyg);
        float gr0, gi0, gr1, gi1;
        upk(g2.x, gr0, gi0); upk(g2.y, gr1, gi1);
        ull gr20 = pk(gr0, gr0), gi20 = pk(gi0, gi0);
        ull gr21 = pk(gr1, gr1), gi21 = pk(gi1, gi1);
        const ulonglong2* ea = (const ulonglong2*)(g_EaT + kx * 256 + hg * 4);
        const ulonglong2* eb = (const ulonglong2*)(g_EbT + kx * 256 + hg * 4);
        ulonglong2 ea0 = __ldg(ea), ea1 = __ldg(ea + 1);
        ulonglong2 eb0 = __ldg(eb), eb1 = __ldg(eb + 1);
        a00 = f2fma(gr20, ea0.x, a00); a00 = f2fma(gi20, eb0.x, a00);
        a01 = f2fma(gr20, ea0.y, a01); a01 = f2fma(gi20, eb0.y, a01);
        a02 = f2fma(gr20, ea1.x, a02); a02 = f2fma(gi20, eb1.x, a02);
        a03 = f2fma(gr20, ea1.y, a03); a03 = f2fma(gi20, eb1.y, a03);
        a10 = f2fma(gr21, ea0.x, a10); a10 = f2fma(gi21, eb0.x, a10);
        a11 = f2fma(gr21, ea0.y, a11); a11 = f2fma(gi21, eb0.y, a11);
        a12 = f2fma(gr21, ea1.x, a12); a12 = f2fma(gi21, eb1.x, a12);
        a13 = f2fma(gr21, ea1.y, a13); a13 = f2fma(gi21, eb1.y, a13);
    }
    ull acc0[4] = {a00, a01, a02, a03};
    ull acc1[4] = {a10, a11, a12, a13};
    #pragma unroll
    for (int hp = 0; hp < 4; hp++) {
        int h = hg * 4 + hp;
        float re0, im0, re1, im1;
        upk(acc0[hp], re0, im0);
        upk(acc1[hp], re1, im1);
        u16 rh0, rl0, ih0, il0, rh1, rl1, ih1, il1;
        splitH(re0, rh0, rl0); splitH(-im0, ih0, il0);
        splitH(re1, rh1, rl1); splitH(-im1, ih1, il1);
        u32 base = (((u32)b * 256 + h) * 64 + o) * 16 + 2 * kyg;
        *(uint2*)(g_Qh32 + base) = make_uint2((u32)rh0 | ((u32)ih0 << 16),
                                              (u32)rh1 | ((u32)ih1 << 16));
        *(uint2*)(g_Ql32 + base) = make_uint2((u32)rl0 | ((u32)il0 << 16),
                                              (u32)rl1 | ((u32)il1 << 16));
    }
}

// -------------------- fused HMMA layer kernel -------------------------------
// smem (bytes):
#define AOF 0          // 26624 = 128*104*2  (fp16 act+syn tile)
#define BHI 26624      // 13312 = 64*104*2
#define BLO 39936      // 13312
#define FWH 53248      // 8704 = 32*136*2
#define FWL 61952      // 8704
#define MSC 70656      // 3072
#define STG 73728      // 34816 (MODE 2 f32 stag [128][68])
#define SMEM_G 108544

// MODE: 0 = lift, 1 = mid layer, 2 = last layer (+head)
template <int MODE>
__global__ __launch_bounds__(256, 2)
void k_gemm(const u16* __restrict__ ain, u16* __restrict__ aout,
            const float* __restrict__ pw_b, int l,
            const float* __restrict__ x, const float* __restrict__ in_w,
            const float* __restrict__ in_b,
            float* __restrict__ out,
            const float* __restrict__ o1w, const float* __restrict__ o1b,
            const float* __restrict__ o2w, const float* __restrict__ o2b) {
    extern __shared__ __align__(16) char sm[];
    int h = blockIdx.x, b = blockIdx.y, t = threadIdx.x;
    int warp = t >> 5, lane = t & 31;
    u16* aT  = (u16*)(sm + AOF);
    u16* bHs = (u16*)(sm + BHI);
    u16* bLs = (u16*)(sm + BLO);
    u16* fwh = (u16*)(sm + FWH);
    u16* fwl = (u16*)(sm + FWL);
    float* bias = (float*)(sm + MSC);
    float* iwS  = (float*)(sm + MSC + 256);
    float* ibS  = (float*)(sm + MSC + 768);
    float* x0s  = (float*)(sm + MSC + 1024);
    float* x1s  = (float*)(sm + MSC + 1536);
    float* psum = (float*)(sm + MSC + 2048);
    u32 sa = smem_u32(sm);

    // ---- pre-loop staging ----
    if (MODE == 0) {
        if (t < 128) iwS[t] = in_w[t];
        if (t < 64) ibS[t] = in_b[t];
    } else {
        {   // pointwise weights (cols 0..63)
            const uint4* pH = (const uint4*)(g_PwH + l * 4096);
            const uint4* pL = (const uint4*)(g_PwL + l * 4096);
            for (int i = t; i < 512; i += 256) {
                int o = i >> 3, q = i & 7;
                *(uint4*)(bHs + o * LDA + q * 8) = pH[i];
                *(uint4*)(bLs + o * LDA + q * 8) = pL[i];
            }
        }
        {   // Q (cols 64..95)
            const uint4* qH = (const uint4*)(g_Qh32 + ((size_t)(b * 256 + h)) * 1024);
            const uint4* qL = (const uint4*)(g_Ql32 + ((size_t)(b * 256 + h)) * 1024);
            for (int i = t; i < 256; i += 256) {
                int o = i >> 2, q = i & 3;
                *(uint4*)(bHs + o * LDA + 64 + q * 8) = qH[i];
                *(uint4*)(bLs + o * LDA + 64 + q * 8) = qL[i];
            }
        }
        if (t < 64) bias[t] = pw_b[t];
        if (MODE == 2) {
            float* w1s = (float*)(sm + FWH);
            float* b1s = (float*)(sm + FWH + 8192);
            float* w2s = (float*)(sm + FWH + 8320);
            for (int i = t; i < 2048; i += 256) w1s[i] = o1w[i];
            if (t < 32) { b1s[t] = o1b[t]; w2s[t] = o2w[t]; }
        }
    }

    int mg = warp & 3, ng = warp >> 2;
    int aRow = (lane & 7) + ((lane >> 3) & 1) * 8;
    int aKq = (lane >> 4) * 8;
    int bSel = (lane >> 4) & 1, bN = lane & 7, bKq = ((lane >> 3) & 1) * 8;
    int mt2 = warp & 1, ng2 = warp >> 1;
    int trow = lane & 7, khalf = (lane >> 3) & 1, chalf = (lane >> 4) & 1;

    float dT[2][4];
    if (MODE != 2) {
        #pragma unroll
        for (int i1 = 0; i1 < 2; i1++)
            #pragma unroll
            for (int i2 = 0; i2 < 4; i2++) dT[i1][i2] = 0.0f;
    }

    for (int wv = 0; wv < 2; wv++) {
        // ---- A staging ----
        if (MODE == 0) {
            if (t < 128) x0s[t] = x[(((size_t)(b * 2)) * 256 + h) * 256 + wv * 128 + t];
            else x1s[t - 128] = x[(((size_t)(b * 2 + 1)) * 256 + h) * 256 + wv * 128 + (t - 128)];
            __syncthreads();
            for (int i = t; i < 8192; i += 256) {
                int w = i >> 6, c = i & 63;
                float v = fmaf(iwS[2 * c], x0s[w], fmaf(iwS[2 * c + 1], x1s[w], ibS[c]));
                aT[w * LDA + c] = h16(v);
            }
        } else {
            const uint4* sA = (const uint4*)(ain + (((size_t)(b * 256 + h)) * 256 + wv * 128) * 64);
            for (int i = t; i < 1024; i += 256) {
                int w = i >> 3, q = i & 7;
                ((uint4*)aT)[w * 13 + q] = sA[i];
            }
            // syn (cols 64..95), single fp16
            const uint4* yF = (const uint4*)(g_SynF + wv * 128 * 32);
            for (int i = t; i < 512; i += 256) {
                int w = i >> 2, q = i & 3;
                *(uint4*)(aT + w * LDA + 64 + q * 8) = yF[i];
            }
        }
        if (MODE != 2) {
            const uint4* fH = (const uint4*)(g_FwAh + wv * 128);
            const uint4* fL = (const uint4*)(g_FwAl + wv * 128);
            for (int i = t; i < 512; i += 256) {
                int r = i >> 4, q = i & 15;
                *(uint4*)(fwh + r * 136 + q * 8) = fH[r * 32 + q];
                *(uint4*)(fwl + r * 136 + q * 8) = fL[r * 32 + q];
            }
        }
        __syncthreads();   // S1

        if (MODE >= 1) {
            // ---- main MMA: D[128w x 64o], K=96, 2-pass (A exact fp16) ----
            float d[2][4][4];
            #pragma unroll
            for (int i1 = 0; i1 < 2; i1++)
                #pragma unroll
                for (int i2 = 0; i2 < 4; i2++)
                    #pragma unroll
                    for (int i3 = 0; i3 < 4; i3++) d[i1][i2][i3] = 0.0f;
            #pragma unroll
            for (int k6 = 0; k6 < 6; k6++) {
                int k0 = k6 * 16;
                u32 af[2][4];
                #pragma unroll
                for (int mt = 0; mt < 2; mt++) {
                    u32 ad = (u32)((32 * mg + mt * 16 + aRow) * LDA + k0 + aKq) * 2;
                    ldmx4(af[mt], sa + AOF + ad);
                }
                #pragma unroll
                for (int np = 0; np < 2; np++) {
                    int q0 = ng * 4 + np * 2;
                    u32 bd = (u32)(((q0 + bSel) * 8 + bN) * LDA + k0 + bKq) * 2;
                    u32 bh4[4], bl4[4];
                    ldmx4(bh4, sa + BHI + bd);
                    ldmx4(bl4, sa + BLO + bd);
                    #pragma unroll
                    for (int sub = 0; sub < 2; sub++) {
                        int nt = np * 2 + sub;
                        #pragma unroll
                        for (int mt = 0; mt < 2; mt++) {
                            mma16816(d[mt][nt], af[mt], bh4[2 * sub], bh4[2 * sub + 1]);
                            mma16816(d[mt][nt], af[mt], bl4[2 * sub], bl4[2 * sub + 1]);
                        }
                    }
                }
            }
            __syncthreads();   // S2

            // ---- epilogue ----
            int g = lane >> 2, c2 = lane & 3;
            if (MODE == 1) {
                #pragma unroll
                for (int mt = 0; mt < 2; mt++) {
                    int wl = 32 * mg + mt * 16 + g;
                    #pragma unroll
                    for (int nt = 0; nt < 4; nt++) {
                        int ob = (ng * 4 + nt) * 8 + 2 * c2;
                        float v0 = gelu_exact(d[mt][nt][0] + bias[ob]);
                        float v1 = gelu_exact(d[mt][nt][1] + bias[ob + 1]);
                        float v2 = gelu_exact(d[mt][nt][2] + bias[ob]);
                        float v3 = gelu_exact(d[mt][nt][3] + bias[ob + 1]);
                        *(u32*)(aT + wl * LDA + ob) = pkh2(v0, v1);
                        *(u32*)(aT + (wl + 8) * LDA + ob) = pkh2(v2, v3);
                    }
                }
            } else {
                float* stagf = (float*)(sm + STG);   // [128][68]
                #pragma unroll
                for (int mt = 0; mt < 2; mt++) {
                    int wl = 32 * mg + mt * 16 + g;
                    #pragma unroll
                    for (int nt = 0; nt < 4; nt++) {
                        int ob = (ng * 4 + nt) * 8 + 2 * c2;
                        stagf[wl * 68 + ob]           = gelu_exact(d[mt][nt][0] + bias[ob]);
                        stagf[wl * 68 + ob + 1]       = gelu_exact(d[mt][nt][1] + bias[ob + 1]);
                        stagf[(wl + 8) * 68 + ob]     = gelu_exact(d[mt][nt][2] + bias[ob]);
                        stagf[(wl + 8) * 68 + ob + 1] = gelu_exact(d[mt][nt][3] + bias[ob + 1]);
                    }
                }
            }
            __syncthreads();   // S3
        }

        if (MODE != 2) {
            // ---- act gmem store ----
            uint4* dA = (uint4*)(aout + (((size_t)(b * 256 + h)) * 256 + wv * 128) * 64);
            for (int i = t; i < 1024; i += 256) {
                int w = i >> 3, q = i & 7;
                dA[i] = ((uint4*)aT)[w * 13 + q];
            }
            // ---- fwd-w DFT GEMM: dT[32][64] += Fw[32][128] . act[128][64] ----
            #pragma unroll
            for (int ks = 0; ks < 8; ks++) {
                int k0 = ks * 16;
                u32 fh[4], fl[4], bv[4];
                u32 fad = (u32)((mt2 * 16 + aRow) * 136 + k0 + aKq) * 2;
                ldmx4(fh, sa + FWH + fad);
                ldmx4(fl, sa + FWL + fad);
                u32 bad = (u32)((k0 + khalf * 8 + trow) * LDA + ng2 * 16 + chalf * 8) * 2;
                ldmx4t(bv, sa + AOF + bad);
                #pragma unroll
                for (int nt = 0; nt < 2; nt++) {
                    mma16816(dT[nt], fh, bv[2 * nt], bv[2 * nt + 1]);
                    mma16816(dT[nt], fl, bv[2 * nt], bv[2 * nt + 1]);
                }
            }
            __syncthreads();   // S4
        } else {
            // ---- head ----
            float* stagf = (float*)(sm + STG);
            float* w1s = (float*)(sm + FWH);
            float* b1s = (float*)(sm + FWH + 8192);
            float* w2s = (float*)(sm + FWH + 8320);
            int p = t & 127, hf = t >> 7;
            ull x2[32];
            const float2* xr = (const float2*)(stagf + p * 68);
            #pragma unroll
            for (int j = 0; j < 32; j++) {
                float2 xx = xr[j];
                x2[j] = pk(xx.x, xx.y);
            }
            float acc = hf ? 0.0f : __ldg(o2b);
            for (int o2 = hf * 16; o2 < hf * 16 + 16; o2++) {
                ull s = pk(b1s[o2], 0.0f);
                const ulonglong2* wv2 = (const ulonglong2*)(w1s + o2 * 64);
                #pragma unroll
                for (int j = 0; j < 16; j++) {
                    ulonglong2 p4 = wv2[j];
                    s = f2fma(p4.x, x2[2 * j], s);
                    s = f2fma(p4.y, x2[2 * j + 1], s);
                }
                float lo, hi; upk(s, lo, hi);
                acc = fmaf(w2s[o2], gelu_exact(lo + hi), acc);
            }
            psum[hf * 128 + p] = acc;
            __syncthreads();   // S4
            if (t < 128)
                out[((size_t)(b * 256 + h)) * 256 + wv * 128 + t] = psum[t] + psum[128 + t];
            __syncthreads();   // S5
        }
    }

    if (MODE != 2) {
        // ---- store T ----
        float* Tf = (float*)g_T;
        int g = lane >> 2, c2 = lane & 3;
        #pragma unroll
        for (int nt = 0; nt < 2; nt++) {
            #pragma unroll
            for (int pr = 0; pr < 2; pr++) {
                int row = mt2 * 16 + g + pr * 8;
                int ky = row >> 1, ri = row & 1;
                int c = ng2 * 16 + nt * 8 + 2 * c2;
                size_t bse = (((size_t)(b * 64 + c)) * 256 + h) * 32 + ky * 2 + ri;
                Tf[bse] = dT[nt][pr * 2 + 0];
                Tf[bse + 8192] = dT[nt][pr * 2 + 1];
            }
        }
    }
}

// ---------------------------------------------------------------------------
extern "C" void kernel_launch(void* const* d_in, const int* in_sizes, int n_in,
                              void* d_out, int out_size) {
    const float* x       = (const float*)d_in[0];
    const float* in_w    = (const float*)d_in[1];
    const float* in_b    = (const float*)d_in[2];
    const float* spec_wr = (const float*)d_in[3];
    const float* spec_wi = (const float*)d_in[4];
    const float* pw_w    = (const float*)d_in[5];
    const float* pw_b    = (const float*)d_in[6];
    const float* o1w     = (const float*)d_in[7];
    const float* o1b     = (const float*)d_in[8];
    const float* o2w     = (const float*)d_in[9];
    const float* o2b     = (const float*)d_in[10];
    float* out = (float*)d_out;

    cudaFuncSetAttribute(k_gemm<0>, cudaFuncAttributeMaxDynamicSharedMemorySize, SMEM_G);
    cudaFuncSetAttribute(k_gemm<1>, cudaFuncAttributeMaxDynamicSharedMemorySize, SMEM_G);
    cudaFuncSetAttribute(k_gemm<2>, cudaFuncAttributeMaxDynamicSharedMemorySize, SMEM_G);

    u16 *aA, *aB;
    cudaGetSymbolAddress((void**)&aA, g_actA);
    cudaGetSymbolAddress((void**)&aB, g_actB);

    k_prep<<<64, 256>>>(pw_w);
    k_twt<<<dim3(128, 8, NL4), dim3(32, 8)>>>(spec_wr, spec_wi);

    dim3 grid(Hh, Bb);
    k_gemm<0><<<grid, 256, SMEM_G>>>(nullptr, aA, nullptr, 0,
                                     x, in_w, in_b, nullptr,
                                     nullptr, nullptr, nullptr, nullptr);

    const u16* cur = aA;
    u16* nxt = aB;
    for (int l = 0; l < NL4; l++) {
        k_fwd_h<<<Bb * C0, 512>>>();
        k_modegemm<<<256, 512>>>(l);
        k_inv_h<<<Bb * C0, 512>>>();
        if (l < NL4 - 1) {
            k_gemm<1><<<grid, 256, SMEM_G>>>(cur, nxt, pw_b + l * 64, l,
                                             nullptr, nullptr, nullptr, nullptr,
                                             nullptr, nullptr, nullptr, nullptr);
            const u16* tmp = cur; cur = nxt; nxt = (u16*)tmp;
        } else {
            k_gemm<2><<<grid, 256, SMEM_G>>>(cur, nullptr, pw_b + l * 64, l,
                                             nullptr, nullptr, nullptr, out,
                                             o1w, o1b, o2w, o2b);
        }
    }
}

// round 12
// speedup vs baseline: 3.5226x; 1.1342x over previous
#include <cuda_runtime.h>
#include <cuda_fp16.h>
#include <math.h>
#include <stdint.h>

#define Bb 8
#define C0 64
#define Hh 256
#define Ww 256
#define MX 16
#define NL4 4
#define HW 65536
#define LDA 104

typedef unsigned long long ull;
typedef unsigned int u32;
typedef unsigned short u16;

// -------------------- helpers ----------------------------------------------
__device__ __forceinline__ ull pk(float lo, float hi) {
    ull r; asm("mov.b64 %0,{%1,%2};" : "=l"(r) : "f"(lo), "f"(hi)); return r;
}
__device__ __forceinline__ void upk(ull v, float& lo, float& hi) {
    asm("mov.b64 {%0,%1},%2;" : "=f"(lo), "=f"(hi) : "l"(v));
}
__device__ __forceinline__ ull f2fma(ull a, ull b, ull c) {
    ull d; asm("fma.rn.f32x2 %0,%1,%2,%3;" : "=l"(d) : "l"(a), "l"(b), "l"(c)); return d;
}
__device__ __forceinline__ void splitH(float v, u16& hi, u16& lo) {
    __half h = __float2half_rn(v);
    hi = __half_as_ushort(h);
    lo = __half_as_ushort(__float2half_rn(v - __half2float(h)));
}
__device__ __forceinline__ u16 h16(float v) {
    return __half_as_ushort(__float2half_rn(v));
}
__device__ __forceinline__ u32 pkh2(float lo, float hi) {   // lo in bits 0..15
    u32 r; asm("cvt.rn.f16x2.f32 %0,%2,%1;" : "=r"(r) : "f"(lo), "f"(hi)); return r;
}
__device__ __forceinline__ u32 smem_u32(const void* p) {
    u32 a; asm("{ .reg .u64 t; cvta.to.shared.u64 t, %1; cvt.u32.u64 %0, t; }" : "=r"(a) : "l"(p));
    return a;
}
__device__ __forceinline__ void ldmx4(u32* r, u32 addr) {
    asm volatile("ldmatrix.sync.aligned.m8n8.x4.shared.b16 {%0,%1,%2,%3},[%4];"
        : "=r"(r[0]), "=r"(r[1]), "=r"(r[2]), "=r"(r[3]) : "r"(addr));
}
__device__ __forceinline__ void ldmx4t(u32* r, u32 addr) {
    asm volatile("ldmatrix.sync.aligned.m8n8.x4.trans.shared.b16 {%0,%1,%2,%3},[%4];"
        : "=r"(r[0]), "=r"(r[1]), "=r"(r[2]), "=r"(r[3]) : "r"(addr));
}
__device__ __forceinline__ void mma16816(float* d, const u32* a, u32 b0, u32 b1) {
    asm volatile("mma.sync.aligned.m16n8k16.row.col.f32.f16.f16.f32 "
        "{%0,%1,%2,%3},{%4,%5,%6,%7},{%8,%9},{%0,%1,%2,%3};"
        : "+f"(d[0]), "+f"(d[1]), "+f"(d[2]), "+f"(d[3])
        : "r"(a[0]), "r"(a[1]), "r"(a[2]), "r"(a[3]), "r"(b0), "r"(b1));
}
__device__ __forceinline__ float gelu_exact(float z) {
    return 0.5f * z * (1.0f + erff(z * 0.70710678118654752f));
}

// -------------------- globals -----------------------------------------------
__device__ u16 g_actA[(size_t)Bb * HW * C0];   // fp16 act plane [b][h][w][c]
__device__ u16 g_actB[(size_t)Bb * HW * C0];
__device__ ull g_T [(size_t)Bb * C0 * Hh * MX];  // [bc][h][ky] (re,im)
__device__ ull g_Xf[(size_t)Bb * C0 * 256];
__device__ ull g_G [(size_t)256 * Bb * C0];
__device__ u32 g_Qh32[(size_t)Bb * Hh * 1024];  // [(b*256+h)][o][ky]: fp16 (reh|imh<<16)
__device__ u32 g_Ql32[(size_t)Bb * Hh * 1024];
__device__ ull g_W2[(size_t)NL4 * 256 * 4096];
__device__ ull g_Fh2a[MX * Hh];                 // [kx][h] = (cos, -sin)
__device__ ull g_EaT[MX * Hh];                  // [kx][h] = (cos,  sin)
__device__ ull g_EbT[MX * Hh];                  // [kx][h] = (-sin, cos)
__device__ u16 g_PwH[NL4 * 4096], g_PwL[NL4 * 4096];  // fp16 hi/lo [l][o][c]
__device__ u16 g_SynF[256 * 32];                      // fp16 single [w][2ky+ri]
__device__ u16 g_FwAh[32 * 256], g_FwAl[32 * 256];    // fp16 hi/lo [2ky+ri][w]

// -------------------- merged prep -------------------------------------------
__global__ void k_prep(const float* __restrict__ pw_w) {
    int idx = blockIdx.x * 256 + threadIdx.x;   // 0..16383
    { u16 h, l; splitH(pw_w[idx], h, l); g_PwH[idx] = h; g_PwL[idx] = l; }
    if (idx < 4096) {
        int a = idx >> 8, p = idx & 255, m = (a * p) & 255;
        float s, c; sincospif((float)m * (1.0f / 128.0f), &s, &c);
        g_Fh2a[idx] = pk(c, -s);
        g_EaT[idx] = pk(c, s);
        g_EbT[idx] = pk(-s, c);
    }
    if (idx < 8192) {
        {   // syn single fp16: [w][2ky+ri]
            int w = idx >> 5, j = idx & 31, ky = j >> 1, ri = j & 1;
            float s, c; sincospif((float)((ky * w) & 255) * (1.0f / 128.0f), &s, &c);
            float ck = ((ky == 0) ? 1.0f : 2.0f) * (1.0f / 256.0f);
            g_SynF[idx] = h16(ri ? s * ck : c * ck);
        }
        {   // fwd-DFT A hi/lo: [2ky+ri][w]
            int row = idx >> 8, w = idx & 255, ky = row >> 1, ri = row & 1;
            float s, c; sincospif((float)((ky * w) & 255) * (1.0f / 128.0f), &s, &c);
            float v = (ri ? -s : c) * (1.0f / 256.0f);
            u16 h, l; splitH(v, h, l);
            g_FwAh[idx] = h; g_FwAl[idx] = l;
        }
    }
}
__global__ void k_twt(const float* __restrict__ wr, const float* __restrict__ wi) {
    __shared__ ull tile[32][33];
    int l = blockIdx.z, tio = blockIdx.x, tm = blockIdx.y;
    int tx = threadIdx.x, ty = threadIdx.y;
    const float* wrl = wr + (size_t)l * 4096 * 256;
    const float* wil = wi + (size_t)l * 4096 * 256;
    #pragma unroll
    for (int r = 0; r < 4; r++) {
        int row = tio * 32 + ty + 8 * r, col = tm * 32 + tx;
        size_t idx = (size_t)row * 256 + col;
        tile[ty + 8 * r][tx] = pk(wrl[idx], wil[idx]);
    }
    __syncthreads();
    #pragma unroll
    for (int r = 0; r < 4; r++) {
        int mm = tm * 32 + ty + 8 * r, io = tio * 32 + tx;
        g_W2[(((size_t)l * 256) + mm) * 4096 + io] = tile[tx][ty + 8 * r];
    }
}

// -------------------- spectral trio -----------------------------------------
#define FWD_STEP(tv, cc, nn) \
    sA0 = fmaf(tv.x, cc, sA0); sB0 = fmaf(tv.y, nn, sB0); \
    sC0 = fmaf(tv.y, cc, sC0); sD0 = fmaf(tv.x, nn, sD0); \
    sA1 = fmaf(tv.z, cc, sA1); sB1 = fmaf(tv.w, nn, sB1); \
    sC1 = fmaf(tv.w, cc, sC1); sD1 = fmaf(tv.z, nn, sD1);

__global__ __launch_bounds__(512, 2) void k_fwd_h() {
    __shared__ ull Ts[4096];
    __shared__ ull red[1024];
    int bc = blockIdx.x, t = threadIdx.x;
    {
        const ulonglong2* Tg2 = (const ulonglong2*)(g_T + (size_t)bc * 4096);
        ulonglong2* Ts2 = (ulonglong2*)Ts;
        for (int i = t; i < 2048; i += 512) Ts2[i] = Tg2[i];
    }
    __syncthreads();
    int kyg = t & 7, kx = (t >> 3) & 15, hq = t >> 7;   // 8 ky-pairs, 16 kx, 4 hq
    const ulonglong2* fa2 = (const ulonglong2*)(g_Fh2a + kx * 256 + hq * 64);
    const float* Tp = (const float*)(Ts + (size_t)(hq * 64) * 16 + 2 * kyg);
    float sA0 = 0, sB0 = 0, sC0 = 0, sD0 = 0;
    float sA1 = 0, sB1 = 0, sC1 = 0, sD1 = 0;
    #pragma unroll 2
    for (int j = 0; j < 16; j++) {
        ulonglong2 fx = __ldg(fa2 + 2 * j);
        ulonglong2 fy = __ldg(fa2 + 2 * j + 1);
        float c0, n0, c1, n1, c2, n2, c3, n3;
        upk(fx.x, c0, n0); upk(fx.y, c1, n1);
        upk(fy.x, c2, n2); upk(fy.y, c3, n3);
        float4 t0 = *(const float4*)(Tp + (4 * j + 0) * 32);
        float4 t1 = *(const float4*)(Tp + (4 * j + 1) * 32);
        float4 t2 = *(const float4*)(Tp + (4 * j + 2) * 32);
        float4 t3 = *(const float4*)(Tp + (4 * j + 3) * 32);
        FWD_STEP(t0, c0, n0)
        FWD_STEP(t1, c1, n1)
        FWD_STEP(t2, c2, n2)
        FWD_STEP(t3, c3, n3)
    }
    *(ulonglong2*)(red + hq * 256 + kx * 16 + 2 * kyg) =
        make_ulonglong2(pk(sA0 - sB0, sC0 + sD0), pk(sA1 - sB1, sC1 + sD1));
    __syncthreads();
    if (t < 256) {
        float r0, i0, r1, i1, r2, i2, r3, i3;
        upk(red[t], r0, i0); upk(red[t + 256], r1, i1);
        upk(red[t + 512], r2, i2); upk(red[t + 768], r3, i3);
        g_Xf[(size_t)bc * 256 + t] = pk((r0 + r1) + (r2 + r3), (i0 + i1) + (i2 + i3));
    }
}

__global__ __launch_bounds__(512, 2) void k_modegemm(int l) {
    __shared__ __align__(16) ull ws[4096];
    __shared__ ull xA[512], xB[512];
    int m = blockIdx.x, t = threadIdx.x;
    {
        const ulonglong2* W2 = (const ulonglong2*)(g_W2 + (((size_t)l * 256) + m) * 4096);
        ulonglong2* ws2 = (ulonglong2*)ws;
        for (int i = t; i < 2048; i += 512) ws2[i] = W2[i];
    }
    {
        int b = t >> 6, i = t & 63;
        float xr, xi; upk(g_Xf[((size_t)b * C0 + i) * 256 + m], xr, xi);
        xA[t] = pk(xr, xr);
        xB[t] = pk(-xi, xi);
    }
    __syncthreads();
    int b = t >> 6, o = t & 63;
    ull acc0 = 0ull, acc1 = 0ull;
    const ull* xa = xA + b * 64;
    const ull* xb = xB + b * 64;
    #pragma unroll 4
    for (int i = 0; i < C0; i += 2) {
        ull w2 = ws[i * 64 + o];
        float wr, wi; upk(w2, wr, wi);
        acc0 = f2fma(xa[i], w2, acc0);
        acc0 = f2fma(xb[i], pk(wi, wr), acc0);
        ull w3 = ws[(i + 1) * 64 + o];
        float wr1, wi1; upk(w3, wr1, wi1);
        acc1 = f2fma(xa[i + 1], w3, acc1);
        acc1 = f2fma(xb[i + 1], pk(wi1, wr1), acc1);
    }
    float p0, q0, p1, q1;
    upk(acc0, p0, q0); upk(acc1, p1, q1);
    g_G[(size_t)m * 512 + t] = pk(p0 + p1, q0 + q1);
}

// inverse kx: thread = (ky-pair, contiguous 4-h range); vector twiddle loads.
__global__ __launch_bounds__(512, 2) void k_inv_h() {
    __shared__ ull Gs[256];
    int bo = blockIdx.x, t = threadIdx.x;
    int b = bo >> 6, o = bo & 63;
    if (t < 256) Gs[t] = g_G[(size_t)t * 512 + bo];
    __syncthreads();
    int kyg = t & 7, hg = t >> 3;        // 8 ky-pairs, hg 0..63, h = hg*4+hp
    ull a00 = 0, a01 = 0, a02 = 0, a03 = 0;
    ull a10 = 0, a11 = 0, a12 = 0, a13 = 0;
    #pragma unroll
    for (int kx = 0; kx < 16; kx++) {
        ulonglong2 g2 = *(const ulonglong2*)(Gs + kx * 16 + 2 * kyg);
        float gr0, gi0, gr1, gi1;
        upk(g2.x, gr0, gi0); upk(g2.y, gr1, gi1);
        ull gr20 = pk(gr0, gr0), gi20 = pk(gi0, gi0);
        ull gr21 = pk(gr1, gr1), gi21 = pk(gi1, gi1);
        const ulonglong2* ea = (const ulonglong2*)(g_EaT + kx * 256 + hg * 4);
        const ulonglong2* eb = (const ulonglong2*)(g_EbT + kx * 256 + hg * 4);
        ulonglong2 ea0 = __ldg(ea), ea1 = __ldg(ea + 1);
        ulonglong2 eb0 = __ldg(eb), eb1 = __ldg(eb + 1);
        a00 = f2fma(gr20, ea0.x, a00); a00 = f2fma(gi20, eb0.x, a00);
        a01 = f2fma(gr20, ea0.y, a01); a01 = f2fma(gi20, eb0.y, a01);
        a02 = f2fma(gr20, ea1.x, a02); a02 = f2fma(gi20, eb1.x, a02);
        a03 = f2fma(gr20, ea1.y, a03); a03 = f2fma(gi20, eb1.y, a03);
        a10 = f2fma(gr21, ea0.x, a10); a10 = f2fma(gi21, eb0.x, a10);
        a11 = f2fma(gr21, ea0.y, a11); a11 = f2fma(gi21, eb0.y, a11);
        a12 = f2fma(gr21, ea1.x, a12); a12 = f2fma(gi21, eb1.x, a12);
        a13 = f2fma(gr21, ea1.y, a13); a13 = f2fma(gi21, eb1.y, a13);
    }
    ull acc0[4] = {a00, a01, a02, a03};
    ull acc1[4] = {a10, a11, a12, a13};
    #pragma unroll
    for (int hp = 0; hp < 4; hp++) {
        int h = hg * 4 + hp;
        float re0, im0, re1, im1;
        upk(acc0[hp], re0, im0);
        upk(acc1[hp], re1, im1);
        u16 rh0, rl0, ih0, il0, rh1, rl1, ih1, il1;
        splitH(re0, rh0, rl0); splitH(-im0, ih0, il0);
        splitH(re1, rh1, rl1); splitH(-im1, ih1, il1);
        u32 base = (((u32)b * 256 + h) * 64 + o) * 16 + 2 * kyg;
        *(uint2*)(g_Qh32 + base) = make_uint2((u32)rh0 | ((u32)ih0 << 16),
                                              (u32)rh1 | ((u32)ih1 << 16));
        *(uint2*)(g_Ql32 + base) = make_uint2((u32)rl0 | ((u32)il0 << 16),
                                              (u32)rl1 | ((u32)il1 << 16));
    }
}

// -------------------- fused HMMA layer kernel -------------------------------
// smem (bytes):
#define AOF 0          // 26624 = 128*104*2  (fp16 act+syn tile)
#define BHI 26624      // 13312 = 64*104*2
#define BLO 39936      // 13312
#define FWH 53248      // 8704 = 32*136*2
#define FWL 61952      // 8704
#define MSC 70656      // 3072
#define STG 73728      // 34816 (MODE 2 f32 stag [128][68])
#define SMEM_S 73728   // MODE 0/1
#define SMEM_G 108544  // MODE 2

// MODE: 0 = lift, 1 = mid layer, 2 = last layer (+head)
template <int MODE>
__global__ __launch_bounds__(256, (MODE == 2 ? 2 : 3))
void k_gemm(const u16* __restrict__ ain, u16* __restrict__ aout,
            const float* __restrict__ pw_b, int l,
            const float* __restrict__ x, const float* __restrict__ in_w,
            const float* __restrict__ in_b,
            float* __restrict__ out,
            const float* __restrict__ o1w, const float* __restrict__ o1b,
            const float* __restrict__ o2w, const float* __restrict__ o2b) {
    extern __shared__ __align__(16) char sm[];
    int h = blockIdx.x, b = blockIdx.y, t = threadIdx.x;
    int warp = t >> 5, lane = t & 31;
    u16* aT  = (u16*)(sm + AOF);
    u16* bHs = (u16*)(sm + BHI);
    u16* bLs = (u16*)(sm + BLO);
    u16* fwh = (u16*)(sm + FWH);
    u16* fwl = (u16*)(sm + FWL);
    float* bias = (float*)(sm + MSC);
    float* iwS  = (float*)(sm + MSC + 256);
    float* ibS  = (float*)(sm + MSC + 768);
    float* x0s  = (float*)(sm + MSC + 1024);
    float* x1s  = (float*)(sm + MSC + 1536);
    float* psum = (float*)(sm + MSC + 2048);
    u32 sa = smem_u32(sm);

    // ---- pre-loop staging ----
    if (MODE == 0) {
        if (t < 128) iwS[t] = in_w[t];
        if (t < 64) ibS[t] = in_b[t];
    } else {
        {   // pointwise weights (cols 0..63)
            const uint4* pH = (const uint4*)(g_PwH + l * 4096);
            const uint4* pL = (const uint4*)(g_PwL + l * 4096);
            for (int i = t; i < 512; i += 256) {
                int o = i >> 3, q = i & 7;
                *(uint4*)(bHs + o * LDA + q * 8) = pH[i];
                *(uint4*)(bLs + o * LDA + q * 8) = pL[i];
            }
        }
        {   // Q (cols 64..95)
            const uint4* qH = (const uint4*)(g_Qh32 + ((size_t)(b * 256 + h)) * 1024);
            const uint4* qL = (const uint4*)(g_Ql32 + ((size_t)(b * 256 + h)) * 1024);
            for (int i = t; i < 256; i += 256) {
                int o = i >> 2, q = i & 3;
                *(uint4*)(bHs + o * LDA + 64 + q * 8) = qH[i];
                *(uint4*)(bLs + o * LDA + 64 + q * 8) = qL[i];
            }
        }
        if (t < 64) bias[t] = pw_b[t];
        if (MODE == 2) {
            float* w1s = (float*)(sm + FWH);
            float* b1s = (float*)(sm + FWH + 8192);
            float* w2s = (float*)(sm + FWH + 8320);
            for (int i = t; i < 2048; i += 256) w1s[i] = o1w[i];
            if (t < 32) { b1s[t] = o1b[t]; w2s[t] = o2w[t]; }
        }
    }

    int mg = warp & 3, ng = warp >> 2;
    int aRow = (lane & 7) + ((lane >> 3) & 1) * 8;
    int aKq = (lane >> 4) * 8;
    int bSel = (lane >> 4) & 1, bN = lane & 7, bKq = ((lane >> 3) & 1) * 8;
    int mt2 = warp & 1, ng2 = warp >> 1;
    int trow = lane & 7, khalf = (lane >> 3) & 1, chalf = (lane >> 4) & 1;

    float dT[2][4];
    if (MODE != 2) {
        #pragma unroll
        for (int i1 = 0; i1 < 2; i1++)
            #pragma unroll
            for (int i2 = 0; i2 < 4; i2++) dT[i1][i2] = 0.0f;
    }

    for (int wv = 0; wv < 2; wv++) {
        // ---- A staging ----
        if (MODE == 0) {
            if (t < 128) x0s[t] = x[(((size_t)(b * 2)) * 256 + h) * 256 + wv * 128 + t];
            else x1s[t - 128] = x[(((size_t)(b * 2 + 1)) * 256 + h) * 256 + wv * 128 + (t - 128)];
            __syncthreads();
            for (int i = t; i < 8192; i += 256) {
                int w = i >> 6, c = i & 63;
                float v = fmaf(iwS[2 * c], x0s[w], fmaf(iwS[2 * c + 1], x1s[w], ibS[c]));
                aT[w * LDA + c] = h16(v);
            }
        } else {
            const uint4* sA = (const uint4*)(ain + (((size_t)(b * 256 + h)) * 256 + wv * 128) * 64);
            for (int i = t; i < 1024; i += 256) {
                int w = i >> 3, q = i & 7;
                ((uint4*)aT)[w * 13 + q] = sA[i];
            }
            // syn (cols 64..95), single fp16
            const uint4* yF = (const uint4*)(g_SynF + wv * 128 * 32);
            for (int i = t; i < 512; i += 256) {
                int w = i >> 2, q = i & 3;
                *(uint4*)(aT + w * LDA + 64 + q * 8) = yF[i];
            }
        }
        if (MODE != 2) {
            const uint4* fH = (const uint4*)(g_FwAh + wv * 128);
            const uint4* fL = (const uint4*)(g_FwAl + wv * 128);
            for (int i = t; i < 512; i += 256) {
                int r = i >> 4, q = i & 15;
                *(uint4*)(fwh + r * 136 + q * 8) = fH[r * 32 + q];
                *(uint4*)(fwl + r * 136 + q * 8) = fL[r * 32 + q];
            }
        }
        __syncthreads();   // S1

        if (MODE >= 1) {
            // ---- main MMA: D[128w x 64o], K=96, 2-pass (A exact fp16) ----
            float d[2][4][4];
            #pragma unroll
            for (int i1 = 0; i1 < 2; i1++)
                #pragma unroll
                for (int i2 = 0; i2 < 4; i2++)
                    #pragma unroll
                    for (int i3 = 0; i3 < 4; i3++) d[i1][i2][i3] = 0.0f;
            #pragma unroll
            for (int k6 = 0; k6 < 6; k6++) {
                int k0 = k6 * 16;
                u32 af[2][4];
                #pragma unroll
                for (int mt = 0; mt < 2; mt++) {
                    u32 ad = (u32)((32 * mg + mt * 16 + aRow) * LDA + k0 + aKq) * 2;
                    ldmx4(af[mt], sa + AOF + ad);
                }
                #pragma unroll
                for (int np = 0; np < 2; np++) {
                    int q0 = ng * 4 + np * 2;
                    u32 bd = (u32)(((q0 + bSel) * 8 + bN) * LDA + k0 + bKq) * 2;
                    u32 bh4[4], bl4[4];
                    ldmx4(bh4, sa + BHI + bd);
                    ldmx4(bl4, sa + BLO + bd);
                    #pragma unroll
                    for (int sub = 0; sub < 2; sub++) {
                        int nt = np * 2 + sub;
                        #pragma unroll
                        for (int mt = 0; mt < 2; mt++) {
                            mma16816(d[mt][nt], af[mt], bh4[2 * sub], bh4[2 * sub + 1]);
                            mma16816(d[mt][nt], af[mt], bl4[2 * sub], bl4[2 * sub + 1]);
                        }
                    }
                }
            }
            __syncthreads();   // S2

            // ---- epilogue ----
            int g = lane >> 2, c2 = lane & 3;
            if (MODE == 1) {
                #pragma unroll
                for (int mt = 0; mt < 2; mt++) {
                    int wl = 32 * mg + mt * 16 + g;
                    #pragma unroll
                    for (int nt = 0; nt < 4; nt++) {
                        int ob = (ng * 4 + nt) * 8 + 2 * c2;
                        float v0 = gelu_exact(d[mt][nt][0] + bias[ob]);
                        float v1 = gelu_exact(d[mt][nt][1] + bias[ob + 1]);
                        float v2 = gelu_exact(d[mt][nt][2] + bias[ob]);
                        float v3 = gelu_exact(d[mt][nt][3] + bias[ob + 1]);
                        *(u32*)(aT + wl * LDA + ob) = pkh2(v0, v1);
                        *(u32*)(aT + (wl + 8) * LDA + ob) = pkh2(v2, v3);
                    }
                }
            } else {
                float* stagf = (float*)(sm + STG);   // [128][68]
                #pragma unroll
                for (int mt = 0; mt < 2; mt++) {
                    int wl = 32 * mg + mt * 16 + g;
                    #pragma unroll
                    for (int nt = 0; nt < 4; nt++) {
                        int ob = (ng * 4 + nt) * 8 + 2 * c2;
                        stagf[wl * 68 + ob]           = gelu_exact(d[mt][nt][0] + bias[ob]);
                        stagf[wl * 68 + ob + 1]       = gelu_exact(d[mt][nt][1] + bias[ob + 1]);
                        stagf[(wl + 8) * 68 + ob]     = gelu_exact(d[mt][nt][2] + bias[ob]);
                        stagf[(wl + 8) * 68 + ob + 1] = gelu_exact(d[mt][nt][3] + bias[ob + 1]);
                    }
                }
            }
            __syncthreads();   // S3
        }

        if (MODE != 2) {
            // ---- act gmem store ----
            uint4* dA = (uint4*)(aout + (((size_t)(b * 256 + h)) * 256 + wv * 128) * 64);
            for (int i = t; i < 1024; i += 256) {
                int w = i >> 3, q = i & 7;
                dA[i] = ((uint4*)aT)[w * 13 + q];
            }
            // ---- fwd-w DFT GEMM: dT[32][64] += Fw[32][128] . act[128][64] ----
            #pragma unroll
            for (int ks = 0; ks < 8; ks++) {
                int k0 = ks * 16;
                u32 fh[4], fl[4], bv[4];
                u32 fad = (u32)((mt2 * 16 + aRow) * 136 + k0 + aKq) * 2;
                ldmx4(fh, sa + FWH + fad);
                ldmx4(fl, sa + FWL + fad);
                u32 bad = (u32)((k0 + khalf * 8 + trow) * LDA + ng2 * 16 + chalf * 8) * 2;
                ldmx4t(bv, sa + AOF + bad);
                #pragma unroll
                for (int nt = 0; nt < 2; nt++) {
                    mma16816(dT[nt], fh, bv[2 * nt], bv[2 * nt + 1]);
                    mma16816(dT[nt], fl, bv[2 * nt], bv[2 * nt + 1]);
                }
            }
            __syncthreads();   // S4
        } else {
            // ---- head ----
            float* stagf = (float*)(sm + STG);
            float* w1s = (float*)(sm + FWH);
            float* b1s = (float*)(sm + FWH + 8192);
            float* w2s = (float*)(sm + FWH + 8320);
            int p = t & 127, hf = t >> 7;
            ull x2[32];
            const float2* xr = (const float2*)(stagf + p * 68);
            #pragma unroll
            for (int j = 0; j < 32; j++) {
                float2 xx = xr[j];
                x2[j] = pk(xx.x, xx.y);
            }
            float acc = hf ? 0.0f : __ldg(o2b);
            for (int o2 = hf * 16; o2 < hf * 16 + 16; o2++) {
                ull s = pk(b1s[o2], 0.0f);
                const ulonglong2* wv2 = (const ulonglong2*)(w1s + o2 * 64);
                #pragma unroll
                for (int j = 0; j < 16; j++) {
                    ulonglong2 p4 = wv2[j];
                    s = f2fma(p4.x, x2[2 * j], s);
                    s = f2fma(p4.y, x2[2 * j + 1], s);
                }
                float lo, hi; upk(s, lo, hi);
                acc = fmaf(w2s[o2], gelu_exact(lo + hi), acc);
            }
            psum[hf * 128 + p] = acc;
            __syncthreads();   // S4
            if (t < 128)
                out[((size_t)(b * 256 + h)) * 256 + wv * 128 + t] = psum[t] + psum[128 + t];
            __syncthreads();   // S5
        }
    }

    if (MODE != 2) {
        // ---- store T ----
        float* Tf = (float*)g_T;
        int g = lane >> 2, c2 = lane & 3;
        #pragma unroll
        for (int nt = 0; nt < 2; nt++) {
            #pragma unroll
            for (int pr = 0; pr < 2; pr++) {
                int row = mt2 * 16 + g + pr * 8;
                int ky = row >> 1, ri = row & 1;
                int c = ng2 * 16 + nt * 8 + 2 * c2;
                size_t bse = (((size_t)(b * 64 + c)) * 256 + h) * 32 + ky * 2 + ri;
                Tf[bse] = dT[nt][pr * 2 + 0];
                Tf[bse + 8192] = dT[nt][pr * 2 + 1];
            }
        }
    }
}

// ---------------------------------------------------------------------------
extern "C" void kernel_launch(void* const* d_in, const int* in_sizes, int n_in,
                              void* d_out, int out_size) {
    const float* x       = (const float*)d_in[0];
    const float* in_w    = (const float*)d_in[1];
    const float* in_b    = (const float*)d_in[2];
    const float* spec_wr = (const float*)d_in[3];
    const float* spec_wi = (const float*)d_in[4];
    const float* pw_w    = (const float*)d_in[5];
    const float* pw_b    = (const float*)d_in[6];
    const float* o1w     = (const float*)d_in[7];
    const float* o1b     = (const float*)d_in[8];
    const float* o2w     = (const float*)d_in[9];
    const float* o2b     = (const float*)d_in[10];
    float* out = (float*)d_out;

    cudaFuncSetAttribute(k_gemm<0>, cudaFuncAttributeMaxDynamicSharedMemorySize, SMEM_S);
    cudaFuncSetAttribute(k_gemm<1>, cudaFuncAttributeMaxDynamicSharedMemorySize, SMEM_S);
    cudaFuncSetAttribute(k_gemm<2>, cudaFuncAttributeMaxDynamicSharedMemorySize, SMEM_G);

    u16 *aA, *aB;
    cudaGetSymbolAddress((void**)&aA, g_actA);
    cudaGetSymbolAddress((void**)&aB, g_actB);

    k_prep<<<64, 256>>>(pw_w);
    k_twt<<<dim3(128, 8, NL4), dim3(32, 8)>>>(spec_wr, spec_wi);

    dim3 grid(Hh, Bb);
    k_gemm<0><<<grid, 256, SMEM_S>>>(nullptr, aA, nullptr, 0,
                                     x, in_w, in_b, nullptr,
                                     nullptr, nullptr, nullptr, nullptr);

    const u16* cur = aA;
    u16* nxt = aB;
    for (int l = 0; l < NL4; l++) {
        k_fwd_h<<<Bb * C0, 512>>>();
        k_modegemm<<<256, 512>>>(l);
        k_inv_h<<<Bb * C0, 512>>>();
        if (l < NL4 - 1) {
            k_gemm<1><<<grid, 256, SMEM_S>>>(cur, nxt, pw_b + l * 64, l,
                                             nullptr, nullptr, nullptr, nullptr,
                                             nullptr, nullptr, nullptr, nullptr);
            const u16* tmp = cur; cur = nxt; nxt = (u16*)tmp;
        } else {
            k_gemm<2><<<grid, 256, SMEM_G>>>(cur, nullptr, pw_b + l * 64, l,
                                             nullptr, nullptr, nullptr, out,
                                             o1w, o1b, o2w, o2b);
        }
    }
}

// round 13
// speedup vs baseline: 3.6603x; 1.0391x over previous
#include <cuda_runtime.h>
#include <cuda_fp16.h>
#include <math.h>
#include <stdint.h>

#define Bb 8
#define C0 64
#define Hh 256
#define Ww 256
#define MX 16
#define NL4 4
#define HW 65536
#define LDA 104

typedef unsigned long long ull;
typedef unsigned int u32;
typedef unsigned short u16;

// -------------------- helpers ----------------------------------------------
__device__ __forceinline__ ull pk(float lo, float hi) {
    ull r; asm("mov.b64 %0,{%1,%2};" : "=l"(r) : "f"(lo), "f"(hi)); return r;
}
__device__ __forceinline__ void upk(ull v, float& lo, float& hi) {
    asm("mov.b64 {%0,%1},%2;" : "=f"(lo), "=f"(hi) : "l"(v));
}
__device__ __forceinline__ ull f2fma(ull a, ull b, ull c) {
    ull d; asm("fma.rn.f32x2 %0,%1,%2,%3;" : "=l"(d) : "l"(a), "l"(b), "l"(c)); return d;
}
__device__ __forceinline__ void splitH(float v, u16& hi, u16& lo) {
    __half h = __float2half_rn(v);
    hi = __half_as_ushort(h);
    lo = __half_as_ushort(__float2half_rn(v - __half2float(h)));
}
__device__ __forceinline__ u16 h16(float v) {
    return __half_as_ushort(__float2half_rn(v));
}
__device__ __forceinline__ u32 pkh2(float lo, float hi) {   // lo in bits 0..15
    u32 r; asm("cvt.rn.f16x2.f32 %0,%2,%1;" : "=r"(r) : "f"(lo), "f"(hi)); return r;
}
__device__ __forceinline__ u32 smem_u32(const void* p) {
    u32 a; asm("{ .reg .u64 t; cvta.to.shared.u64 t, %1; cvt.u32.u64 %0, t; }" : "=r"(a) : "l"(p));
    return a;
}
__device__ __forceinline__ void ldmx4(u32* r, u32 addr) {
    asm volatile("ldmatrix.sync.aligned.m8n8.x4.shared.b16 {%0,%1,%2,%3},[%4];"
        : "=r"(r[0]), "=r"(r[1]), "=r"(r[2]), "=r"(r[3]) : "r"(addr));
}
__device__ __forceinline__ void ldmx4t(u32* r, u32 addr) {
    asm volatile("ldmatrix.sync.aligned.m8n8.x4.trans.shared.b16 {%0,%1,%2,%3},[%4];"
        : "=r"(r[0]), "=r"(r[1]), "=r"(r[2]), "=r"(r[3]) : "r"(addr));
}
__device__ __forceinline__ void mma16816(float* d, const u32* a, u32 b0, u32 b1) {
    asm volatile("mma.sync.aligned.m16n8k16.row.col.f32.f16.f16.f32 "
        "{%0,%1,%2,%3},{%4,%5,%6,%7},{%8,%9},{%0,%1,%2,%3};"
        : "+f"(d[0]), "+f"(d[1]), "+f"(d[2]), "+f"(d[3])
        : "r"(a[0]), "r"(a[1]), "r"(a[2]), "r"(a[3]), "r"(b0), "r"(b1));
}
__device__ __forceinline__ float gelu_exact(float z) {
    return 0.5f * z * (1.0f + erff(z * 0.70710678118654752f));
}

// -------------------- globals -----------------------------------------------
__device__ u16 g_actA[(size_t)Bb * HW * C0];   // fp16 act plane [b][h][w][c]
__device__ u16 g_actB[(size_t)Bb * HW * C0];
__device__ u16 g_T16[(size_t)Bb * C0 * Hh * 32]; // [bc][h][2ky+ri] fp16 (8.4MB)
__device__ ull g_Xf[(size_t)Bb * C0 * 256];
__device__ ull g_G [(size_t)256 * Bb * C0];
__device__ u32 g_Qh32[(size_t)Bb * Hh * 1024];  // [(b*256+h)][o][ky]: fp16 (reh|imh<<16)
__device__ u32 g_Ql32[(size_t)Bb * Hh * 1024];
__device__ u32 g_W216[(size_t)NL4 * 256 * 4096]; // [l][m][i*64+o] fp16 (wr|wi) 16.7MB
__device__ ull g_Fh2a[MX * Hh];                 // [kx][h] = (cos, -sin)
__device__ ull g_EaT[MX * Hh];                  // [kx][h] = (cos,  sin)
__device__ ull g_EbT[MX * Hh];                  // [kx][h] = (-sin, cos)
__device__ u16 g_PwH[NL4 * 4096], g_PwL[NL4 * 4096];  // fp16 hi/lo [l][o][c]
__device__ u16 g_SynF[256 * 32];                      // fp16 single [w][2ky+ri]
__device__ u16 g_FwAh[32 * 256], g_FwAl[32 * 256];    // fp16 hi/lo [2ky+ri][w]

// -------------------- merged prep -------------------------------------------
__global__ void k_prep(const float* __restrict__ pw_w) {
    int idx = blockIdx.x * 256 + threadIdx.x;   // 0..16383
    { u16 h, l; splitH(pw_w[idx], h, l); g_PwH[idx] = h; g_PwL[idx] = l; }
    if (idx < 4096) {
        int a = idx >> 8, p = idx & 255, m = (a * p) & 255;
        float s, c; sincospif((float)m * (1.0f / 128.0f), &s, &c);
        g_Fh2a[idx] = pk(c, -s);
        g_EaT[idx] = pk(c, s);
        g_EbT[idx] = pk(-s, c);
    }
    if (idx < 8192) {
        {   // syn single fp16: [w][2ky+ri]
            int w = idx >> 5, j = idx & 31, ky = j >> 1, ri = j & 1;
            float s, c; sincospif((float)((ky * w) & 255) * (1.0f / 128.0f), &s, &c);
            float ck = ((ky == 0) ? 1.0f : 2.0f) * (1.0f / 256.0f);
            g_SynF[idx] = h16(ri ? s * ck : c * ck);
        }
        {   // fwd-DFT A hi/lo: [2ky+ri][w]
            int row = idx >> 8, w = idx & 255, ky = row >> 1, ri = row & 1;
            float s, c; sincospif((float)((ky * w) & 255) * (1.0f / 128.0f), &s, &c);
            float v = (ri ? -s : c) * (1.0f / 256.0f);
            u16 h, l; splitH(v, h, l);
            g_FwAh[idx] = h; g_FwAl[idx] = l;
        }
    }
}
__global__ void k_twt(const float* __restrict__ wr, const float* __restrict__ wi) {
    __shared__ u32 tile[32][33];
    int l = blockIdx.z, tio = blockIdx.x, tm = blockIdx.y;
    int tx = threadIdx.x, ty = threadIdx.y;
    const float* wrl = wr + (size_t)l * 4096 * 256;
    const float* wil = wi + (size_t)l * 4096 * 256;
    #pragma unroll
    for (int r = 0; r < 4; r++) {
        int row = tio * 32 + ty + 8 * r, col = tm * 32 + tx;
        size_t idx = (size_t)row * 256 + col;
        tile[ty + 8 * r][tx] = pkh2(wrl[idx], wil[idx]);
    }
    __syncthreads();
    #pragma unroll
    for (int r = 0; r < 4; r++) {
        int mm = tm * 32 + ty + 8 * r, io = tio * 32 + tx;
        g_W216[(((size_t)l * 256) + mm) * 4096 + io] = tile[tx][ty + 8 * r];
    }
}

// -------------------- spectral trio -----------------------------------------
#define FWD_STEP(px, py, cc, nn) \
    sA0 = fmaf(px.x, cc, sA0); sB0 = fmaf(px.y, nn, sB0); \
    sC0 = fmaf(px.y, cc, sC0); sD0 = fmaf(px.x, nn, sD0); \
    sA1 = fmaf(py.x, cc, sA1); sB1 = fmaf(py.y, nn, sB1); \
    sC1 = fmaf(py.y, cc, sC1); sD1 = fmaf(py.x, nn, sD1);

__global__ __launch_bounds__(512, 3) void k_fwd_h() {
    __shared__ u32 Ts[4096];    // 16KB: [h][2*kyg(+1)] u32 = (re,im) fp16 pairs
    __shared__ ull red[1024];
    int bc = blockIdx.x, t = threadIdx.x;
    {
        const uint4* Tg4 = (const uint4*)(g_T16 + (size_t)bc * 8192);
        uint4* Ts4 = (uint4*)Ts;
        for (int i = t; i < 1024; i += 512) Ts4[i] = Tg4[i];
    }
    __syncthreads();
    int kyg = t & 7, kx = (t >> 3) & 15, hq = t >> 7;   // 8 ky-pairs, 16 kx, 4 hq
    const ulonglong2* fa2 = (const ulonglong2*)(g_Fh2a + kx * 256 + hq * 64);
    const u32* Tp = Ts + (hq * 64) * 16 + 2 * kyg;
    float sA0 = 0, sB0 = 0, sC0 = 0, sD0 = 0;
    float sA1 = 0, sB1 = 0, sC1 = 0, sD1 = 0;
    #pragma unroll 2
    for (int j = 0; j < 16; j++) {
        ulonglong2 fx = __ldg(fa2 + 2 * j);
        ulonglong2 fy = __ldg(fa2 + 2 * j + 1);
        float c0, n0, c1, n1, c2, n2, c3, n3;
        upk(fx.x, c0, n0); upk(fx.y, c1, n1);
        upk(fy.x, c2, n2); upk(fy.y, c3, n3);
        uint2 v0 = *(const uint2*)(Tp + (4 * j + 0) * 16);
        uint2 v1 = *(const uint2*)(Tp + (4 * j + 1) * 16);
        uint2 v2 = *(const uint2*)(Tp + (4 * j + 2) * 16);
        uint2 v3 = *(const uint2*)(Tp + (4 * j + 3) * 16);
        float2 p0, p1;
        p0 = __half22float2(*(__half2*)&v0.x); p1 = __half22float2(*(__half2*)&v0.y);
        FWD_STEP(p0, p1, c0, n0)
        p0 = __half22float2(*(__half2*)&v1.x); p1 = __half22float2(*(__half2*)&v1.y);
        FWD_STEP(p0, p1, c1, n1)
        p0 = __half22float2(*(__half2*)&v2.x); p1 = __half22float2(*(__half2*)&v2.y);
        FWD_STEP(p0, p1, c2, n2)
        p0 = __half22float2(*(__half2*)&v3.x); p1 = __half22float2(*(__half2*)&v3.y);
        FWD_STEP(p0, p1, c3, n3)
    }
    *(ulonglong2*)(red + hq * 256 + kx * 16 + 2 * kyg) =
        make_ulonglong2(pk(sA0 - sB0, sC0 + sD0), pk(sA1 - sB1, sC1 + sD1));
    __syncthreads();
    if (t < 256) {
        float r0, i0, r1, i1, r2, i2, r3, i3;
        upk(red[t], r0, i0); upk(red[t + 256], r1, i1);
        upk(red[t + 512], r2, i2); upk(red[t + 768], r3, i3);
        g_Xf[(size_t)bc * 256 + t] = pk((r0 + r1) + (r2 + r3), (i0 + i1) + (i2 + i3));
    }
}

__global__ __launch_bounds__(512, 3) void k_modegemm(int l) {
    __shared__ __align__(16) u32 ws[4096];   // 16KB fp16 pairs
    __shared__ ull xA[512], xB[512];
    int m = blockIdx.x, t = threadIdx.x;
    {
        const uint4* W4 = (const uint4*)(g_W216 + (((size_t)l * 256) + m) * 4096);
        uint4* ws4 = (uint4*)ws;
        for (int i = t; i < 1024; i += 512) ws4[i] = W4[i];
    }
    {
        int b = t >> 6, i = t & 63;
        float xr, xi; upk(g_Xf[((size_t)b * C0 + i) * 256 + m], xr, xi);
        xA[t] = pk(xr, xr);
        xB[t] = pk(-xi, xi);
    }
    __syncthreads();
    int b = t >> 6, o = t & 63;
    ull acc0 = 0ull, acc1 = 0ull;
    const ull* xa = xA + b * 64;
    const ull* xb = xB + b * 64;
    #pragma unroll 4
    for (int i = 0; i < C0; i += 2) {
        u32 w2 = ws[i * 64 + o];
        float2 wf = __half22float2(*(__half2*)&w2);
        acc0 = f2fma(xa[i], pk(wf.x, wf.y), acc0);
        acc0 = f2fma(xb[i], pk(wf.y, wf.x), acc0);
        u32 w3 = ws[(i + 1) * 64 + o];
        float2 wg = __half22float2(*(__half2*)&w3);
        acc1 = f2fma(xa[i + 1], pk(wg.x, wg.y), acc1);
        acc1 = f2fma(xb[i + 1], pk(wg.y, wg.x), acc1);
    }
    float p0, q0, p1, q1;
    upk(acc0, p0, q0); upk(acc1, p1, q1);
    g_G[(size_t)m * 512 + t] = pk(p0 + p1, q0 + q1);
}

// inverse kx: thread = (ky-pair, contiguous 4-h range); vector twiddle loads.
__global__ __launch_bounds__(512, 2) void k_inv_h() {
    __shared__ ull Gs[256];
    int bo = blockIdx.x, t = threadIdx.x;
    int b = bo >> 6, o = bo & 63;
    if (t < 256) Gs[t] = g_G[(size_t)t * 512 + bo];
    __syncthreads();
    int kyg = t & 7, hg = t >> 3;        // 8 ky-pairs, hg 0..63, h = hg*4+hp
    ull a00 = 0, a01 = 0, a02 = 0, a03 = 0;
    ull a10 = 0, a11 = 0, a12 = 0, a13 = 0;
    #pragma unroll
    for (int kx = 0; kx < 16; kx++) {
        ulonglong2 g2 = *(const ulonglong2*)(Gs + kx * 16 + 2 * kyg);
        float gr0, gi0, gr1, gi1;
        upk(g2.x, gr0, gi0); upk(g2.y, gr1, gi1);
        ull gr20 = pk(gr0, gr0), gi20 = pk(gi0, gi0);
        ull gr21 = pk(gr1, gr1), gi21 = pk(gi1, gi1);
        const ulonglong2* ea = (const ulonglong2*)(g_EaT + kx * 256 + hg * 4);
        const ulonglong2* eb = (const ulonglong2*)(g_EbT + kx * 256 + hg * 4);
        ulonglong2 ea0 = __ldg(ea), ea1 = __ldg(ea + 1);
        ulonglong2 eb0 = __ldg(eb), eb1 = __ldg(eb + 1);
        a00 = f2fma(gr20, ea0.x, a00); a00 = f2fma(gi20, eb0.x, a00);
        a01 = f2fma(gr20, ea0.y, a01); a01 = f2fma(gi20, eb0.y, a01);
        a02 = f2fma(gr20, ea1.x, a02); a02 = f2fma(gi20, eb1.x, a02);
        a03 = f2fma(gr20, ea1.y, a03); a03 = f2fma(gi20, eb1.y, a03);
        a10 = f2fma(gr21, ea0.x, a10); a10 = f2fma(gi21, eb0.x, a10);
        a11 = f2fma(gr21, ea0.y, a11); a11 = f2fma(gi21, eb0.y, a11);
        a12 = f2fma(gr21, ea1.x, a12); a12 = f2fma(gi21, eb1.x, a12);
        a13 = f2fma(gr21, ea1.y, a13); a13 = f2fma(gi21, eb1.y, a13);
    }
    ull acc0[4] = {a00, a01, a02, a03};
    ull acc1[4] = {a10, a11, a12, a13};
    #pragma unroll
    for (int hp = 0; hp < 4; hp++) {
        int h = hg * 4 + hp;
        float re0, im0, re1, im1;
        upk(acc0[hp], re0, im0);
        upk(acc1[hp], re1, im1);
        u16 rh0, rl0, ih0, il0, rh1, rl1, ih1, il1;
        splitH(re0, rh0, rl0); splitH(-im0, ih0, il0);
        splitH(re1, rh1, rl1); splitH(-im1, ih1, il1);
        u32 base = (((u32)b * 256 + h) * 64 + o) * 16 + 2 * kyg;
        *(uint2*)(g_Qh32 + base) = make_uint2((u32)rh0 | ((u32)ih0 << 16),
                                              (u32)rh1 | ((u32)ih1 << 16));
        *(uint2*)(g_Ql32 + base) = make_uint2((u32)rl0 | ((u32)il0 << 16),
                                              (u32)rl1 | ((u32)il1 << 16));
    }
}

// -------------------- fused HMMA layer kernel -------------------------------
// smem (bytes):
#define AOF 0          // 26624 = 128*104*2  (fp16 act+syn tile)
#define BHI 26624      // 13312 = 64*104*2
#define BLO 39936      // 13312
#define FWH 53248      // 8704 = 32*136*2
#define FWL 61952      // 8704
#define MSC 70656      // 3072
#define STG 73728      // 34816 (MODE 2 f32 stag [128][68])
#define SMEM_S 73728   // MODE 0/1
#define SMEM_G 108544  // MODE 2

// MODE: 0 = lift, 1 = mid layer, 2 = last layer (+head)
template <int MODE>
__global__ __launch_bounds__(256, (MODE == 2 ? 2 : 3))
void k_gemm(const u16* __restrict__ ain, u16* __restrict__ aout,
            const float* __restrict__ pw_b, int l,
            const float* __restrict__ x, const float* __restrict__ in_w,
            const float* __restrict__ in_b,
            float* __restrict__ out,
            const float* __restrict__ o1w, const float* __restrict__ o1b,
            const float* __restrict__ o2w, const float* __restrict__ o2b) {
    extern __shared__ __align__(16) char sm[];
    int h = blockIdx.x, b = blockIdx.y, t = threadIdx.x;
    int warp = t >> 5, lane = t & 31;
    u16* aT  = (u16*)(sm + AOF);
    u16* bHs = (u16*)(sm + BHI);
    u16* bLs = (u16*)(sm + BLO);
    u16* fwh = (u16*)(sm + FWH);
    u16* fwl = (u16*)(sm + FWL);
    float* bias = (float*)(sm + MSC);
    float* iwS  = (float*)(sm + MSC + 256);
    float* ibS  = (float*)(sm + MSC + 768);
    float* x0s  = (float*)(sm + MSC + 1024);
    float* x1s  = (float*)(sm + MSC + 1536);
    float* psum = (float*)(sm + MSC + 2048);
    u32 sa = smem_u32(sm);

    // ---- pre-loop staging ----
    if (MODE == 0) {
        if (t < 128) iwS[t] = in_w[t];
        if (t < 64) ibS[t] = in_b[t];
    } else {
        {   // pointwise weights (cols 0..63)
            const uint4* pH = (const uint4*)(g_PwH + l * 4096);
            const uint4* pL = (const uint4*)(g_PwL + l * 4096);
            for (int i = t; i < 512; i += 256) {
                int o = i >> 3, q = i & 7;
                *(uint4*)(bHs + o * LDA + q * 8) = pH[i];
                *(uint4*)(bLs + o * LDA + q * 8) = pL[i];
            }
        }
        {   // Q (cols 64..95)
            const uint4* qH = (const uint4*)(g_Qh32 + ((size_t)(b * 256 + h)) * 1024);
            const uint4* qL = (const uint4*)(g_Ql32 + ((size_t)(b * 256 + h)) * 1024);
            for (int i = t; i < 256; i += 256) {
                int o = i >> 2, q = i & 3;
                *(uint4*)(bHs + o * LDA + 64 + q * 8) = qH[i];
                *(uint4*)(bLs + o * LDA + 64 + q * 8) = qL[i];
            }
        }
        if (t < 64) bias[t] = pw_b[t];
        if (MODE == 2) {
            float* w1s = (float*)(sm + FWH);
            float* b1s = (float*)(sm + FWH + 8192);
            float* w2s = (float*)(sm + FWH + 8320);
            for (int i = t; i < 2048; i += 256) w1s[i] = o1w[i];
            if (t < 32) { b1s[t] = o1b[t]; w2s[t] = o2w[t]; }
        }
    }

    int mg = warp & 3, ng = warp >> 2;
    int aRow = (lane & 7) + ((lane >> 3) & 1) * 8;
    int aKq = (lane >> 4) * 8;
    int bSel = (lane >> 4) & 1, bN = lane & 7, bKq = ((lane >> 3) & 1) * 8;
    int mt2 = warp & 1, ng2 = warp >> 1;
    int trow = lane & 7, khalf = (lane >> 3) & 1, chalf = (lane >> 4) & 1;

    float dT[2][4];
    if (MODE != 2) {
        #pragma unroll
        for (int i1 = 0; i1 < 2; i1++)
            #pragma unroll
            for (int i2 = 0; i2 < 4; i2++) dT[i1][i2] = 0.0f;
    }

    for (int wv = 0; wv < 2; wv++) {
        // ---- A staging ----
        if (MODE == 0) {
            if (t < 128) x0s[t] = x[(((size_t)(b * 2)) * 256 + h) * 256 + wv * 128 + t];
            else x1s[t - 128] = x[(((size_t)(b * 2 + 1)) * 256 + h) * 256 + wv * 128 + (t - 128)];
            __syncthreads();
            for (int i = t; i < 8192; i += 256) {
                int w = i >> 6, c = i & 63;
                float v = fmaf(iwS[2 * c], x0s[w], fmaf(iwS[2 * c + 1], x1s[w], ibS[c]));
                aT[w * LDA + c] = h16(v);
            }
        } else {
            const uint4* sA = (const uint4*)(ain + (((size_t)(b * 256 + h)) * 256 + wv * 128) * 64);
            for (int i = t; i < 1024; i += 256) {
                int w = i >> 3, q = i & 7;
                ((uint4*)aT)[w * 13 + q] = sA[i];
            }
            // syn (cols 64..95), single fp16
            const uint4* yF = (const uint4*)(g_SynF + wv * 128 * 32);
            for (int i = t; i < 512; i += 256) {
                int w = i >> 2, q = i & 3;
                *(uint4*)(aT + w * LDA + 64 + q * 8) = yF[i];
            }
        }
        if (MODE != 2) {
            const uint4* fH = (const uint4*)(g_FwAh + wv * 128);
            const uint4* fL = (const uint4*)(g_FwAl + wv * 128);
            for (int i = t; i < 512; i += 256) {
                int r = i >> 4, q = i & 15;
                *(uint4*)(fwh + r * 136 + q * 8) = fH[r * 32 + q];
                *(uint4*)(fwl + r * 136 + q * 8) = fL[r * 32 + q];
            }
        }
        __syncthreads();   // S1

        if (MODE >= 1) {
            // ---- main MMA: D[128w x 64o], K=96, 2-pass (A exact fp16) ----
            float d[2][4][4];
            #pragma unroll
            for (int i1 = 0; i1 < 2; i1++)
                #pragma unroll
                for (int i2 = 0; i2 < 4; i2++)
                    #pragma unroll
                    for (int i3 = 0; i3 < 4; i3++) d[i1][i2][i3] = 0.0f;
            #pragma unroll
            for (int k6 = 0; k6 < 6; k6++) {
                int k0 = k6 * 16;
                u32 af[2][4];
                #pragma unroll
                for (int mt = 0; mt < 2; mt++) {
                    u32 ad = (u32)((32 * mg + mt * 16 + aRow) * LDA + k0 + aKq) * 2;
                    ldmx4(af[mt], sa + AOF + ad);
                }
                #pragma unroll
                for (int np = 0; np < 2; np++) {
                    int q0 = ng * 4 + np * 2;
                    u32 bd = (u32)(((q0 + bSel) * 8 + bN) * LDA + k0 + bKq) * 2;
                    u32 bh4[4], bl4[4];
                    ldmx4(bh4, sa + BHI + bd);
                    ldmx4(bl4, sa + BLO + bd);
                    #pragma unroll
                    for (int sub = 0; sub < 2; sub++) {
                        int nt = np * 2 + sub;
                        #pragma unroll
                        for (int mt = 0; mt < 2; mt++) {
                            mma16816(d[mt][nt], af[mt], bh4[2 * sub], bh4[2 * sub + 1]);
                            mma16816(d[mt][nt], af[mt], bl4[2 * sub], bl4[2 * sub + 1]);
                        }
                    }
                }
            }
            __syncthreads();   // S2

            // ---- epilogue ----
            int g = lane >> 2, c2 = lane & 3;
            if (MODE == 1) {
                #pragma unroll
                for (int mt = 0; mt < 2; mt++) {
                    int wl = 32 * mg + mt * 16 + g;
                    #pragma unroll
                    for (int nt = 0; nt < 4; nt++) {
                        int ob = (ng * 4 + nt) * 8 + 2 * c2;
                        float v0 = gelu_exact(d[mt][nt][0] + bias[ob]);
                        float v1 = gelu_exact(d[mt][nt][1] + bias[ob + 1]);
                        float v2 = gelu_exact(d[mt][nt][2] + bias[ob]);
                        float v3 = gelu_exact(d[mt][nt][3] + bias[ob + 1]);
                        *(u32*)(aT + wl * LDA + ob) = pkh2(v0, v1);
                        *(u32*)(aT + (wl + 8) * LDA + ob) = pkh2(v2, v3);
                    }
                }
            } else {
                float* stagf = (float*)(sm + STG);   // [128][68]
                #pragma unroll
                for (int mt = 0; mt < 2; mt++) {
                    int wl = 32 * mg + mt * 16 + g;
                    #pragma unroll
                    for (int nt = 0; nt < 4; nt++) {
                        int ob = (ng * 4 + nt) * 8 + 2 * c2;
                        stagf[wl * 68 + ob]           = gelu_exact(d[mt][nt][0] + bias[ob]);
                        stagf[wl * 68 + ob + 1]       = gelu_exact(d[mt][nt][1] + bias[ob + 1]);
                        stagf[(wl + 8) * 68 + ob]     = gelu_exact(d[mt][nt][2] + bias[ob]);
                        stagf[(wl + 8) * 68 + ob + 1] = gelu_exact(d[mt][nt][3] + bias[ob + 1]);
                    }
                }
            }
            __syncthreads();   // S3
        }

        if (MODE != 2) {
            // ---- act gmem store ----
            uint4* dA = (uint4*)(aout + (((size_t)(b * 256 + h)) * 256 + wv * 128) * 64);
            for (int i = t; i < 1024; i += 256) {
                int w = i >> 3, q = i & 7;
                dA[i] = ((uint4*)aT)[w * 13 + q];
            }
            // ---- fwd-w DFT GEMM: dT[32][64] += Fw[32][128] . act[128][64] ----
            #pragma unroll
            for (int ks = 0; ks < 8; ks++) {
                int k0 = ks * 16;
                u32 fh[4], fl[4], bv[4];
                u32 fad = (u32)((mt2 * 16 + aRow) * 136 + k0 + aKq) * 2;
                ldmx4(fh, sa + FWH + fad);
                ldmx4(fl, sa + FWL + fad);
                u32 bad = (u32)((k0 + khalf * 8 + trow) * LDA + ng2 * 16 + chalf * 8) * 2;
                ldmx4t(bv, sa + AOF + bad);
                #pragma unroll
                for (int nt = 0; nt < 2; nt++) {
                    mma16816(dT[nt], fh, bv[2 * nt], bv[2 * nt + 1]);
                    mma16816(dT[nt], fl, bv[2 * nt], bv[2 * nt + 1]);
                }
            }
            __syncthreads();   // S4
        } else {
            // ---- head ----
            float* stagf = (float*)(sm + STG);
            float* w1s = (float*)(sm + FWH);
            float* b1s = (float*)(sm + FWH + 8192);
            float* w2s = (float*)(sm + FWH + 8320);
            int p = t & 127, hf = t >> 7;
            ull x2[32];
            const float2* xr = (const float2*)(stagf + p * 68);
            #pragma unroll
            for (int j = 0; j < 32; j++) {
                float2 xx = xr[j];
                x2[j] = pk(xx.x, xx.y);
            }
            float acc = hf ? 0.0f : __ldg(o2b);
            for (int o2 = hf * 16; o2 < hf * 16 + 16; o2++) {
                ull s = pk(b1s[o2], 0.0f);
                const ulonglong2* wv2 = (const ulonglong2*)(w1s + o2 * 64);
                #pragma unroll
                for (int j = 0; j < 16; j++) {
                    ulonglong2 p4 = wv2[j];
                    s = f2fma(p4.x, x2[2 * j], s);
                    s = f2fma(p4.y, x2[2 * j + 1], s);
                }
                float lo, hi; upk(s, lo, hi);
                acc = fmaf(w2s[o2], gelu_exact(lo + hi), acc);
            }
            psum[hf * 128 + p] = acc;
            __syncthreads();   // S4
            if (t < 128)
                out[((size_t)(b * 256 + h)) * 256 + wv * 128 + t] = psum[t] + psum[128 + t];
            __syncthreads();   // S5
        }
    }

    if (MODE != 2) {
        // ---- store T (fp16) ----
        int g = lane >> 2, c2 = lane & 3;
        #pragma unroll
        for (int nt = 0; nt < 2; nt++) {
            #pragma unroll
            for (int pr = 0; pr < 2; pr++) {
                int row = mt2 * 16 + g + pr * 8;
                int ky = row >> 1, ri = row & 1;
                int c = ng2 * 16 + nt * 8 + 2 * c2;
                size_t bse = (((size_t)(b * 64 + c)) * 256 + h) * 32 + ky * 2 + ri;
                g_T16[bse] = h16(dT[nt][pr * 2 + 0]);
                g_T16[bse + 8192] = h16(dT[nt][pr * 2 + 1]);
            }
        }
    }
}

// ---------------------------------------------------------------------------
extern "C" void kernel_launch(void* const* d_in, const int* in_sizes, int n_in,
                              void* d_out, int out_size) {
    const float* x       = (const float*)d_in[0];
    const float* in_w    = (const float*)d_in[1];
    const float* in_b    = (const float*)d_in[2];
    const float* spec_wr = (const float*)d_in[3];
    const float* spec_wi = (const float*)d_in[4];
    const float* pw_w    = (const float*)d_in[5];
    const float* pw_b    = (const float*)d_in[6];
    const float* o1w     = (const float*)d_in[7];
    const float* o1b     = (const float*)d_in[8];
    const float* o2w     = (const float*)d_in[9];
    const float* o2b     = (const float*)d_in[10];
    float* out = (float*)d_out;

    cudaFuncSetAttribute(k_gemm<0>, cudaFuncAttributeMaxDynamicSharedMemorySize, SMEM_S);
    cudaFuncSetAttribute(k_gemm<1>, cudaFuncAttributeMaxDynamicSharedMemorySize, SMEM_S);
    cudaFuncSetAttribute(k_gemm<2>, cudaFuncAttributeMaxDynamicSharedMemorySize, SMEM_G);

    u16 *aA, *aB;
    cudaGetSymbolAddress((void**)&aA, g_actA);
    cudaGetSymbolAddress((void**)&aB, g_actB);

    k_prep<<<64, 256>>>(pw_w);
    k_twt<<<dim3(128, 8, NL4), dim3(32, 8)>>>(spec_wr, spec_wi);

    dim3 grid(Hh, Bb);
    k_gemm<0><<<grid, 256, SMEM_S>>>(nullptr, aA, nullptr, 0,
                                     x, in_w, in_b, nullptr,
                                     nullptr, nullptr, nullptr, nullptr);

    const u16* cur = aA;
    u16* nxt = aB;
    for (int l = 0; l < NL4; l++) {
        k_fwd_h<<<Bb * C0, 512>>>();
        k_modegemm<<<256, 512>>>(l);
        k_inv_h<<<Bb * C0, 512>>>();
        if (l < NL4 - 1) {
            k_gemm<1><<<grid, 256, SMEM_S>>>(cur, nxt, pw_b + l * 64, l,
                                             nullptr, nullptr, nullptr, nullptr,
                                             nullptr, nullptr, nullptr, nullptr);
            const u16* tmp = cur; cur = nxt; nxt = (u16*)tmp;
        } else {
            k_gemm<2><<<grid, 256, SMEM_G>>>(cur, nullptr, pw_b + l * 64, l,
                                             nullptr, nullptr, nullptr, out,
                                             o1w, o1b, o2w, o2b);
        }
    }
}

// round 14
// speedup vs baseline: 4.0134x; 1.0965x over previous
#include <cuda_runtime.h>
#include <cuda_fp16.h>
#include <math.h>
#include <stdint.h>

#define Bb 8
#define C0 64
#define Hh 256
#define Ww 256
#define MX 16
#define NL4 4
#define HW 65536
#define LDA 104

typedef unsigned long long ull;
typedef unsigned int u32;
typedef unsigned short u16;

// -------------------- helpers ----------------------------------------------
__device__ __forceinline__ ull pk(float lo, float hi) {
    ull r; asm("mov.b64 %0,{%1,%2};" : "=l"(r) : "f"(lo), "f"(hi)); return r;
}
__device__ __forceinline__ void upk(ull v, float& lo, float& hi) {
    asm("mov.b64 {%0,%1},%2;" : "=f"(lo), "=f"(hi) : "l"(v));
}
__device__ __forceinline__ ull f2fma(ull a, ull b, ull c) {
    ull d; asm("fma.rn.f32x2 %0,%1,%2,%3;" : "=l"(d) : "l"(a), "l"(b), "l"(c)); return d;
}
__device__ __forceinline__ void splitH(float v, u16& hi, u16& lo) {
    __half h = __float2half_rn(v);
    hi = __half_as_ushort(h);
    lo = __half_as_ushort(__float2half_rn(v - __half2float(h)));
}
__device__ __forceinline__ u16 h16(float v) {
    return __half_as_ushort(__float2half_rn(v));
}
__device__ __forceinline__ u32 pkh2(float lo, float hi) {   // lo in bits 0..15
    u32 r; asm("cvt.rn.f16x2.f32 %0,%2,%1;" : "=r"(r) : "f"(lo), "f"(hi)); return r;
}
__device__ __forceinline__ u32 smem_u32(const void* p) {
    u32 a; asm("{ .reg .u64 t; cvta.to.shared.u64 t, %1; cvt.u32.u64 %0, t; }" : "=r"(a) : "l"(p));
    return a;
}
__device__ __forceinline__ void ldmx4(u32* r, u32 addr) {
    asm volatile("ldmatrix.sync.aligned.m8n8.x4.shared.b16 {%0,%1,%2,%3},[%4];"
        : "=r"(r[0]), "=r"(r[1]), "=r"(r[2]), "=r"(r[3]) : "r"(addr));
}
__device__ __forceinline__ void ldmx4t(u32* r, u32 addr) {
    asm volatile("ldmatrix.sync.aligned.m8n8.x4.trans.shared.b16 {%0,%1,%2,%3},[%4];"
        : "=r"(r[0]), "=r"(r[1]), "=r"(r[2]), "=r"(r[3]) : "r"(addr));
}
__device__ __forceinline__ void mma16816(float* d, const u32* a, u32 b0, u32 b1) {
    asm volatile("mma.sync.aligned.m16n8k16.row.col.f32.f16.f16.f32 "
        "{%0,%1,%2,%3},{%4,%5,%6,%7},{%8,%9},{%0,%1,%2,%3};"
        : "+f"(d[0]), "+f"(d[1]), "+f"(d[2]), "+f"(d[3])
        : "r"(a[0]), "r"(a[1]), "r"(a[2]), "r"(a[3]), "r"(b0), "r"(b1));
}
__device__ __forceinline__ float gelu_exact(float z) {
    return 0.5f * z * (1.0f + erff(z * 0.70710678118654752f));
}

// -------------------- globals -----------------------------------------------
__device__ u16 g_actA[(size_t)Bb * HW * C0];   // fp16 act plane [b][h][w][c]
__device__ u16 g_actB[(size_t)Bb * HW * C0];
__device__ u16 g_T16[(size_t)Bb * C0 * Hh * 32]; // [bc][h][2ky+ri] fp16
__device__ ull g_Xf[(size_t)Bb * C0 * 256];
__device__ ull g_G [(size_t)256 * Bb * C0];
__device__ u32 g_Qh32[(size_t)Bb * Hh * 1024];  // [(b*256+h)][o][ky]: fp16 (re|-im<<16)
__device__ u32 g_W216[(size_t)NL4 * 256 * 4096]; // [l][m][i*64+o] fp16 (wr|wi)
__device__ ull g_Fh2a[MX * Hh];                 // [kx][h] = (cos, -sin)
__device__ ull g_EaT[MX * Hh];                  // [kx][h] = (cos,  sin)
__device__ ull g_EbT[MX * Hh];                  // [kx][h] = (-sin, cos)
__device__ u16 g_PwF[NL4 * 4096];               // fp16 single [l][o][c]
__device__ u16 g_SynF[256 * 32];                // fp16 single [w][2ky+ri]
__device__ u16 g_FwAh[32 * 256], g_FwAl[32 * 256]; // fp16 hi/lo [2ky+ri][w]

// -------------------- merged prep -------------------------------------------
__global__ void k_prep(const float* __restrict__ pw_w) {
    int idx = blockIdx.x * 256 + threadIdx.x;   // 0..16383
    g_PwF[idx] = h16(pw_w[idx]);
    if (idx < 4096) {
        int a = idx >> 8, p = idx & 255, m = (a * p) & 255;
        float s, c; sincospif((float)m * (1.0f / 128.0f), &s, &c);
        g_Fh2a[idx] = pk(c, -s);
        g_EaT[idx] = pk(c, s);
        g_EbT[idx] = pk(-s, c);
    }
    if (idx < 8192) {
        {   // syn single fp16: [w][2ky+ri]
            int w = idx >> 5, j = idx & 31, ky = j >> 1, ri = j & 1;
            float s, c; sincospif((float)((ky * w) & 255) * (1.0f / 128.0f), &s, &c);
            float ck = ((ky == 0) ? 1.0f : 2.0f) * (1.0f / 256.0f);
            g_SynF[idx] = h16(ri ? s * ck : c * ck);
        }
        {   // fwd-DFT A hi/lo: [2ky+ri][w]
            int row = idx >> 8, w = idx & 255, ky = row >> 1, ri = row & 1;
            float s, c; sincospif((float)((ky * w) & 255) * (1.0f / 128.0f), &s, &c);
            float v = (ri ? -s : c) * (1.0f / 256.0f);
            u16 h, l; splitH(v, h, l);
            g_FwAh[idx] = h; g_FwAl[idx] = l;
        }
    }
}
__global__ void k_twt(const float* __restrict__ wr, const float* __restrict__ wi) {
    __shared__ u32 tile[32][33];
    int l = blockIdx.z, tio = blockIdx.x, tm = blockIdx.y;
    int tx = threadIdx.x, ty = threadIdx.y;
    const float* wrl = wr + (size_t)l * 4096 * 256;
    const float* wil = wi + (size_t)l * 4096 * 256;
    #pragma unroll
    for (int r = 0; r < 4; r++) {
        int row = tio * 32 + ty + 8 * r, col = tm * 32 + tx;
        size_t idx = (size_t)row * 256 + col;
        tile[ty + 8 * r][tx] = pkh2(wrl[idx], wil[idx]);
    }
    __syncthreads();
    #pragma unroll
    for (int r = 0; r < 4; r++) {
        int mm = tm * 32 + ty + 8 * r, io = tio * 32 + tx;
        g_W216[(((size_t)l * 256) + mm) * 4096 + io] = tile[tx][ty + 8 * r];
    }
}

// -------------------- spectral trio -----------------------------------------
#define FWD_STEP(px, py, cc, nn) \
    sA0 = fmaf(px.x, cc, sA0); sB0 = fmaf(px.y, nn, sB0); \
    sC0 = fmaf(px.y, cc, sC0); sD0 = fmaf(px.x, nn, sD0); \
    sA1 = fmaf(py.x, cc, sA1); sB1 = fmaf(py.y, nn, sB1); \
    sC1 = fmaf(py.y, cc, sC1); sD1 = fmaf(py.x, nn, sD1);

__global__ __launch_bounds__(512, 3) void k_fwd_h() {
    __shared__ u32 Ts[4096];
    __shared__ ull red[1024];
    int bc = blockIdx.x, t = threadIdx.x;
    {
        const uint4* Tg4 = (const uint4*)(g_T16 + (size_t)bc * 8192);
        uint4* Ts4 = (uint4*)Ts;
        for (int i = t; i < 1024; i += 512) Ts4[i] = Tg4[i];
    }
    __syncthreads();
    int kyg = t & 7, kx = (t >> 3) & 15, hq = t >> 7;
    const ulonglong2* fa2 = (const ulonglong2*)(g_Fh2a + kx * 256 + hq * 64);
    const u32* Tp = Ts + (hq * 64) * 16 + 2 * kyg;
    float sA0 = 0, sB0 = 0, sC0 = 0, sD0 = 0;
    float sA1 = 0, sB1 = 0, sC1 = 0, sD1 = 0;
    #pragma unroll 2
    for (int j = 0; j < 16; j++) {
        ulonglong2 fx = __ldg(fa2 + 2 * j);
        ulonglong2 fy = __ldg(fa2 + 2 * j + 1);
        float c0, n0, c1, n1, c2, n2, c3, n3;
        upk(fx.x, c0, n0); upk(fx.y, c1, n1);
        upk(fy.x, c2, n2); upk(fy.y, c3, n3);
        uint2 v0 = *(const uint2*)(Tp + (4 * j + 0) * 16);
        uint2 v1 = *(const uint2*)(Tp + (4 * j + 1) * 16);
        uint2 v2 = *(const uint2*)(Tp + (4 * j + 2) * 16);
        uint2 v3 = *(const uint2*)(Tp + (4 * j + 3) * 16);
        float2 p0, p1;
        p0 = __half22float2(*(__half2*)&v0.x); p1 = __half22float2(*(__half2*)&v0.y);
        FWD_STEP(p0, p1, c0, n0)
        p0 = __half22float2(*(__half2*)&v1.x); p1 = __half22float2(*(__half2*)&v1.y);
        FWD_STEP(p0, p1, c1, n1)
        p0 = __half22float2(*(__half2*)&v2.x); p1 = __half22float2(*(__half2*)&v2.y);
        FWD_STEP(p0, p1, c2, n2)
        p0 = __half22float2(*(__half2*)&v3.x); p1 = __half22float2(*(__half2*)&v3.y);
        FWD_STEP(p0, p1, c3, n3)
    }
    *(ulonglong2*)(red + hq * 256 + kx * 16 + 2 * kyg) =
        make_ulonglong2(pk(sA0 - sB0, sC0 + sD0), pk(sA1 - sB1, sC1 + sD1));
    __syncthreads();
    if (t < 256) {
        float r0, i0, r1, i1, r2, i2, r3, i3;
        upk(red[t], r0, i0); upk(red[t + 256], r1, i1);
        upk(red[t + 512], r2, i2); upk(red[t + 768], r3, i3);
        g_Xf[(size_t)bc * 256 + t] = pk((r0 + r1) + (r2 + r3), (i0 + i1) + (i2 + i3));
    }
}

__global__ __launch_bounds__(512, 3) void k_modegemm(int l) {
    __shared__ __align__(16) u32 ws[4096];
    __shared__ ull xA[512], xB[512];
    int m = blockIdx.x, t = threadIdx.x;
    {
        const uint4* W4 = (const uint4*)(g_W216 + (((size_t)l * 256) + m) * 4096);
        uint4* ws4 = (uint4*)ws;
        for (int i = t; i < 1024; i += 512) ws4[i] = W4[i];
    }
    {
        int b = t >> 6, i = t & 63;
        float xr, xi; upk(g_Xf[((size_t)b * C0 + i) * 256 + m], xr, xi);
        xA[t] = pk(xr, xr);
        xB[t] = pk(-xi, xi);
    }
    __syncthreads();
    int b = t >> 6, o = t & 63;
    ull acc0 = 0ull, acc1 = 0ull;
    const ull* xa = xA + b * 64;
    const ull* xb = xB + b * 64;
    #pragma unroll 4
    for (int i = 0; i < C0; i += 2) {
        u32 w2 = ws[i * 64 + o];
        float2 wf = __half22float2(*(__half2*)&w2);
        acc0 = f2fma(xa[i], pk(wf.x, wf.y), acc0);
        acc0 = f2fma(xb[i], pk(wf.y, wf.x), acc0);
        u32 w3 = ws[(i + 1) * 64 + o];
        float2 wg = __half22float2(*(__half2*)&w3);
        acc1 = f2fma(xa[i + 1], pk(wg.x, wg.y), acc1);
        acc1 = f2fma(xb[i + 1], pk(wg.y, wg.x), acc1);
    }
    float p0, q0, p1, q1;
    upk(acc0, p0, q0); upk(acc1, p1, q1);
    g_G[(size_t)m * 512 + t] = pk(p0 + p1, q0 + q1);
}

// inverse kx: single fp16 Q plane output.
__global__ __launch_bounds__(512, 2) void k_inv_h() {
    __shared__ ull Gs[256];
    int bo = blockIdx.x, t = threadIdx.x;
    int b = bo >> 6, o = bo & 63;
    if (t < 256) Gs[t] = g_G[(size_t)t * 512 + bo];
    __syncthreads();
    int kyg = t & 7, hg = t >> 3;
    ull a00 = 0, a01 = 0, a02 = 0, a03 = 0;
    ull a10 = 0, a11 = 0, a12 = 0, a13 = 0;
    #pragma unroll
    for (int kx = 0; kx < 16; kx++) {
        ulonglong2 g2 = *(const ulonglong2*)(Gs + kx * 16 + 2 * kyg);
        float gr0, gi0, gr1, gi1;
        upk(g2.x, gr0, gi0); upk(g2.y, gr1, gi1);
        ull gr20 = pk(gr0, gr0), gi20 = pk(gi0, gi0);
        ull gr21 = pk(gr1, gr1), gi21 = pk(gi1, gi1);
        const ulonglong2* ea = (const ulonglong2*)(g_EaT + kx * 256 + hg * 4);
        const ulonglong2* eb = (const ulonglong2*)(g_EbT + kx * 256 + hg * 4);
        ulonglong2 ea0 = __ldg(ea), ea1 = __ldg(ea + 1);
        ulonglong2 eb0 = __ldg(eb), eb1 = __ldg(eb + 1);
        a00 = f2fma(gr20, ea0.x, a00); a00 = f2fma(gi20, eb0.x, a00);
        a01 = f2fma(gr20, ea0.y, a01); a01 = f2fma(gi20, eb0.y, a01);
        a02 = f2fma(gr20, ea1.x, a02); a02 = f2fma(gi20, eb1.x, a02);
        a03 = f2fma(gr20, ea1.y, a03); a03 = f2fma(gi20, eb1.y, a03);
        a10 = f2fma(gr21, ea0.x, a10); a10 = f2fma(gi21, eb0.x, a10);
        a11 = f2fma(gr21, ea0.y, a11); a11 = f2fma(gi21, eb0.y, a11);
        a12 = f2fma(gr21, ea1.x, a12); a12 = f2fma(gi21, eb1.x, a12);
        a13 = f2fma(gr21, ea1.y, a13); a13 = f2fma(gi21, eb1.y, a13);
    }
    ull acc0[4] = {a00, a01, a02, a03};
    ull acc1[4] = {a10, a11, a12, a13};
    #pragma unroll
    for (int hp = 0; hp < 4; hp++) {
        int h = hg * 4 + hp;
        float re0, im0, re1, im1;
        upk(acc0[hp], re0, im0);
        upk(acc1[hp], re1, im1);
        u32 base = (((u32)b * 256 + h) * 64 + o) * 16 + 2 * kyg;
        *(uint2*)(g_Qh32 + base) = make_uint2(
            (u32)h16(re0) | ((u32)h16(-im0) << 16),
            (u32)h16(re1) | ((u32)h16(-im1) << 16));
    }
}

// -------------------- fused HMMA layer kernel -------------------------------
// smem (bytes):
#define AOF 0          // 26624 = 128*104*2  (fp16 act+syn tile)
#define BHI 26624      // 13312 = 64*104*2 (single fp16 B)
#define FWH 39936      // 8704 = 32*136*2
#define FWL 48640      // 8704
#define MSC 57344      // 3072
#define STG 60416      // 34816 (MODE 2 f32 stag [128][68])
#define SMEM_S 60416   // MODE 0/1
#define SMEM_G 95232   // MODE 2

// MODE: 0 = lift, 1 = mid layer, 2 = last layer (+head)
template <int MODE>
__global__ __launch_bounds__(256, (MODE == 2 ? 2 : 3))
void k_gemm(const u16* __restrict__ ain, u16* __restrict__ aout,
            const float* __restrict__ pw_b, int l,
            const float* __restrict__ x, const float* __restrict__ in_w,
            const float* __restrict__ in_b,
            float* __restrict__ out,
            const float* __restrict__ o1w, const float* __restrict__ o1b,
            const float* __restrict__ o2w, const float* __restrict__ o2b) {
    extern __shared__ __align__(16) char sm[];
    int h = blockIdx.x, b = blockIdx.y, t = threadIdx.x;
    int warp = t >> 5, lane = t & 31;
    u16* aT  = (u16*)(sm + AOF);
    u16* bHs = (u16*)(sm + BHI);
    u16* fwh = (u16*)(sm + FWH);
    u16* fwl = (u16*)(sm + FWL);
    float* bias = (float*)(sm + MSC);
    float* iwS  = (float*)(sm + MSC + 256);
    float* ibS  = (float*)(sm + MSC + 768);
    float* x0s  = (float*)(sm + MSC + 1024);
    float* x1s  = (float*)(sm + MSC + 1536);
    float* psum = (float*)(sm + MSC + 2048);
    u32 sa = smem_u32(sm);

    // ---- pre-loop staging ----
    if (MODE == 0) {
        if (t < 128) iwS[t] = in_w[t];
        if (t < 64) ibS[t] = in_b[t];
    } else {
        {   // pointwise weights (cols 0..63), single fp16
            const uint4* pF = (const uint4*)(g_PwF + l * 4096);
            for (int i = t; i < 512; i += 256) {
                int o = i >> 3, q = i & 7;
                *(uint4*)(bHs + o * LDA + q * 8) = pF[i];
            }
        }
        {   // Q (cols 64..95), single fp16
            const uint4* qH = (const uint4*)(g_Qh32 + ((size_t)(b * 256 + h)) * 1024);
            for (int i = t; i < 256; i += 256) {
                int o = i >> 2, q = i & 3;
                *(uint4*)(bHs + o * LDA + 64 + q * 8) = qH[i];
            }
        }
        if (t < 64) bias[t] = pw_b[t];
        if (MODE == 2) {
            float* w1s = (float*)(sm + FWH);
            float* b1s = (float*)(sm + FWH + 8192);
            float* w2s = (float*)(sm + FWH + 8320);
            for (int i = t; i < 2048; i += 256) w1s[i] = o1w[i];
            if (t < 32) { b1s[t] = o1b[t]; w2s[t] = o2w[t]; }
        }
    }

    int mg = warp & 3, ng = warp >> 2;
    int aRow = (lane & 7) + ((lane >> 3) & 1) * 8;
    int aKq = (lane >> 4) * 8;
    int bSel = (lane >> 4) & 1, bN = lane & 7, bKq = ((lane >> 3) & 1) * 8;
    int mt2 = warp & 1, ng2 = warp >> 1;
    int trow = lane & 7, khalf = (lane >> 3) & 1, chalf = (lane >> 4) & 1;

    float dT[2][4];
    if (MODE != 2) {
        #pragma unroll
        for (int i1 = 0; i1 < 2; i1++)
            #pragma unroll
            for (int i2 = 0; i2 < 4; i2++) dT[i1][i2] = 0.0f;
    }

    for (int wv = 0; wv < 2; wv++) {
        // ---- A staging ----
        if (MODE == 0) {
            if (t < 128) x0s[t] = x[(((size_t)(b * 2)) * 256 + h) * 256 + wv * 128 + t];
            else x1s[t - 128] = x[(((size_t)(b * 2 + 1)) * 256 + h) * 256 + wv * 128 + (t - 128)];
            __syncthreads();
            for (int i = t; i < 8192; i += 256) {
                int w = i >> 6, c = i & 63;
                float v = fmaf(iwS[2 * c], x0s[w], fmaf(iwS[2 * c + 1], x1s[w], ibS[c]));
                aT[w * LDA + c] = h16(v);
            }
        } else {
            const uint4* sA = (const uint4*)(ain + (((size_t)(b * 256 + h)) * 256 + wv * 128) * 64);
            for (int i = t; i < 1024; i += 256) {
                int w = i >> 3, q = i & 7;
                ((uint4*)aT)[w * 13 + q] = sA[i];
            }
            const uint4* yF = (const uint4*)(g_SynF + wv * 128 * 32);
            for (int i = t; i < 512; i += 256) {
                int w = i >> 2, q = i & 3;
                *(uint4*)(aT + w * LDA + 64 + q * 8) = yF[i];
            }
        }
        if (MODE != 2) {
            const uint4* fH = (const uint4*)(g_FwAh + wv * 128);
            const uint4* fL = (const uint4*)(g_FwAl + wv * 128);
            for (int i = t; i < 512; i += 256) {
                int r = i >> 4, q = i & 15;
                *(uint4*)(fwh + r * 136 + q * 8) = fH[r * 32 + q];
                *(uint4*)(fwl + r * 136 + q * 8) = fL[r * 32 + q];
            }
        }
        __syncthreads();   // S1

        if (MODE >= 1) {
            // ---- main MMA: D[128w x 64o], K=96, single-pass B ----
            float d[2][4][4];
            #pragma unroll
            for (int i1 = 0; i1 < 2; i1++)
                #pragma unroll
                for (int i2 = 0; i2 < 4; i2++)
                    #pragma unroll
                    for (int i3 = 0; i3 < 4; i3++) d[i1][i2][i3] = 0.0f;
            #pragma unroll
            for (int k6 = 0; k6 < 6; k6++) {
                int k0 = k6 * 16;
                u32 af[2][4];
                #pragma unroll
                for (int mt = 0; mt < 2; mt++) {
                    u32 ad = (u32)((32 * mg + mt * 16 + aRow) * LDA + k0 + aKq) * 2;
                    ldmx4(af[mt], sa + AOF + ad);
                }
                #pragma unroll
                for (int np = 0; np < 2; np++) {
                    int q0 = ng * 4 + np * 2;
                    u32 bd = (u32)(((q0 + bSel) * 8 + bN) * LDA + k0 + bKq) * 2;
                    u32 bh4[4];
                    ldmx4(bh4, sa + BHI + bd);
                    #pragma unroll
                    for (int sub = 0; sub < 2; sub++) {
                        int nt = np * 2 + sub;
                        #pragma unroll
                        for (int mt = 0; mt < 2; mt++)
                            mma16816(d[mt][nt], af[mt], bh4[2 * sub], bh4[2 * sub + 1]);
                    }
                }
            }
            __syncthreads();   // S2

            // ---- epilogue ----
            int g = lane >> 2, c2 = lane & 3;
            if (MODE == 1) {
                #pragma unroll
                for (int mt = 0; mt < 2; mt++) {
                    int wl = 32 * mg + mt * 16 + g;
                    #pragma unroll
                    for (int nt = 0; nt < 4; nt++) {
                        int ob = (ng * 4 + nt) * 8 + 2 * c2;
                        float v0 = gelu_exact(d[mt][nt][0] + bias[ob]);
                        float v1 = gelu_exact(d[mt][nt][1] + bias[ob + 1]);
                        float v2 = gelu_exact(d[mt][nt][2] + bias[ob]);
                        float v3 = gelu_exact(d[mt][nt][3] + bias[ob + 1]);
                        *(u32*)(aT + wl * LDA + ob) = pkh2(v0, v1);
                        *(u32*)(aT + (wl + 8) * LDA + ob) = pkh2(v2, v3);
                    }
                }
            } else {
                float* stagf = (float*)(sm + STG);   // [128][68]
                #pragma unroll
                for (int mt = 0; mt < 2; mt++) {
                    int wl = 32 * mg + mt * 16 + g;
                    #pragma unroll
                    for (int nt = 0; nt < 4; nt++) {
                        int ob = (ng * 4 + nt) * 8 + 2 * c2;
                        stagf[wl * 68 + ob]           = gelu_exact(d[mt][nt][0] + bias[ob]);
                        stagf[wl * 68 + ob + 1]       = gelu_exact(d[mt][nt][1] + bias[ob + 1]);
                        stagf[(wl + 8) * 68 + ob]     = gelu_exact(d[mt][nt][2] + bias[ob]);
                        stagf[(wl + 8) * 68 + ob + 1] = gelu_exact(d[mt][nt][3] + bias[ob + 1]);
                    }
                }
            }
            __syncthreads();   // S3
        }

        if (MODE != 2) {
            // ---- act gmem store ----
            uint4* dA = (uint4*)(aout + (((size_t)(b * 256 + h)) * 256 + wv * 128) * 64);
            for (int i = t; i < 1024; i += 256) {
                int w = i >> 3, q = i & 7;
                dA[i] = ((uint4*)aT)[w * 13 + q];
            }
            // ---- fwd-w DFT GEMM: dT[32][64] += Fw[32][128] . act[128][64] ----
            #pragma unroll
            for (int ks = 0; ks < 8; ks++) {
                int k0 = ks * 16;
                u32 fh[4], fl[4], bv[4];
                u32 fad = (u32)((mt2 * 16 + aRow) * 136 + k0 + aKq) * 2;
                ldmx4(fh, sa + FWH + fad);
                ldmx4(fl, sa + FWL + fad);
                u32 bad = (u32)((k0 + khalf * 8 + trow) * LDA + ng2 * 16 + chalf * 8) * 2;
                ldmx4t(bv, sa + AOF + bad);
                #pragma unroll
                for (int nt = 0; nt < 2; nt++) {
                    mma16816(dT[nt], fh, bv[2 * nt], bv[2 * nt + 1]);
                    mma16816(dT[nt], fl, bv[2 * nt], bv[2 * nt + 1]);
                }
            }
            __syncthreads();   // S4
        } else {
            // ---- head ----
            float* stagf = (float*)(sm + STG);
            float* w1s = (float*)(sm + FWH);
            float* b1s = (float*)(sm + FWH + 8192);
            float* w2s = (float*)(sm + FWH + 8320);
            int p = t & 127, hf = t >> 7;
            ull x2[32];
            const float2* xr = (const float2*)(stagf + p * 68);
            #pragma unroll
            for (int j = 0; j < 32; j++) {
                float2 xx = xr[j];
                x2[j] = pk(xx.x, xx.y);
            }
            float acc = hf ? 0.0f : __ldg(o2b);
            for (int o2 = hf * 16; o2 < hf * 16 + 16; o2++) {
                ull s = pk(b1s[o2], 0.0f);
                const ulonglong2* wv2 = (const ulonglong2*)(w1s + o2 * 64);
                #pragma unroll
                for (int j = 0; j < 16; j++) {
                    ulonglong2 p4 = wv2[j];
                    s = f2fma(p4.x, x2[2 * j], s);
                    s = f2fma(p4.y, x2[2 * j + 1], s);
                }
                float lo, hi; upk(s, lo, hi);
                acc = fmaf(w2s[o2], gelu_exact(lo + hi), acc);
            }
            psum[hf * 128 + p] = acc;
            __syncthreads();   // S4
            if (t < 128)
                out[((size_t)(b * 256 + h)) * 256 + wv * 128 + t] = psum[t] + psum[128 + t];
            __syncthreads();   // S5
        }
    }

    if (MODE != 2) {
        // ---- store T (fp16) ----
        int g = lane >> 2, c2 = lane & 3;
        #pragma unroll
        for (int nt = 0; nt < 2; nt++) {
            #pragma unroll
            for (int pr = 0; pr < 2; pr++) {
                int row = mt2 * 16 + g + pr * 8;
                int ky = row >> 1, ri = row & 1;
                int c = ng2 * 16 + nt * 8 + 2 * c2;
                size_t bse = (((size_t)(b * 64 + c)) * 256 + h) * 32 + ky * 2 + ri;
                g_T16[bse] = h16(dT[nt][pr * 2 + 0]);
                g_T16[bse + 8192] = h16(dT[nt][pr * 2 + 1]);
            }
        }
    }
}

// ---------------------------------------------------------------------------
extern "C" void kernel_launch(void* const* d_in, const int* in_sizes, int n_in,
                              void* d_out, int out_size) {
    const float* x       = (const float*)d_in[0];
    const float* in_w    = (const float*)d_in[1];
    const float* in_b    = (const float*)d_in[2];
    const float* spec_wr = (const float*)d_in[3];
    const float* spec_wi = (const float*)d_in[4];
    const float* pw_w    = (const float*)d_in[5];
    const float* pw_b    = (const float*)d_in[6];
    const float* o1w     = (const float*)d_in[7];
    const float* o1b     = (const float*)d_in[8];
    const float* o2w     = (const float*)d_in[9];
    const float* o2b     = (const float*)d_in[10];
    float* out = (float*)d_out;

    cudaFuncSetAttribute(k_gemm<0>, cudaFuncAttributeMaxDynamicSharedMemorySize, SMEM_S);
    cudaFuncSetAttribute(k_gemm<1>, cudaFuncAttributeMaxDynamicSharedMemorySize, SMEM_S);
    cudaFuncSetAttribute(k_gemm<2>, cudaFuncAttributeMaxDynamicSharedMemorySize, SMEM_G);

    u16 *aA, *aB;
    cudaGetSymbolAddress((void**)&aA, g_actA);
    cudaGetSymbolAddress((void**)&aB, g_actB);

    k_prep<<<64, 256>>>(pw_w);
    k_twt<<<dim3(128, 8, NL4), dim3(32, 8)>>>(spec_wr, spec_wi);

    dim3 grid(Hh, Bb);
    k_gemm<0><<<grid, 256, SMEM_S>>>(nullptr, aA, nullptr, 0,
                                     x, in_w, in_b, nullptr,
                                     nullptr, nullptr, nullptr, nullptr);

    const u16* cur = aA;
    u16* nxt = aB;
    for (int l = 0; l < NL4; l++) {
        k_fwd_h<<<Bb * C0, 512>>>();
        k_modegemm<<<256, 512>>>(l);
        k_inv_h<<<Bb * C0, 512>>>();
        if (l < NL4 - 1) {
            k_gemm<1><<<grid, 256, SMEM_S>>>(cur, nxt, pw_b + l * 64, l,
                                             nullptr, nullptr, nullptr, nullptr,
                                             nullptr, nullptr, nullptr, nullptr);
            const u16* tmp = cur; cur = nxt; nxt = (u16*)tmp;
        } else {
            k_gemm<2><<<grid, 256, SMEM_G>>>(cur, nullptr, pw_b + l * 64, l,
                                             nullptr, nullptr, nullptr, out,
                                             o1w, o1b, o2w, o2b);
        }
    }
}

// round 15
// speedup vs baseline: 4.1442x; 1.0326x over previous
#include <cuda_runtime.h>
#include <cuda_fp16.h>
#include <math.h>
#include <stdint.h>

#define Bb 8
#define C0 64
#define Hh 256
#define Ww 256
#define MX 16
#define NL4 4
#define HW 65536
#define LDA 104

typedef unsigned long long ull;
typedef unsigned int u32;
typedef unsigned short u16;

// -------------------- helpers ----------------------------------------------
__device__ __forceinline__ ull pk(float lo, float hi) {
    ull r; asm("mov.b64 %0,{%1,%2};" : "=l"(r) : "f"(lo), "f"(hi)); return r;
}
__device__ __forceinline__ void upk(ull v, float& lo, float& hi) {
    asm("mov.b64 {%0,%1},%2;" : "=f"(lo), "=f"(hi) : "l"(v));
}
__device__ __forceinline__ ull f2fma(ull a, ull b, ull c) {
    ull d; asm("fma.rn.f32x2 %0,%1,%2,%3;" : "=l"(d) : "l"(a), "l"(b), "l"(c)); return d;
}
__device__ __forceinline__ u16 h16(float v) {
    return __half_as_ushort(__float2half_rn(v));
}
__device__ __forceinline__ u32 pkh2(float lo, float hi) {   // lo in bits 0..15
    u32 r; asm("cvt.rn.f16x2.f32 %0,%2,%1;" : "=r"(r) : "f"(lo), "f"(hi)); return r;
}
__device__ __forceinline__ u32 smem_u32(const void* p) {
    u32 a; asm("{ .reg .u64 t; cvta.to.shared.u64 t, %1; cvt.u32.u64 %0, t; }" : "=r"(a) : "l"(p));
    return a;
}
__device__ __forceinline__ void ldmx4(u32* r, u32 addr) {
    asm volatile("ldmatrix.sync.aligned.m8n8.x4.shared.b16 {%0,%1,%2,%3},[%4];"
        : "=r"(r[0]), "=r"(r[1]), "=r"(r[2]), "=r"(r[3]) : "r"(addr));
}
__device__ __forceinline__ void ldmx4t(u32* r, u32 addr) {
    asm volatile("ldmatrix.sync.aligned.m8n8.x4.trans.shared.b16 {%0,%1,%2,%3},[%4];"
        : "=r"(r[0]), "=r"(r[1]), "=r"(r[2]), "=r"(r[3]) : "r"(addr));
}
__device__ __forceinline__ void mma16816(float* d, const u32* a, u32 b0, u32 b1) {
    asm volatile("mma.sync.aligned.m16n8k16.row.col.f32.f16.f16.f32 "
        "{%0,%1,%2,%3},{%4,%5,%6,%7},{%8,%9},{%0,%1,%2,%3};"
        : "+f"(d[0]), "+f"(d[1]), "+f"(d[2]), "+f"(d[3])
        : "r"(a[0]), "r"(a[1]), "r"(a[2]), "r"(a[3]), "r"(b0), "r"(b1));
}
__device__ __forceinline__ float gelu_exact(float z) {
    return 0.5f * z * (1.0f + erff(z * 0.70710678118654752f));
}

// -------------------- globals -----------------------------------------------
__device__ u16 g_actA[(size_t)Bb * HW * C0];   // fp16 act plane [b][h][w][c]
__device__ u16 g_actB[(size_t)Bb * HW * C0];
__device__ u16 g_T16[(size_t)Bb * C0 * Hh * 32]; // [bc][h][2ky+ri] fp16
__device__ ull g_Xf[(size_t)Bb * C0 * 256];
__device__ ull g_G [(size_t)256 * Bb * C0];
__device__ u32 g_Qh32[(size_t)Bb * Hh * 1024];  // [(b*256+h)][o][ky]: fp16 (re|-im<<16)
__device__ u32 g_W216[(size_t)NL4 * 256 * 4096]; // [l][m][i*64+o] fp16 (wr|wi)
__device__ ull g_Fh2a[MX * Hh];                 // [kx][h] = (cos, -sin)
__device__ ull g_EaT[MX * Hh];                  // [kx][h] = (cos,  sin)
__device__ ull g_EbT[MX * Hh];                  // [kx][h] = (-sin, cos)
__device__ u16 g_PwF[NL4 * 4096];               // fp16 single [l][o][c]
__device__ u16 g_SynF[256 * 32];                // fp16 single [w][2ky+ri]
__device__ u16 g_FwF[32 * 256];                 // fp16 single [2ky+ri][w]

// -------------------- merged prep -------------------------------------------
__global__ void k_prep(const float* __restrict__ pw_w) {
    int idx = blockIdx.x * 256 + threadIdx.x;   // 0..16383
    g_PwF[idx] = h16(pw_w[idx]);
    if (idx < 4096) {
        int a = idx >> 8, p = idx & 255, m = (a * p) & 255;
        float s, c; sincospif((float)m * (1.0f / 128.0f), &s, &c);
        g_Fh2a[idx] = pk(c, -s);
        g_EaT[idx] = pk(c, s);
        g_EbT[idx] = pk(-s, c);
    }
    if (idx < 8192) {
        {   // syn single fp16: [w][2ky+ri]
            int w = idx >> 5, j = idx & 31, ky = j >> 1, ri = j & 1;
            float s, c; sincospif((float)((ky * w) & 255) * (1.0f / 128.0f), &s, &c);
            float ck = ((ky == 0) ? 1.0f : 2.0f) * (1.0f / 256.0f);
            g_SynF[idx] = h16(ri ? s * ck : c * ck);
        }
        {   // fwd-DFT A single fp16: [2ky+ri][w]
            int row = idx >> 8, w = idx & 255, ky = row >> 1, ri = row & 1;
            float s, c; sincospif((float)((ky * w) & 255) * (1.0f / 128.0f), &s, &c);
            g_FwF[idx] = h16((ri ? -s : c) * (1.0f / 256.0f));
        }
    }
}
__global__ void k_twt(const float* __restrict__ wr, const float* __restrict__ wi) {
    __shared__ u32 tile[32][33];
    int l = blockIdx.z, tio = blockIdx.x, tm = blockIdx.y;
    int tx = threadIdx.x, ty = threadIdx.y;
    const float* wrl = wr + (size_t)l * 4096 * 256;
    const float* wil = wi + (size_t)l * 4096 * 256;
    #pragma unroll
    for (int r = 0; r < 4; r++) {
        int row = tio * 32 + ty + 8 * r, col = tm * 32 + tx;
        size_t idx = (size_t)row * 256 + col;
        tile[ty + 8 * r][tx] = pkh2(wrl[idx], wil[idx]);
    }
    __syncthreads();
    #pragma unroll
    for (int r = 0; r < 4; r++) {
        int mm = tm * 32 + ty + 8 * r, io = tio * 32 + tx;
        g_W216[(((size_t)l * 256) + mm) * 4096 + io] = tile[tx][ty + 8 * r];
    }
}

// -------------------- spectral trio -----------------------------------------
#define FWD_STEP(px, py, cc, nn) \
    sA0 = fmaf(px.x, cc, sA0); sB0 = fmaf(px.y, nn, sB0); \
    sC0 = fmaf(px.y, cc, sC0); sD0 = fmaf(px.x, nn, sD0); \
    sA1 = fmaf(py.x, cc, sA1); sB1 = fmaf(py.y, nn, sB1); \
    sC1 = fmaf(py.y, cc, sC1); sD1 = fmaf(py.x, nn, sD1);

__global__ __launch_bounds__(512, 3) void k_fwd_h() {
    __shared__ u32 Ts[4096];
    __shared__ ull red[1024];
    int bc = blockIdx.x, t = threadIdx.x;
    {
        const uint4* Tg4 = (const uint4*)(g_T16 + (size_t)bc * 8192);
        uint4* Ts4 = (uint4*)Ts;
        for (int i = t; i < 1024; i += 512) Ts4[i] = Tg4[i];
    }
    __syncthreads();
    int kyg = t & 7, kx = (t >> 3) & 15, hq = t >> 7;
    const ulonglong2* fa2 = (const ulonglong2*)(g_Fh2a + kx * 256 + hq * 64);
    const u32* Tp = Ts + (hq * 64) * 16 + 2 * kyg;
    float sA0 = 0, sB0 = 0, sC0 = 0, sD0 = 0;
    float sA1 = 0, sB1 = 0, sC1 = 0, sD1 = 0;
    #pragma unroll 2
    for (int j = 0; j < 16; j++) {
        ulonglong2 fx = __ldg(fa2 + 2 * j);
        ulonglong2 fy = __ldg(fa2 + 2 * j + 1);
        float c0, n0, c1, n1, c2, n2, c3, n3;
        upk(fx.x, c0, n0); upk(fx.y, c1, n1);
        upk(fy.x, c2, n2); upk(fy.y, c3, n3);
        uint2 v0 = *(const uint2*)(Tp + (4 * j + 0) * 16);
        uint2 v1 = *(const uint2*)(Tp + (4 * j + 1) * 16);
        uint2 v2 = *(const uint2*)(Tp + (4 * j + 2) * 16);
        uint2 v3 = *(const uint2*)(Tp + (4 * j + 3) * 16);
        float2 p0, p1;
        p0 = __half22float2(*(__half2*)&v0.x); p1 = __half22float2(*(__half2*)&v0.y);
        FWD_STEP(p0, p1, c0, n0)
        p0 = __half22float2(*(__half2*)&v1.x); p1 = __half22float2(*(__half2*)&v1.y);
        FWD_STEP(p0, p1, c1, n1)
        p0 = __half22float2(*(__half2*)&v2.x); p1 = __half22float2(*(__half2*)&v2.y);
        FWD_STEP(p0, p1, c2, n2)
        p0 = __half22float2(*(__half2*)&v3.x); p1 = __half22float2(*(__half2*)&v3.y);
        FWD_STEP(p0, p1, c3, n3)
    }
    *(ulonglong2*)(red + hq * 256 + kx * 16 + 2 * kyg) =
        make_ulonglong2(pk(sA0 - sB0, sC0 + sD0), pk(sA1 - sB1, sC1 + sD1));
    __syncthreads();
    if (t < 256) {
        float r0, i0, r1, i1, r2, i2, r3, i3;
        upk(red[t], r0, i0); upk(red[t + 256], r1, i1);
        upk(red[t + 512], r2, i2); upk(red[t + 768], r3, i3);
        g_Xf[(size_t)bc * 256 + t] = pk((r0 + r1) + (r2 + r3), (i0 + i1) + (i2 + i3));
    }
}

__global__ __launch_bounds__(512, 3) void k_modegemm(int l) {
    __shared__ __align__(16) u32 ws[4096];
    __shared__ ull xA[512], xB[512];
    int m = blockIdx.x, t = threadIdx.x;
    {
        const uint4* W4 = (const uint4*)(g_W216 + (((size_t)l * 256) + m) * 4096);
        uint4* ws4 = (uint4*)ws;
        for (int i = t; i < 1024; i += 512) ws4[i] = W4[i];
    }
    {
        int b = t >> 6, i = t & 63;
        float xr, xi; upk(g_Xf[((size_t)b * C0 + i) * 256 + m], xr, xi);
        xA[t] = pk(xr, xr);
        xB[t] = pk(-xi, xi);
    }
    __syncthreads();
    int b = t >> 6, o = t & 63;
    ull acc0 = 0ull, acc1 = 0ull;
    const ull* xa = xA + b * 64;
    const ull* xb = xB + b * 64;
    #pragma unroll 4
    for (int i = 0; i < C0; i += 2) {
        u32 w2 = ws[i * 64 + o];
        float2 wf = __half22float2(*(__half2*)&w2);
        acc0 = f2fma(xa[i], pk(wf.x, wf.y), acc0);
        acc0 = f2fma(xb[i], pk(wf.y, wf.x), acc0);
        u32 w3 = ws[(i + 1) * 64 + o];
        float2 wg = __half22float2(*(__half2*)&w3);
        acc1 = f2fma(xa[i + 1], pk(wg.x, wg.y), acc1);
        acc1 = f2fma(xb[i + 1], pk(wg.y, wg.x), acc1);
    }
    float p0, q0, p1, q1;
    upk(acc0, p0, q0); upk(acc1, p1, q1);
    g_G[(size_t)m * 512 + t] = pk(p0 + p1, q0 + q1);
}

// inverse kx: single fp16 Q plane output.
__global__ __launch_bounds__(512, 2) void k_inv_h() {
    __shared__ ull Gs[256];
    int bo = blockIdx.x, t = threadIdx.x;
    int b = bo >> 6, o = bo & 63;
    if (t < 256) Gs[t] = g_G[(size_t)t * 512 + bo];
    __syncthreads();
    int kyg = t & 7, hg = t >> 3;
    ull a00 = 0, a01 = 0, a02 = 0, a03 = 0;
    ull a10 = 0, a11 = 0, a12 = 0, a13 = 0;
    #pragma unroll
    for (int kx = 0; kx < 16; kx++) {
        ulonglong2 g2 = *(const ulonglong2*)(Gs + kx * 16 + 2 * kyg);
        float gr0, gi0, gr1, gi1;
        upk(g2.x, gr0, gi0); upk(g2.y, gr1, gi1);
        ull gr20 = pk(gr0, gr0), gi20 = pk(gi0, gi0);
        ull gr21 = pk(gr1, gr1), gi21 = pk(gi1, gi1);
        const ulonglong2* ea = (const ulonglong2*)(g_EaT + kx * 256 + hg * 4);
        const ulonglong2* eb = (const ulonglong2*)(g_EbT + kx * 256 + hg * 4);
        ulonglong2 ea0 = __ldg(ea), ea1 = __ldg(ea + 1);
        ulonglong2 eb0 = __ldg(eb), eb1 = __ldg(eb + 1);
        a00 = f2fma(gr20, ea0.x, a00); a00 = f2fma(gi20, eb0.x, a00);
        a01 = f2fma(gr20, ea0.y, a01); a01 = f2fma(gi20, eb0.y, a01);
        a02 = f2fma(gr20, ea1.x, a02); a02 = f2fma(gi20, eb1.x, a02);
        a03 = f2fma(gr20, ea1.y, a03); a03 = f2fma(gi20, eb1.y, a03);
        a10 = f2fma(gr21, ea0.x, a10); a10 = f2fma(gi21, eb0.x, a10);
        a11 = f2fma(gr21, ea0.y, a11); a11 = f2fma(gi21, eb0.y, a11);
        a12 = f2fma(gr21, ea1.x, a12); a12 = f2fma(gi21, eb1.x, a12);
        a13 = f2fma(gr21, ea1.y, a13); a13 = f2fma(gi21, eb1.y, a13);
    }
    ull acc0[4] = {a00, a01, a02, a03};
    ull acc1[4] = {a10, a11, a12, a13};
    #pragma unroll
    for (int hp = 0; hp < 4; hp++) {
        int h = hg * 4 + hp;
        float re0, im0, re1, im1;
        upk(acc0[hp], re0, im0);
        upk(acc1[hp], re1, im1);
        u32 base = (((u32)b * 256 + h) * 64 + o) * 16 + 2 * kyg;
        *(uint2*)(g_Qh32 + base) = make_uint2(
            (u32)h16(re0) | ((u32)h16(-im0) << 16),
            (u32)h16(re1) | ((u32)h16(-im1) << 16));
    }
}

// -------------------- fused HMMA layer kernel -------------------------------
// smem (bytes):
#define AOF 0          // 26624 = 128*104*2  (fp16 act+syn tile)
#define BHI 26624      // 13312 = 64*104*2 (single fp16 B)
#define FWH 39936      // 8704 = 32*136*2 (single fp16 Fw; MODE2: head weights)
#define MSC 48640      // 3072
#define STG 51712      // 34816 (MODE 2 f32 stag [128][68])
#define SMEM_S 51712   // MODE 0/1
#define SMEM_G 86528   // MODE 2

// MODE: 0 = lift, 1 = mid layer, 2 = last layer (+head)
template <int MODE>
__global__ __launch_bounds__(256, (MODE == 2 ? 2 : 3))
void k_gemm(const u16* __restrict__ ain, u16* __restrict__ aout,
            const float* __restrict__ pw_b, int l,
            const float* __restrict__ x, const float* __restrict__ in_w,
            const float* __restrict__ in_b,
            float* __restrict__ out,
            const float* __restrict__ o1w, const float* __restrict__ o1b,
            const float* __restrict__ o2w, const float* __restrict__ o2b) {
    extern __shared__ __align__(16) char sm[];
    int h = blockIdx.x, b = blockIdx.y, t = threadIdx.x;
    int warp = t >> 5, lane = t & 31;
    u16* aT  = (u16*)(sm + AOF);
    u16* bHs = (u16*)(sm + BHI);
    u16* fwh = (u16*)(sm + FWH);
    float* bias = (float*)(sm + MSC);
    float* iwS  = (float*)(sm + MSC + 256);
    float* ibS  = (float*)(sm + MSC + 768);
    float* x0s  = (float*)(sm + MSC + 1024);
    float* x1s  = (float*)(sm + MSC + 1536);
    float* psum = (float*)(sm + MSC + 2048);
    u32 sa = smem_u32(sm);

    // ---- pre-loop staging ----
    if (MODE == 0) {
        if (t < 128) iwS[t] = in_w[t];
        if (t < 64) ibS[t] = in_b[t];
    } else {
        {   // pointwise weights (cols 0..63), single fp16
            const uint4* pF = (const uint4*)(g_PwF + l * 4096);
            for (int i = t; i < 512; i += 256) {
                int o = i >> 3, q = i & 7;
                *(uint4*)(bHs + o * LDA + q * 8) = pF[i];
            }
        }
        {   // Q (cols 64..95), single fp16
            const uint4* qH = (const uint4*)(g_Qh32 + ((size_t)(b * 256 + h)) * 1024);
            for (int i = t; i < 256; i += 256) {
                int o = i >> 2, q = i & 3;
                *(uint4*)(bHs + o * LDA + 64 + q * 8) = qH[i];
            }
        }
        if (t < 64) bias[t] = pw_b[t];
        if (MODE == 2) {
            float* w1s = (float*)(sm + FWH);
            float* b1s = (float*)(sm + FWH + 8192);
            float* w2s = (float*)(sm + FWH + 8320);
            for (int i = t; i < 2048; i += 256) w1s[i] = o1w[i];
            if (t < 32) { b1s[t] = o1b[t]; w2s[t] = o2w[t]; }
        }
    }

    int mg = warp & 3, ng = warp >> 2;
    int aRow = (lane & 7) + ((lane >> 3) & 1) * 8;
    int aKq = (lane >> 4) * 8;
    int bSel = (lane >> 4) & 1, bN = lane & 7, bKq = ((lane >> 3) & 1) * 8;
    int mt2 = warp & 1, ng2 = warp >> 1;
    int trow = lane & 7, khalf = (lane >> 3) & 1, chalf = (lane >> 4) & 1;

    float dT[2][4];
    if (MODE != 2) {
        #pragma unroll
        for (int i1 = 0; i1 < 2; i1++)
            #pragma unroll
            for (int i2 = 0; i2 < 4; i2++) dT[i1][i2] = 0.0f;
    }

    for (int wv = 0; wv < 2; wv++) {
        // ---- A staging ----
        if (MODE == 0) {
            if (t < 128) x0s[t] = x[(((size_t)(b * 2)) * 256 + h) * 256 + wv * 128 + t];
            else x1s[t - 128] = x[(((size_t)(b * 2 + 1)) * 256 + h) * 256 + wv * 128 + (t - 128)];
            __syncthreads();
            for (int i = t; i < 8192; i += 256) {
                int w = i >> 6, c = i & 63;
                float v = fmaf(iwS[2 * c], x0s[w], fmaf(iwS[2 * c + 1], x1s[w], ibS[c]));
                aT[w * LDA + c] = h16(v);
            }
        } else {
            const uint4* sA = (const uint4*)(ain + (((size_t)(b * 256 + h)) * 256 + wv * 128) * 64);
            for (int i = t; i < 1024; i += 256) {
                int w = i >> 3, q = i & 7;
                ((uint4*)aT)[w * 13 + q] = sA[i];
            }
            const uint4* yF = (const uint4*)(g_SynF + wv * 128 * 32);
            for (int i = t; i < 512; i += 256) {
                int w = i >> 2, q = i & 3;
                *(uint4*)(aT + w * LDA + 64 + q * 8) = yF[i];
            }
        }
        if (MODE != 2) {
            const uint4* fF = (const uint4*)(g_FwF + wv * 128);
            for (int i = t; i < 512; i += 256) {
                int r = i >> 4, q = i & 15;
                *(uint4*)(fwh + r * 136 + q * 8) = fF[r * 32 + q];
            }
        }
        __syncthreads();   // S1

        if (MODE >= 1) {
            // ---- main MMA: D[128w x 64o], K=96, single-pass ----
            float d[2][4][4];
            #pragma unroll
            for (int i1 = 0; i1 < 2; i1++)
                #pragma unroll
                for (int i2 = 0; i2 < 4; i2++)
                    #pragma unroll
                    for (int i3 = 0; i3 < 4; i3++) d[i1][i2][i3] = 0.0f;
            #pragma unroll
            for (int k6 = 0; k6 < 6; k6++) {
                int k0 = k6 * 16;
                u32 af[2][4];
                #pragma unroll
                for (int mt = 0; mt < 2; mt++) {
                    u32 ad = (u32)((32 * mg + mt * 16 + aRow) * LDA + k0 + aKq) * 2;
                    ldmx4(af[mt], sa + AOF + ad);
                }
                #pragma unroll
                for (int np = 0; np < 2; np++) {
                    int q0 = ng * 4 + np * 2;
                    u32 bd = (u32)(((q0 + bSel) * 8 + bN) * LDA + k0 + bKq) * 2;
                    u32 bh4[4];
                    ldmx4(bh4, sa + BHI + bd);
                    #pragma unroll
                    for (int sub = 0; sub < 2; sub++) {
                        int nt = np * 2 + sub;
                        #pragma unroll
                        for (int mt = 0; mt < 2; mt++)
                            mma16816(d[mt][nt], af[mt], bh4[2 * sub], bh4[2 * sub + 1]);
                    }
                }
            }
            __syncthreads();   // S2

            // ---- epilogue ----
            int g = lane >> 2, c2 = lane & 3;
            if (MODE == 1) {
                #pragma unroll
                for (int mt = 0; mt < 2; mt++) {
                    int wl = 32 * mg + mt * 16 + g;
                    #pragma unroll
                    for (int nt = 0; nt < 4; nt++) {
                        int ob = (ng * 4 + nt) * 8 + 2 * c2;
                        float v0 = gelu_exact(d[mt][nt][0] + bias[ob]);
                        float v1 = gelu_exact(d[mt][nt][1] + bias[ob + 1]);
                        float v2 = gelu_exact(d[mt][nt][2] + bias[ob]);
                        float v3 = gelu_exact(d[mt][nt][3] + bias[ob + 1]);
                        *(u32*)(aT + wl * LDA + ob) = pkh2(v0, v1);
                        *(u32*)(aT + (wl + 8) * LDA + ob) = pkh2(v2, v3);
                    }
                }
            } else {
                float* stagf = (float*)(sm + STG);   // [128][68]
                #pragma unroll
                for (int mt = 0; mt < 2; mt++) {
                    int wl = 32 * mg + mt * 16 + g;
                    #pragma unroll
                    for (int nt = 0; nt < 4; nt++) {
                        int ob = (ng * 4 + nt) * 8 + 2 * c2;
                        stagf[wl * 68 + ob]           = gelu_exact(d[mt][nt][0] + bias[ob]);
                        stagf[wl * 68 + ob + 1]       = gelu_exact(d[mt][nt][1] + bias[ob + 1]);
                        stagf[(wl + 8) * 68 + ob]     = gelu_exact(d[mt][nt][2] + bias[ob]);
                        stagf[(wl + 8) * 68 + ob + 1] = gelu_exact(d[mt][nt][3] + bias[ob + 1]);
                    }
                }
            }
            __syncthreads();   // S3
        }

        if (MODE != 2) {
            // ---- act gmem store ----
            uint4* dA = (uint4*)(aout + (((size_t)(b * 256 + h)) * 256 + wv * 128) * 64);
            for (int i = t; i < 1024; i += 256) {
                int w = i >> 3, q = i & 7;
                dA[i] = ((uint4*)aT)[w * 13 + q];
            }
            // ---- fwd-w DFT GEMM: dT[32][64] += Fw[32][128] . act[128][64] ----
            #pragma unroll
            for (int ks = 0; ks < 8; ks++) {
                int k0 = ks * 16;
                u32 fh[4], bv[4];
                u32 fad = (u32)((mt2 * 16 + aRow) * 136 + k0 + aKq) * 2;
                ldmx4(fh, sa + FWH + fad);
                u32 bad = (u32)((k0 + khalf * 8 + trow) * LDA + ng2 * 16 + chalf * 8) * 2;
                ldmx4t(bv, sa + AOF + bad);
                #pragma unroll
                for (int nt = 0; nt < 2; nt++)
                    mma16816(dT[nt], fh, bv[2 * nt], bv[2 * nt + 1]);
            }
            __syncthreads();   // S4
        } else {
            // ---- head ----
            float* stagf = (float*)(sm + STG);
            float* w1s = (float*)(sm + FWH);
            float* b1s = (float*)(sm + FWH + 8192);
            float* w2s = (float*)(sm + FWH + 8320);
            int p = t & 127, hf = t >> 7;
            ull x2[32];
            const float2* xr = (const float2*)(stagf + p * 68);
            #pragma unroll
            for (int j = 0; j < 32; j++) {
                float2 xx = xr[j];
                x2[j] = pk(xx.x, xx.y);
            }
            float acc = hf ? 0.0f : __ldg(o2b);
            for (int o2 = hf * 16; o2 < hf * 16 + 16; o2++) {
                ull s = pk(b1s[o2], 0.0f);
                const ulonglong2* wv2 = (const ulonglong2*)(w1s + o2 * 64);
                #pragma unroll
                for (int j = 0; j < 16; j++) {
                    ulonglong2 p4 = wv2[j];
                    s = f2fma(p4.x, x2[2 * j], s);
                    s = f2fma(p4.y, x2[2 * j + 1], s);
                }
                float lo, hi; upk(s, lo, hi);
                acc = fmaf(w2s[o2], gelu_exact(lo + hi), acc);
            }
            psum[hf * 128 + p] = acc;
            __syncthreads();   // S4
            if (t < 128)
                out[((size_t)(b * 256 + h)) * 256 + wv * 128 + t] = psum[t] + psum[128 + t];
            __syncthreads();   // S5
        }
    }

    if (MODE != 2) {
        // ---- store T (fp16) ----
        int g = lane >> 2, c2 = lane & 3;
        #pragma unroll
        for (int nt = 0; nt < 2; nt++) {
            #pragma unroll
            for (int pr = 0; pr < 2; pr++) {
                int row = mt2 * 16 + g + pr * 8;
                int ky = row >> 1, ri = row & 1;
                int c = ng2 * 16 + nt * 8 + 2 * c2;
                size_t bse = (((size_t)(b * 64 + c)) * 256 + h) * 32 + ky * 2 + ri;
                g_T16[bse] = h16(dT[nt][pr * 2 + 0]);
                g_T16[bse + 8192] = h16(dT[nt][pr * 2 + 1]);
            }
        }
    }
}

// ---------------------------------------------------------------------------
extern "C" void kernel_launch(void* const* d_in, const int* in_sizes, int n_in,
                              void* d_out, int out_size) {
    const float* x       = (const float*)d_in[0];
    const float* in_w    = (const float*)d_in[1];
    const float* in_b    = (const float*)d_in[2];
    const float* spec_wr = (const float*)d_in[3];
    const float* spec_wi = (const float*)d_in[4];
    const float* pw_w    = (const float*)d_in[5];
    const float* pw_b    = (const float*)d_in[6];
    const float* o1w     = (const float*)d_in[7];
    const float* o1b     = (const float*)d_in[8];
    const float* o2w     = (const float*)d_in[9];
    const float* o2b     = (const float*)d_in[10];
    float* out = (float*)d_out;

    cudaFuncSetAttribute(k_gemm<0>, cudaFuncAttributeMaxDynamicSharedMemorySize, SMEM_S);
    cudaFuncSetAttribute(k_gemm<1>, cudaFuncAttributeMaxDynamicSharedMemorySize, SMEM_S);
    cudaFuncSetAttribute(k_gemm<2>, cudaFuncAttributeMaxDynamicSharedMemorySize, SMEM_G);

    u16 *aA, *aB;
    cudaGetSymbolAddress((void**)&aA, g_actA);
    cudaGetSymbolAddress((void**)&aB, g_actB);

    k_prep<<<64, 256>>>(pw_w);
    k_twt<<<dim3(128, 8, NL4), dim3(32, 8)>>>(spec_wr, spec_wi);

    dim3 grid(Hh, Bb);
    k_gemm<0><<<grid, 256, SMEM_S>>>(nullptr, aA, nullptr, 0,
                                     x, in_w, in_b, nullptr,
                                     nullptr, nullptr, nullptr, nullptr);

    const u16* cur = aA;
    u16* nxt = aB;
    for (int l = 0; l < NL4; l++) {
        k_fwd_h<<<Bb * C0, 512>>>();
        k_modegemm<<<256, 512>>>(l);
        k_inv_h<<<Bb * C0, 512>>>();
        if (l < NL4 - 1) {
            k_gemm<1><<<grid, 256, SMEM_S>>>(cur, nxt, pw_b + l * 64, l,
                                             nullptr, nullptr, nullptr, nullptr,
                                             nullptr, nullptr, nullptr, nullptr);
            const u16* tmp = cur; cur = nxt; nxt = (u16*)tmp;
        } else {
            k_gemm<2><<<grid, 256, SMEM_G>>>(cur, nullptr, pw_b + l * 64, l,
                                             nullptr, nullptr, nullptr, out,
                                             o1w, o1b, o2w, o2b);
        }
    }
}

// round 16
// speedup vs baseline: 4.1922x; 1.0116x over previous
#include <cuda_runtime.h>
#include <cuda_fp16.h>
#include <math.h>
#include <stdint.h>

#define Bb 8
#define C0 64
#define Hh 256
#define Ww 256
#define MX 16
#define NL4 4
#define HW 65536
#define LDA 104

typedef unsigned long long ull;
typedef unsigned int u32;
typedef unsigned short u16;

// -------------------- helpers ----------------------------------------------
__device__ __forceinline__ ull pk(float lo, float hi) {
    ull r; asm("mov.b64 %0,{%1,%2};" : "=l"(r) : "f"(lo), "f"(hi)); return r;
}
__device__ __forceinline__ void upk(ull v, float& lo, float& hi) {
    asm("mov.b64 {%0,%1},%2;" : "=f"(lo), "=f"(hi) : "l"(v));
}
__device__ __forceinline__ ull f2fma(ull a, ull b, ull c) {
    ull d; asm("fma.rn.f32x2 %0,%1,%2,%3;" : "=l"(d) : "l"(a), "l"(b), "l"(c)); return d;
}
__device__ __forceinline__ u16 h16(float v) {
    return __half_as_ushort(__float2half_rn(v));
}
__device__ __forceinline__ u32 pkh2(float lo, float hi) {   // lo in bits 0..15
    u32 r; asm("cvt.rn.f16x2.f32 %0,%2,%1;" : "=r"(r) : "f"(lo), "f"(hi)); return r;
}
__device__ __forceinline__ u32 smem_u32(const void* p) {
    u32 a; asm("{ .reg .u64 t; cvta.to.shared.u64 t, %1; cvt.u32.u64 %0, t; }" : "=r"(a) : "l"(p));
    return a;
}
__device__ __forceinline__ void ldmx4(u32* r, u32 addr) {
    asm volatile("ldmatrix.sync.aligned.m8n8.x4.shared.b16 {%0,%1,%2,%3},[%4];"
        : "=r"(r[0]), "=r"(r[1]), "=r"(r[2]), "=r"(r[3]) : "r"(addr));
}
__device__ __forceinline__ void ldmx4t(u32* r, u32 addr) {
    asm volatile("ldmatrix.sync.aligned.m8n8.x4.trans.shared.b16 {%0,%1,%2,%3},[%4];"
        : "=r"(r[0]), "=r"(r[1]), "=r"(r[2]), "=r"(r[3]) : "r"(addr));
}
__device__ __forceinline__ void mma16816(float* d, const u32* a, u32 b0, u32 b1) {
    asm volatile("mma.sync.aligned.m16n8k16.row.col.f32.f16.f16.f32 "
        "{%0,%1,%2,%3},{%4,%5,%6,%7},{%8,%9},{%0,%1,%2,%3};"
        : "+f"(d[0]), "+f"(d[1]), "+f"(d[2]), "+f"(d[3])
        : "r"(a[0]), "r"(a[1]), "r"(a[2]), "r"(a[3]), "r"(b0), "r"(b1));
}
// exact-erf GELU via A&S 7.1.26 (|eps| <= 1.5e-7, invisible at fp16 act precision)
__device__ __forceinline__ float gelu_exact(float x) {
    float u = 0.70710678118654752f * x;
    float au = fabsf(u);
    float t = __fdividef(1.0f, fmaf(0.3275911f, au, 1.0f));
    float p = t * fmaf(t, fmaf(t, fmaf(t, fmaf(t, 1.061405429f, -1.453152027f),
                 1.421413741f), -0.284496736f), 0.254829592f);
    float e = __expf(-u * u);
    float er = fmaf(-p, e, 1.0f);      // erf(|u|)
    er = copysignf(er, u);
    return 0.5f * x * (1.0f + er);
}

// -------------------- globals -----------------------------------------------
__device__ u16 g_actA[(size_t)Bb * HW * C0];   // fp16 act plane [b][h][w][c]
__device__ u16 g_actB[(size_t)Bb * HW * C0];
__device__ u16 g_T16[(size_t)Bb * C0 * Hh * 32]; // [bc][h][2ky+ri] fp16
__device__ ull g_Xf[(size_t)Bb * C0 * 256];
__device__ ull g_G [(size_t)256 * Bb * C0];
__device__ u32 g_Qh32[(size_t)Bb * Hh * 1024];  // [(b*256+h)][o][ky]: fp16 (re|-im<<16)
__device__ u32 g_W216[(size_t)NL4 * 256 * 4096]; // [l][m][i*64+o] fp16 (wr|wi)
__device__ ull g_Fh2a[MX * Hh];                 // [kx][h] = (cos, -sin)
__device__ ull g_EaT[MX * Hh];                  // [kx][h] = (cos,  sin)
__device__ ull g_EbT[MX * Hh];                  // [kx][h] = (-sin, cos)
__device__ u16 g_PwF[NL4 * 4096];               // fp16 single [l][o][c]
__device__ u16 g_SynF[256 * 32];                // fp16 single [w][2ky+ri]
__device__ u16 g_FwF[32 * 256];                 // fp16 single [2ky+ri][w]

// -------------------- merged prep -------------------------------------------
__global__ void k_prep(const float* __restrict__ pw_w) {
    int idx = blockIdx.x * 256 + threadIdx.x;   // 0..16383
    g_PwF[idx] = h16(pw_w[idx]);
    if (idx < 4096) {
        int a = idx >> 8, p = idx & 255, m = (a * p) & 255;
        float s, c; sincospif((float)m * (1.0f / 128.0f), &s, &c);
        g_Fh2a[idx] = pk(c, -s);
        g_EaT[idx] = pk(c, s);
        g_EbT[idx] = pk(-s, c);
    }
    if (idx < 8192) {
        {   // syn single fp16: [w][2ky+ri]
            int w = idx >> 5, j = idx & 31, ky = j >> 1, ri = j & 1;
            float s, c; sincospif((float)((ky * w) & 255) * (1.0f / 128.0f), &s, &c);
            float ck = ((ky == 0) ? 1.0f : 2.0f) * (1.0f / 256.0f);
            g_SynF[idx] = h16(ri ? s * ck : c * ck);
        }
        {   // fwd-DFT A single fp16: [2ky+ri][w]
            int row = idx >> 8, w = idx & 255, ky = row >> 1, ri = row & 1;
            float s, c; sincospif((float)((ky * w) & 255) * (1.0f / 128.0f), &s, &c);
            g_FwF[idx] = h16((ri ? -s : c) * (1.0f / 256.0f));
        }
    }
}
__global__ void k_twt(const float* __restrict__ wr, const float* __restrict__ wi) {
    __shared__ u32 tile[32][33];
    int l = blockIdx.z, tio = blockIdx.x, tm = blockIdx.y;
    int tx = threadIdx.x, ty = threadIdx.y;
    const float* wrl = wr + (size_t)l * 4096 * 256;
    const float* wil = wi + (size_t)l * 4096 * 256;
    #pragma unroll
    for (int r = 0; r < 4; r++) {
        int row = tio * 32 + ty + 8 * r, col = tm * 32 + tx;
        size_t idx = (size_t)row * 256 + col;
        tile[ty + 8 * r][tx] = pkh2(wrl[idx], wil[idx]);
    }
    __syncthreads();
    #pragma unroll
    for (int r = 0; r < 4; r++) {
        int mm = tm * 32 + ty + 8 * r, io = tio * 32 + tx;
        g_W216[(((size_t)l * 256) + mm) * 4096 + io] = tile[tx][ty + 8 * r];
    }
}

// -------------------- spectral trio -----------------------------------------
#define FWD_STEP(px, py, cc, nn) \
    sA0 = fmaf(px.x, cc, sA0); sB0 = fmaf(px.y, nn, sB0); \
    sC0 = fmaf(px.y, cc, sC0); sD0 = fmaf(px.x, nn, sD0); \
    sA1 = fmaf(py.x, cc, sA1); sB1 = fmaf(py.y, nn, sB1); \
    sC1 = fmaf(py.y, cc, sC1); sD1 = fmaf(py.x, nn, sD1);

__global__ __launch_bounds__(512, 3) void k_fwd_h() {
    __shared__ u32 Ts[4096];
    __shared__ ull red[1024];
    int bc = blockIdx.x, t = threadIdx.x;
    {
        const uint4* Tg4 = (const uint4*)(g_T16 + (size_t)bc * 8192);
        uint4* Ts4 = (uint4*)Ts;
        for (int i = t; i < 1024; i += 512) Ts4[i] = Tg4[i];
    }
    __syncthreads();
    int kyg = t & 7, kx = (t >> 3) & 15, hq = t >> 7;
    const ulonglong2* fa2 = (const ulonglong2*)(g_Fh2a + kx * 256 + hq * 64);
    const u32* Tp = Ts + (hq * 64) * 16 + 2 * kyg;
    float sA0 = 0, sB0 = 0, sC0 = 0, sD0 = 0;
    float sA1 = 0, sB1 = 0, sC1 = 0, sD1 = 0;
    #pragma unroll 2
    for (int j = 0; j < 16; j++) {
        ulonglong2 fx = __ldg(fa2 + 2 * j);
        ulonglong2 fy = __ldg(fa2 + 2 * j + 1);
        float c0, n0, c1, n1, c2, n2, c3, n3;
        upk(fx.x, c0, n0); upk(fx.y, c1, n1);
        upk(fy.x, c2, n2); upk(fy.y, c3, n3);
        uint2 v0 = *(const uint2*)(Tp + (4 * j + 0) * 16);
        uint2 v1 = *(const uint2*)(Tp + (4 * j + 1) * 16);
        uint2 v2 = *(const uint2*)(Tp + (4 * j + 2) * 16);
        uint2 v3 = *(const uint2*)(Tp + (4 * j + 3) * 16);
        float2 p0, p1;
        p0 = __half22float2(*(__half2*)&v0.x); p1 = __half22float2(*(__half2*)&v0.y);
        FWD_STEP(p0, p1, c0, n0)
        p0 = __half22float2(*(__half2*)&v1.x); p1 = __half22float2(*(__half2*)&v1.y);
        FWD_STEP(p0, p1, c1, n1)
        p0 = __half22float2(*(__half2*)&v2.x); p1 = __half22float2(*(__half2*)&v2.y);
        FWD_STEP(p0, p1, c2, n2)
        p0 = __half22float2(*(__half2*)&v3.x); p1 = __half22float2(*(__half2*)&v3.y);
        FWD_STEP(p0, p1, c3, n3)
    }
    *(ulonglong2*)(red + hq * 256 + kx * 16 + 2 * kyg) =
        make_ulonglong2(pk(sA0 - sB0, sC0 + sD0), pk(sA1 - sB1, sC1 + sD1));
    __syncthreads();
    if (t < 256) {
        float r0, i0, r1, i1, r2, i2, r3, i3;
        upk(red[t], r0, i0); upk(red[t + 256], r1, i1);
        upk(red[t + 512], r2, i2); upk(red[t + 768], r3, i3);
        g_Xf[(size_t)bc * 256 + t] = pk((r0 + r1) + (r2 + r3), (i0 + i1) + (i2 + i3));
    }
}

__global__ __launch_bounds__(512, 3) void k_modegemm(int l) {
    __shared__ __align__(16) u32 ws[4096];
    __shared__ ull xA[512], xB[512];
    int m = blockIdx.x, t = threadIdx.x;
    {
        const uint4* W4 = (const uint4*)(g_W216 + (((size_t)l * 256) + m) * 4096);
        uint4* ws4 = (uint4*)ws;
        for (int i = t; i < 1024; i += 512) ws4[i] = W4[i];
    }
    {
        int b = t >> 6, i = t & 63;
        float xr, xi; upk(g_Xf[((size_t)b * C0 + i) * 256 + m], xr, xi);
        xA[t] = pk(xr, xr);
        xB[t] = pk(-xi, xi);
    }
    __syncthreads();
    int b = t >> 6, o = t & 63;
    ull acc0 = 0ull, acc1 = 0ull;
    const ull* xa = xA + b * 64;
    const ull* xb = xB + b * 64;
    #pragma unroll 4
    for (int i = 0; i < C0; i += 2) {
        u32 w2 = ws[i * 64 + o];
        float2 wf = __half22float2(*(__half2*)&w2);
        acc0 = f2fma(xa[i], pk(wf.x, wf.y), acc0);
        acc0 = f2fma(xb[i], pk(wf.y, wf.x), acc0);
        u32 w3 = ws[(i + 1) * 64 + o];
        float2 wg = __half22float2(*(__half2*)&w3);
        acc1 = f2fma(xa[i + 1], pk(wg.x, wg.y), acc1);
        acc1 = f2fma(xb[i + 1], pk(wg.y, wg.x), acc1);
    }
    float p0, q0, p1, q1;
    upk(acc0, p0, q0); upk(acc1, p1, q1);
    g_G[(size_t)m * 512 + t] = pk(p0 + p1, q0 + q1);
}

// inverse kx: single fp16 Q plane output.
__global__ __launch_bounds__(512, 2) void k_inv_h() {
    __shared__ ull Gs[256];
    int bo = blockIdx.x, t = threadIdx.x;
    int b = bo >> 6, o = bo & 63;
    if (t < 256) Gs[t] = g_G[(size_t)t * 512 + bo];
    __syncthreads();
    int kyg = t & 7, hg = t >> 3;
    ull a00 = 0, a01 = 0, a02 = 0, a03 = 0;
    ull a10 = 0, a11 = 0, a12 = 0, a13 = 0;
    #pragma unroll
    for (int kx = 0; kx < 16; kx++) {
        ulonglong2 g2 = *(const ulonglong2*)(Gs + kx * 16 + 2 * kyg);
        float gr0, gi0, gr1, gi1;
        upk(g2.x, gr0, gi0); upk(g2.y, gr1, gi1);
        ull gr20 = pk(gr0, gr0), gi20 = pk(gi0, gi0);
        ull gr21 = pk(gr1, gr1), gi21 = pk(gi1, gi1);
        const ulonglong2* ea = (const ulonglong2*)(g_EaT + kx * 256 + hg * 4);
        const ulonglong2* eb = (const ulonglong2*)(g_EbT + kx * 256 + hg * 4);
        ulonglong2 ea0 = __ldg(ea), ea1 = __ldg(ea + 1);
        ulonglong2 eb0 = __ldg(eb), eb1 = __ldg(eb + 1);
        a00 = f2fma(gr20, ea0.x, a00); a00 = f2fma(gi20, eb0.x, a00);
        a01 = f2fma(gr20, ea0.y, a01); a01 = f2fma(gi20, eb0.y, a01);
        a02 = f2fma(gr20, ea1.x, a02); a02 = f2fma(gi20, eb1.x, a02);
        a03 = f2fma(gr20, ea1.y, a03); a03 = f2fma(gi20, eb1.y, a03);
        a10 = f2fma(gr21, ea0.x, a10); a10 = f2fma(gi21, eb0.x, a10);
        a11 = f2fma(gr21, ea0.y, a11); a11 = f2fma(gi21, eb0.y, a11);
        a12 = f2fma(gr21, ea1.x, a12); a12 = f2fma(gi21, eb1.x, a12);
        a13 = f2fma(gr21, ea1.y, a13); a13 = f2fma(gi21, eb1.y, a13);
    }
    ull acc0[4] = {a00, a01, a02, a03};
    ull acc1[4] = {a10, a11, a12, a13};
    #pragma unroll
    for (int hp = 0; hp < 4; hp++) {
        int h = hg * 4 + hp;
        float re0, im0, re1, im1;
        upk(acc0[hp], re0, im0);
        upk(acc1[hp], re1, im1);
        u32 base = (((u32)b * 256 + h) * 64 + o) * 16 + 2 * kyg;
        *(uint2*)(g_Qh32 + base) = make_uint2(
            (u32)h16(re0) | ((u32)h16(-im0) << 16),
            (u32)h16(re1) | ((u32)h16(-im1) << 16));
    }
}

// -------------------- fused HMMA layer kernel -------------------------------
// smem (bytes):
#define AOF 0          // 26624 = 128*104*2  (fp16 act+syn tile)
#define BHI 26624      // 13312 = 64*104*2 (single fp16 B)
#define FWH 39936      // 8704 = 32*136*2 (single fp16 Fw; MODE2: head weights)
#define MSC 48640      // 3072
#define STG 51712      // 34816 (MODE 2 f32 stag [128][68])
#define SMEM_S 51712   // MODE 0/1
#define SMEM_G 86528   // MODE 2

// MODE: 0 = lift, 1 = mid layer, 2 = last layer (+head)
template <int MODE>
__global__ __launch_bounds__(256, (MODE == 2 ? 2 : 3))
void k_gemm(const u16* __restrict__ ain, u16* __restrict__ aout,
            const float* __restrict__ pw_b, int l,
            const float* __restrict__ x, const float* __restrict__ in_w,
            const float* __restrict__ in_b,
            float* __restrict__ out,
            const float* __restrict__ o1w, const float* __restrict__ o1b,
            const float* __restrict__ o2w, const float* __restrict__ o2b) {
    extern __shared__ __align__(16) char sm[];
    int h = blockIdx.x, b = blockIdx.y, t = threadIdx.x;
    int warp = t >> 5, lane = t & 31;
    u16* aT  = (u16*)(sm + AOF);
    u16* bHs = (u16*)(sm + BHI);
    u16* fwh = (u16*)(sm + FWH);
    float* bias = (float*)(sm + MSC);
    float* iwS  = (float*)(sm + MSC + 256);
    float* ibS  = (float*)(sm + MSC + 768);
    float* x0s  = (float*)(sm + MSC + 1024);
    float* x1s  = (float*)(sm + MSC + 1536);
    float* psum = (float*)(sm + MSC + 2048);
    u32 sa = smem_u32(sm);

    // ---- pre-loop staging ----
    if (MODE == 0) {
        if (t < 128) iwS[t] = in_w[t];
        if (t < 64) ibS[t] = in_b[t];
    } else {
        {   // pointwise weights (cols 0..63), single fp16
            const uint4* pF = (const uint4*)(g_PwF + l * 4096);
            for (int i = t; i < 512; i += 256) {
                int o = i >> 3, q = i & 7;
                *(uint4*)(bHs + o * LDA + q * 8) = pF[i];
            }
        }
        {   // Q (cols 64..95), single fp16
            const uint4* qH = (const uint4*)(g_Qh32 + ((size_t)(b * 256 + h)) * 1024);
            for (int i = t; i < 256; i += 256) {
                int o = i >> 2, q = i & 3;
                *(uint4*)(bHs + o * LDA + 64 + q * 8) = qH[i];
            }
        }
        if (t < 64) bias[t] = pw_b[t];
        if (MODE == 2) {
            float* w1s = (float*)(sm + FWH);
            float* b1s = (float*)(sm + FWH + 8192);
            float* w2s = (float*)(sm + FWH + 8320);
            for (int i = t; i < 2048; i += 256) w1s[i] = o1w[i];
            if (t < 32) { b1s[t] = o1b[t]; w2s[t] = o2w[t]; }
        }
    }

    int mg = warp & 3, ng = warp >> 2;
    int aRow = (lane & 7) + ((lane >> 3) & 1) * 8;
    int aKq = (lane >> 4) * 8;
    int bSel = (lane >> 4) & 1, bN = lane & 7, bKq = ((lane >> 3) & 1) * 8;
    int mt2 = warp & 1, ng2 = warp >> 1;
    int trow = lane & 7, khalf = (lane >> 3) & 1, chalf = (lane >> 4) & 1;

    float dT[2][4];
    if (MODE != 2) {
        #pragma unroll
        for (int i1 = 0; i1 < 2; i1++)
            #pragma unroll
            for (int i2 = 0; i2 < 4; i2++) dT[i1][i2] = 0.0f;
    }

    for (int wv = 0; wv < 2; wv++) {
        // ---- A staging ----
        if (MODE == 0) {
            if (t < 128) x0s[t] = x[(((size_t)(b * 2)) * 256 + h) * 256 + wv * 128 + t];
            else x1s[t - 128] = x[(((size_t)(b * 2 + 1)) * 256 + h) * 256 + wv * 128 + (t - 128)];
            __syncthreads();
            for (int i = t; i < 8192; i += 256) {
                int w = i >> 6, c = i & 63;
                float v = fmaf(iwS[2 * c], x0s[w], fmaf(iwS[2 * c + 1], x1s[w], ibS[c]));
                aT[w * LDA + c] = h16(v);
            }
        } else {
            const uint4* sA = (const uint4*)(ain + (((size_t)(b * 256 + h)) * 256 + wv * 128) * 64);
            for (int i = t; i < 1024; i += 256) {
                int w = i >> 3, q = i & 7;
                ((uint4*)aT)[w * 13 + q] = sA[i];
            }
            const uint4* yF = (const uint4*)(g_SynF + wv * 128 * 32);
            for (int i = t; i < 512; i += 256) {
                int w = i >> 2, q = i & 3;
                *(uint4*)(aT + w * LDA + 64 + q * 8) = yF[i];
            }
        }
        if (MODE != 2) {
            const uint4* fF = (const uint4*)(g_FwF + wv * 128);
            for (int i = t; i < 512; i += 256) {
                int r = i >> 4, q = i & 15;
                *(uint4*)(fwh + r * 136 + q * 8) = fF[r * 32 + q];
            }
        }
        __syncthreads();   // S1

        if (MODE >= 1) {
            // ---- main MMA: D[128w x 64o], K=96, single-pass ----
            float d[2][4][4];
            #pragma unroll
            for (int i1 = 0; i1 < 2; i1++)
                #pragma unroll
                for (int i2 = 0; i2 < 4; i2++)
                    #pragma unroll
                    for (int i3 = 0; i3 < 4; i3++) d[i1][i2][i3] = 0.0f;
            #pragma unroll
            for (int k6 = 0; k6 < 6; k6++) {
                int k0 = k6 * 16;
                u32 af[2][4];
                #pragma unroll
                for (int mt = 0; mt < 2; mt++) {
                    u32 ad = (u32)((32 * mg + mt * 16 + aRow) * LDA + k0 + aKq) * 2;
                    ldmx4(af[mt], sa + AOF + ad);
                }
                #pragma unroll
                for (int np = 0; np < 2; np++) {
                    int q0 = ng * 4 + np * 2;
                    u32 bd = (u32)(((q0 + bSel) * 8 + bN) * LDA + k0 + bKq) * 2;
                    u32 bh4[4];
                    ldmx4(bh4, sa + BHI + bd);
                    #pragma unroll
                    for (int sub = 0; sub < 2; sub++) {
                        int nt = np * 2 + sub;
                        #pragma unroll
                        for (int mt = 0; mt < 2; mt++)
                            mma16816(d[mt][nt], af[mt], bh4[2 * sub], bh4[2 * sub + 1]);
                    }
                }
            }
            __syncthreads();   // S2

            // ---- epilogue ----
            int g = lane >> 2, c2 = lane & 3;
            if (MODE == 1) {
                #pragma unroll
                for (int mt = 0; mt < 2; mt++) {
                    int wl = 32 * mg + mt * 16 + g;
                    #pragma unroll
                    for (int nt = 0; nt < 4; nt++) {
                        int ob = (ng * 4 + nt) * 8 + 2 * c2;
                        float v0 = gelu_exact(d[mt][nt][0] + bias[ob]);
                        float v1 = gelu_exact(d[mt][nt][1] + bias[ob + 1]);
                        float v2 = gelu_exact(d[mt][nt][2] + bias[ob]);
                        float v3 = gelu_exact(d[mt][nt][3] + bias[ob + 1]);
                        *(u32*)(aT + wl * LDA + ob) = pkh2(v0, v1);
                        *(u32*)(aT + (wl + 8) * LDA + ob) = pkh2(v2, v3);
                    }
                }
            } else {
                float* stagf = (float*)(sm + STG);   // [128][68]
                #pragma unroll
                for (int mt = 0; mt < 2; mt++) {
                    int wl = 32 * mg + mt * 16 + g;
                    #pragma unroll
                    for (int nt = 0; nt < 4; nt++) {
                        int ob = (ng * 4 + nt) * 8 + 2 * c2;
                        stagf[wl * 68 + ob]           = gelu_exact(d[mt][nt][0] + bias[ob]);
                        stagf[wl * 68 + ob + 1]       = gelu_exact(d[mt][nt][1] + bias[ob + 1]);
                        stagf[(wl + 8) * 68 + ob]     = gelu_exact(d[mt][nt][2] + bias[ob]);
                        stagf[(wl + 8) * 68 + ob + 1] = gelu_exact(d[mt][nt][3] + bias[ob + 1]);
                    }
                }
            }
            __syncthreads();   // S3
        }

        if (MODE != 2) {
            // ---- act gmem store ----
            uint4* dA = (uint4*)(aout + (((size_t)(b * 256 + h)) * 256 + wv * 128) * 64);
            for (int i = t; i < 1024; i += 256) {
                int w = i >> 3, q = i & 7;
                dA[i] = ((uint4*)aT)[w * 13 + q];
            }
            // ---- fwd-w DFT GEMM: dT[32][64] += Fw[32][128] . act[128][64] ----
            #pragma unroll
            for (int ks = 0; ks < 8; ks++) {
                int k0 = ks * 16;
                u32 fh[4], bv[4];
                u32 fad = (u32)((mt2 * 16 + aRow) * 136 + k0 + aKq) * 2;
                ldmx4(fh, sa + FWH + fad);
                u32 bad = (u32)((k0 + khalf * 8 + trow) * LDA + ng2 * 16 + chalf * 8) * 2;
                ldmx4t(bv, sa + AOF + bad);
                #pragma unroll
                for (int nt = 0; nt < 2; nt++)
                    mma16816(dT[nt], fh, bv[2 * nt], bv[2 * nt + 1]);
            }
            __syncthreads();   // S4
        } else {
            // ---- head ----
            float* stagf = (float*)(sm + STG);
            float* w1s = (float*)(sm + FWH);
            float* b1s = (float*)(sm + FWH + 8192);
            float* w2s = (float*)(sm + FWH + 8320);
            int p = t & 127, hf = t >> 7;
            ull x2[32];
            const float2* xr = (const float2*)(stagf + p * 68);
            #pragma unroll
            for (int j = 0; j < 32; j++) {
                float2 xx = xr[j];
                x2[j] = pk(xx.x, xx.y);
            }
            float acc = hf ? 0.0f : __ldg(o2b);
            for (int o2 = hf * 16; o2 < hf * 16 + 16; o2++) {
                ull s = pk(b1s[o2], 0.0f);
                const ulonglong2* wv2 = (const ulonglong2*)(w1s + o2 * 64);
                #pragma unroll
                for (int j = 0; j < 16; j++) {
                    ulonglong2 p4 = wv2[j];
                    s = f2fma(p4.x, x2[2 * j], s);
                    s = f2fma(p4.y, x2[2 * j + 1], s);
                }
                float lo, hi; upk(s, lo, hi);
                acc = fmaf(w2s[o2], gelu_exact(lo + hi), acc);
            }
            psum[hf * 128 + p] = acc;
            __syncthreads();   // S4
            if (t < 128)
                out[((size_t)(b * 256 + h)) * 256 + wv * 128 + t] = psum[t] + psum[128 + t];
            __syncthreads();   // S5
        }
    }

    if (MODE != 2) {
        // ---- store T (fp16) ----
        int g = lane >> 2, c2 = lane & 3;
        #pragma unroll
        for (int nt = 0; nt < 2; nt++) {
            #pragma unroll
            for (int pr = 0; pr < 2; pr++) {
                int row = mt2 * 16 + g + pr * 8;
                int ky = row >> 1, ri = row & 1;
                int c = ng2 * 16 + nt * 8 + 2 * c2;
                size_t bse = (((size_t)(b * 64 + c)) * 256 + h) * 32 + ky * 2 + ri;
                g_T16[bse] = h16(dT[nt][pr * 2 + 0]);
                g_T16[bse + 8192] = h16(dT[nt][pr * 2 + 1]);
            }
        }
    }
}

// ---------------------------------------------------------------------------
extern "C" void kernel_launch(void* const* d_in, const int* in_sizes, int n_in,
                              void* d_out, int out_size) {
    const float* x       = (const float*)d_in[0];
    const float* in_w    = (const float*)d_in[1];
    const float* in_b    = (const float*)d_in[2];
    const float* spec_wr = (const float*)d_in[3];
    const float* spec_wi = (const float*)d_in[4];
    const float* pw_w    = (const float*)d_in[5];
    const float* pw_b    = (const float*)d_in[6];
    const float* o1w     = (const float*)d_in[7];
    const float* o1b     = (const float*)d_in[8];
    const float* o2w     = (const float*)d_in[9];
    const float* o2b     = (const float*)d_in[10];
    float* out = (float*)d_out;

    cudaFuncSetAttribute(k_gemm<0>, cudaFuncAttributeMaxDynamicSharedMemorySize, SMEM_S);
    cudaFuncSetAttribute(k_gemm<1>, cudaFuncAttributeMaxDynamicSharedMemorySize, SMEM_S);
    cudaFuncSetAttribute(k_gemm<2>, cudaFuncAttributeMaxDynamicSharedMemorySize, SMEM_G);

    u16 *aA, *aB;
    cudaGetSymbolAddress((void**)&aA, g_actA);
    cudaGetSymbolAddress((void**)&aB, g_actB);

    k_prep<<<64, 256>>>(pw_w);
    k_twt<<<dim3(128, 8, NL4), dim3(32, 8)>>>(spec_wr, spec_wi);

    dim3 grid(Hh, Bb);
    k_gemm<0><<<grid, 256, SMEM_S>>>(nullptr, aA, nullptr, 0,
                                     x, in_w, in_b, nullptr,
                                     nullptr, nullptr, nullptr, nullptr);

    const u16* cur = aA;
    u16* nxt = aB;
    for (int l = 0; l < NL4; l++) {
        k_fwd_h<<<Bb * C0, 512>>>();
        k_modegemm<<<256, 512>>>(l);
        k_inv_h<<<Bb * C0, 512>>>();
        if (l < NL4 - 1) {
            k_gemm<1><<<grid, 256, SMEM_S>>>(cur, nxt, pw_b + l * 64, l,
                                             nullptr, nullptr, nullptr, nullptr,
                                             nullptr, nullptr, nullptr, nullptr);
            const u16* tmp = cur; cur = nxt; nxt = (u16*)tmp;
        } else {
            k_gemm<2><<<grid, 256, SMEM_G>>>(cur, nullptr, pw_b + l * 64, l,
                                             nullptr, nullptr, nullptr, out,
                                             o1w, o1b, o2w, o2b);
        }
    }
}

// round 17
// speedup vs baseline: 4.3876x; 1.0466x over previous
#include <cuda_runtime.h>
#include <cuda_fp16.h>
#include <math.h>
#include <stdint.h>

#define Bb 8
#define C0 64
#define Hh 256
#define Ww 256
#define MX 16
#define NL4 4
#define HW 65536
#define LDA 104

typedef unsigned long long ull;
typedef unsigned int u32;
typedef unsigned short u16;

// -------------------- helpers ----------------------------------------------
__device__ __forceinline__ ull pk(float lo, float hi) {
    ull r; asm("mov.b64 %0,{%1,%2};" : "=l"(r) : "f"(lo), "f"(hi)); return r;
}
__device__ __forceinline__ void upk(ull v, float& lo, float& hi) {
    asm("mov.b64 {%0,%1},%2;" : "=f"(lo), "=f"(hi) : "l"(v));
}
__device__ __forceinline__ ull f2fma(ull a, ull b, ull c) {
    ull d; asm("fma.rn.f32x2 %0,%1,%2,%3;" : "=l"(d) : "l"(a), "l"(b), "l"(c)); return d;
}
__device__ __forceinline__ u16 h16(float v) {
    return __half_as_ushort(__float2half_rn(v));
}
__device__ __forceinline__ u32 pkh2(float lo, float hi) {   // lo in bits 0..15
    u32 r; asm("cvt.rn.f16x2.f32 %0,%2,%1;" : "=r"(r) : "f"(lo), "f"(hi)); return r;
}
__device__ __forceinline__ u32 smem_u32(const void* p) {
    u32 a; asm("{ .reg .u64 t; cvta.to.shared.u64 t, %1; cvt.u32.u64 %0, t; }" : "=r"(a) : "l"(p));
    return a;
}
__device__ __forceinline__ void ldmx4(u32* r, u32 addr) {
    asm volatile("ldmatrix.sync.aligned.m8n8.x4.shared.b16 {%0,%1,%2,%3},[%4];"
        : "=r"(r[0]), "=r"(r[1]), "=r"(r[2]), "=r"(r[3]) : "r"(addr));
}
__device__ __forceinline__ void ldmx4t(u32* r, u32 addr) {
    asm volatile("ldmatrix.sync.aligned.m8n8.x4.trans.shared.b16 {%0,%1,%2,%3},[%4];"
        : "=r"(r[0]), "=r"(r[1]), "=r"(r[2]), "=r"(r[3]) : "r"(addr));
}
__device__ __forceinline__ void mma16816(float* d, const u32* a, u32 b0, u32 b1) {
    asm volatile("mma.sync.aligned.m16n8k16.row.col.f32.f16.f16.f32 "
        "{%0,%1,%2,%3},{%4,%5,%6,%7},{%8,%9},{%0,%1,%2,%3};"
        : "+f"(d[0]), "+f"(d[1]), "+f"(d[2]), "+f"(d[3])
        : "r"(a[0]), "r"(a[1]), "r"(a[2]), "r"(a[3]), "r"(b0), "r"(b1));
}
// exact-erf GELU via A&S 7.1.26 (|eps| <= 1.5e-7)
__device__ __forceinline__ float gelu_exact(float x) {
    float u = 0.70710678118654752f * x;
    float au = fabsf(u);
    float t = __fdividef(1.0f, fmaf(0.3275911f, au, 1.0f));
    float p = t * fmaf(t, fmaf(t, fmaf(t, fmaf(t, 1.061405429f, -1.453152027f),
                 1.421413741f), -0.284496736f), 0.254829592f);
    float e = __expf(-u * u);
    float er = fmaf(-p, e, 1.0f);
    er = copysignf(er, u);
    return 0.5f * x * (1.0f + er);
}

// -------------------- globals -----------------------------------------------
__device__ u16 g_actA[(size_t)Bb * HW * C0];   // fp16 act plane [b][h][w][c]
__device__ u16 g_actB[(size_t)Bb * HW * C0];
__device__ u16 g_T16[(size_t)Bb * C0 * Hh * 32]; // [bc][h][2ky+ri] fp16
__device__ ull g_Xf[(size_t)Bb * C0 * 256];
__device__ ull g_G [(size_t)256 * Bb * C0];
__device__ u32 g_Qh32[(size_t)Bb * Hh * 1024];  // [(b*256+h)][o][ky]: fp16 (re|-im<<16)
__device__ u32 g_W216[(size_t)NL4 * 256 * 4096]; // [l][m][i*64+o] fp16 (wr|wi)
__device__ ull g_Fh2a[MX * Hh];                 // [kx][h] = (cos, -sin)
__device__ ull g_EaT[MX * Hh];                  // [kx][h] = (cos,  sin)
__device__ ull g_EbT[MX * Hh];                  // [kx][h] = (-sin, cos)
__device__ u16 g_PwF[NL4 * 4096];               // fp16 single [l][o][c]
__device__ u16 g_SynF[256 * 32];                // fp16 single [w][2ky+ri]
__device__ u16 g_FwF[32 * 256];                 // fp16 single [2ky+ri][w]

// -------------------- merged prep -------------------------------------------
__global__ void k_prep(const float* __restrict__ pw_w) {
    int idx = blockIdx.x * 256 + threadIdx.x;   // 0..16383
    g_PwF[idx] = h16(pw_w[idx]);
    if (idx < 4096) {
        int a = idx >> 8, p = idx & 255, m = (a * p) & 255;
        float s, c; sincospif((float)m * (1.0f / 128.0f), &s, &c);
        g_Fh2a[idx] = pk(c, -s);
        g_EaT[idx] = pk(c, s);
        g_EbT[idx] = pk(-s, c);
    }
    if (idx < 8192) {
        {   // syn single fp16: [w][2ky+ri]
            int w = idx >> 5, j = idx & 31, ky = j >> 1, ri = j & 1;
            float s, c; sincospif((float)((ky * w) & 255) * (1.0f / 128.0f), &s, &c);
            float ck = ((ky == 0) ? 1.0f : 2.0f) * (1.0f / 256.0f);
            g_SynF[idx] = h16(ri ? s * ck : c * ck);
        }
        {   // fwd-DFT A single fp16: [2ky+ri][w]
            int row = idx >> 8, w = idx & 255, ky = row >> 1, ri = row & 1;
            float s, c; sincospif((float)((ky * w) & 255) * (1.0f / 128.0f), &s, &c);
            g_FwF[idx] = h16((ri ? -s : c) * (1.0f / 256.0f));
        }
    }
}
__global__ void k_twt(const float* __restrict__ wr, const float* __restrict__ wi) {
    __shared__ u32 tile[32][33];
    int l = blockIdx.z, tio = blockIdx.x, tm = blockIdx.y;
    int tx = threadIdx.x, ty = threadIdx.y;
    const float* wrl = wr + (size_t)l * 4096 * 256;
    const float* wil = wi + (size_t)l * 4096 * 256;
    #pragma unroll
    for (int r = 0; r < 4; r++) {
        int row = tio * 32 + ty + 8 * r, col = tm * 32 + tx;
        size_t idx = (size_t)row * 256 + col;
        tile[ty + 8 * r][tx] = pkh2(wrl[idx], wil[idx]);
    }
    __syncthreads();
    #pragma unroll
    for (int r = 0; r < 4; r++) {
        int mm = tm * 32 + ty + 8 * r, io = tio * 32 + tx;
        g_W216[(((size_t)l * 256) + mm) * 4096 + io] = tile[tx][ty + 8 * r];
    }
}

// -------------------- spectral trio -----------------------------------------
#define FWD_STEP(px, py, cc, nn) \
    sA0 = fmaf(px.x, cc, sA0); sB0 = fmaf(px.y, nn, sB0); \
    sC0 = fmaf(px.y, cc, sC0); sD0 = fmaf(px.x, nn, sD0); \
    sA1 = fmaf(py.x, cc, sA1); sB1 = fmaf(py.y, nn, sB1); \
    sC1 = fmaf(py.y, cc, sC1); sD1 = fmaf(py.x, nn, sD1);

__global__ __launch_bounds__(512, 3) void k_fwd_h() {
    __shared__ u32 Ts[4096];
    __shared__ ull red[1024];
    int bc = blockIdx.x, t = threadIdx.x;
    {
        const uint4* Tg4 = (const uint4*)(g_T16 + (size_t)bc * 8192);
        uint4* Ts4 = (uint4*)Ts;
        for (int i = t; i < 1024; i += 512) Ts4[i] = Tg4[i];
    }
    __syncthreads();
    int kyg = t & 7, kx = (t >> 3) & 15, hq = t >> 7;
    const ulonglong2* fa2 = (const ulonglong2*)(g_Fh2a + kx * 256 + hq * 64);
    const u32* Tp = Ts + (hq * 64) * 16 + 2 * kyg;
    float sA0 = 0, sB0 = 0, sC0 = 0, sD0 = 0;
    float sA1 = 0, sB1 = 0, sC1 = 0, sD1 = 0;
    #pragma unroll 2
    for (int j = 0; j < 16; j++) {
        ulonglong2 fx = __ldg(fa2 + 2 * j);
        ulonglong2 fy = __ldg(fa2 + 2 * j + 1);
        float c0, n0, c1, n1, c2, n2, c3, n3;
        upk(fx.x, c0, n0); upk(fx.y, c1, n1);
        upk(fy.x, c2, n2); upk(fy.y, c3, n3);
        uint2 v0 = *(const uint2*)(Tp + (4 * j + 0) * 16);
        uint2 v1 = *(const uint2*)(Tp + (4 * j + 1) * 16);
        uint2 v2 = *(const uint2*)(Tp + (4 * j + 2) * 16);
        uint2 v3 = *(const uint2*)(Tp + (4 * j + 3) * 16);
        float2 p0, p1;
        p0 = __half22float2(*(__half2*)&v0.x); p1 = __half22float2(*(__half2*)&v0.y);
        FWD_STEP(p0, p1, c0, n0)
        p0 = __half22float2(*(__half2*)&v1.x); p1 = __half22float2(*(__half2*)&v1.y);
        FWD_STEP(p0, p1, c1, n1)
        p0 = __half22float2(*(__half2*)&v2.x); p1 = __half22float2(*(__half2*)&v2.y);
        FWD_STEP(p0, p1, c2, n2)
        p0 = __half22float2(*(__half2*)&v3.x); p1 = __half22float2(*(__half2*)&v3.y);
        FWD_STEP(p0, p1, c3, n3)
    }
    *(ulonglong2*)(red + hq * 256 + kx * 16 + 2 * kyg) =
        make_ulonglong2(pk(sA0 - sB0, sC0 + sD0), pk(sA1 - sB1, sC1 + sD1));
    __syncthreads();
    if (t < 256) {
        float r0, i0, r1, i1, r2, i2, r3, i3;
        upk(red[t], r0, i0); upk(red[t + 256], r1, i1);
        upk(red[t + 512], r2, i2); upk(red[t + 768], r3, i3);
        g_Xf[(size_t)bc * 256 + t] = pk((r0 + r1) + (r2 + r3), (i0 + i1) + (i2 + i3));
    }
}

__global__ __launch_bounds__(512, 3) void k_modegemm(int l) {
    __shared__ __align__(16) u32 ws[4096];
    __shared__ ull xA[512], xB[512];
    int m = blockIdx.x, t = threadIdx.x;
    {
        const uint4* W4 = (const uint4*)(g_W216 + (((size_t)l * 256) + m) * 4096);
        uint4* ws4 = (uint4*)ws;
        for (int i = t; i < 1024; i += 512) ws4[i] = W4[i];
    }
    {
        int b = t >> 6, i = t & 63;
        float xr, xi; upk(g_Xf[((size_t)b * C0 + i) * 256 + m], xr, xi);
        xA[t] = pk(xr, xr);
        xB[t] = pk(-xi, xi);
    }
    __syncthreads();
    int b = t >> 6, o = t & 63;
    ull acc0 = 0ull, acc1 = 0ull;
    const ull* xa = xA + b * 64;
    const ull* xb = xB + b * 64;
    #pragma unroll 4
    for (int i = 0; i < C0; i += 2) {
        u32 w2 = ws[i * 64 + o];
        float2 wf = __half22float2(*(__half2*)&w2);
        acc0 = f2fma(xa[i], pk(wf.x, wf.y), acc0);
        acc0 = f2fma(xb[i], pk(wf.y, wf.x), acc0);
        u32 w3 = ws[(i + 1) * 64 + o];
        float2 wg = __half22float2(*(__half2*)&w3);
        acc1 = f2fma(xa[i + 1], pk(wg.x, wg.y), acc1);
        acc1 = f2fma(xb[i + 1], pk(wg.y, wg.x), acc1);
    }
    float p0, q0, p1, q1;
    upk(acc0, p0, q0); upk(acc1, p1, q1);
    g_G[(size_t)m * 512 + t] = pk(p0 + p1, q0 + q1);
}

// inverse kx: single fp16 Q plane output.
__global__ __launch_bounds__(512, 2) void k_inv_h() {
    __shared__ ull Gs[256];
    int bo = blockIdx.x, t = threadIdx.x;
    int b = bo >> 6, o = bo & 63;
    if (t < 256) Gs[t] = g_G[(size_t)t * 512 + bo];
    __syncthreads();
    int kyg = t & 7, hg = t >> 3;
    ull a00 = 0, a01 = 0, a02 = 0, a03 = 0;
    ull a10 = 0, a11 = 0, a12 = 0, a13 = 0;
    #pragma unroll
    for (int kx = 0; kx < 16; kx++) {
        ulonglong2 g2 = *(const ulonglong2*)(Gs + kx * 16 + 2 * kyg);
        float gr0, gi0, gr1, gi1;
        upk(g2.x, gr0, gi0); upk(g2.y, gr1, gi1);
        ull gr20 = pk(gr0, gr0), gi20 = pk(gi0, gi0);
        ull gr21 = pk(gr1, gr1), gi21 = pk(gi1, gi1);
        const ulonglong2* ea = (const ulonglong2*)(g_EaT + kx * 256 + hg * 4);
        const ulonglong2* eb = (const ulonglong2*)(g_EbT + kx * 256 + hg * 4);
        ulonglong2 ea0 = __ldg(ea), ea1 = __ldg(ea + 1);
        ulonglong2 eb0 = __ldg(eb), eb1 = __ldg(eb + 1);
        a00 = f2fma(gr20, ea0.x, a00); a00 = f2fma(gi20, eb0.x, a00);
        a01 = f2fma(gr20, ea0.y, a01); a01 = f2fma(gi20, eb0.y, a01);
        a02 = f2fma(gr20, ea1.x, a02); a02 = f2fma(gi20, eb1.x, a02);
        a03 = f2fma(gr20, ea1.y, a03); a03 = f2fma(gi20, eb1.y, a03);
        a10 = f2fma(gr21, ea0.x, a10); a10 = f2fma(gi21, eb0.x, a10);
        a11 = f2fma(gr21, ea0.y, a11); a11 = f2fma(gi21, eb0.y, a11);
        a12 = f2fma(gr21, ea1.x, a12); a12 = f2fma(gi21, eb1.x, a12);
        a13 = f2fma(gr21, ea1.y, a13); a13 = f2fma(gi21, eb1.y, a13);
    }
    ull acc0[4] = {a00, a01, a02, a03};
    ull acc1[4] = {a10, a11, a12, a13};
    #pragma unroll
    for (int hp = 0; hp < 4; hp++) {
        int h = hg * 4 + hp;
        float re0, im0, re1, im1;
        upk(acc0[hp], re0, im0);
        upk(acc1[hp], re1, im1);
        u32 base = (((u32)b * 256 + h) * 64 + o) * 16 + 2 * kyg;
        *(uint2*)(g_Qh32 + base) = make_uint2(
            (u32)h16(re0) | ((u32)h16(-im0) << 16),
            (u32)h16(re1) | ((u32)h16(-im1) << 16));
    }
}

// -------------------- fused HMMA layer kernel -------------------------------
// smem (bytes):
#define AOF 0          // 26624 = 128*104*2  (fp16 act+syn tile)
#define BHI 26624      // 13312 = 64*104*2 (single fp16 B)
#define FWH 39936      // 8704 = 32*136*2 (single fp16 Fw; MODE2: head weights)
#define MSC 48640      // 3072
#define STG 51712      // 34816 (MODE 2 f32 stag [128][68])
#define SMEM_S 51712   // MODE 0/1
#define SMEM_G 86528   // MODE 2

// MODE: 0 = lift, 1 = mid layer, 2 = last layer (+head)
template <int MODE>
__global__ __launch_bounds__(256, (MODE == 2 ? 2 : 4))
void k_gemm(const u16* __restrict__ ain, u16* __restrict__ aout,
            const float* __restrict__ pw_b, int l,
            const float* __restrict__ x, const float* __restrict__ in_w,
            const float* __restrict__ in_b,
            float* __restrict__ out,
            const float* __restrict__ o1w, const float* __restrict__ o1b,
            const float* __restrict__ o2w, const float* __restrict__ o2b) {
    extern __shared__ __align__(16) char sm[];
    int h = blockIdx.x, b = blockIdx.y, t = threadIdx.x;
    int warp = t >> 5, lane = t & 31;
    u16* aT  = (u16*)(sm + AOF);
    u16* bHs = (u16*)(sm + BHI);
    u16* fwh = (u16*)(sm + FWH);
    float* bias = (float*)(sm + MSC);
    float* iwS  = (float*)(sm + MSC + 256);
    float* ibS  = (float*)(sm + MSC + 768);
    float* x0s  = (float*)(sm + MSC + 1024);
    float* x1s  = (float*)(sm + MSC + 1536);
    float* psum = (float*)(sm + MSC + 2048);
    u32 sa = smem_u32(sm);

    // ---- pre-loop staging ----
    if (MODE == 0) {
        if (t < 128) iwS[t] = in_w[t];
        if (t < 64) ibS[t] = in_b[t];
    } else {
        {   // pointwise weights (cols 0..63), single fp16
            const uint4* pF = (const uint4*)(g_PwF + l * 4096);
            for (int i = t; i < 512; i += 256) {
                int o = i >> 3, q = i & 7;
                *(uint4*)(bHs + o * LDA + q * 8) = pF[i];
            }
        }
        {   // Q (cols 64..95), single fp16
            const uint4* qH = (const uint4*)(g_Qh32 + ((size_t)(b * 256 + h)) * 1024);
            for (int i = t; i < 256; i += 256) {
                int o = i >> 2, q = i & 3;
                *(uint4*)(bHs + o * LDA + 64 + q * 8) = qH[i];
            }
        }
        if (t < 64) bias[t] = pw_b[t];
        if (MODE == 2) {
            float* w1s = (float*)(sm + FWH);
            float* b1s = (float*)(sm + FWH + 8192);
            float* w2s = (float*)(sm + FWH + 8320);
            for (int i = t; i < 2048; i += 256) w1s[i] = o1w[i];
            if (t < 32) { b1s[t] = o1b[t]; w2s[t] = o2w[t]; }
        }
    }

    int mg = warp & 3, ng = warp >> 2;
    int aRow = (lane & 7) + ((lane >> 3) & 1) * 8;
    int aKq = (lane >> 4) * 8;
    int bSel = (lane >> 4) & 1, bN = lane & 7, bKq = ((lane >> 3) & 1) * 8;
    int mt2 = warp & 1, ng2 = warp >> 1;
    int trow = lane & 7, khalf = (lane >> 3) & 1, chalf = (lane >> 4) & 1;

    float dT[2][4];
    if (MODE != 2) {
        #pragma unroll
        for (int i1 = 0; i1 < 2; i1++)
            #pragma unroll
            for (int i2 = 0; i2 < 4; i2++) dT[i1][i2] = 0.0f;
    }

    for (int wv = 0; wv < 2; wv++) {
        // ---- A staging ----
        if (MODE == 0) {
            if (t < 128) x0s[t] = x[(((size_t)(b * 2)) * 256 + h) * 256 + wv * 128 + t];
            else x1s[t - 128] = x[(((size_t)(b * 2 + 1)) * 256 + h) * 256 + wv * 128 + (t - 128)];
            __syncthreads();
            for (int i = t; i < 8192; i += 256) {
                int w = i >> 6, c = i & 63;
                float v = fmaf(iwS[2 * c], x0s[w], fmaf(iwS[2 * c + 1], x1s[w], ibS[c]));
                aT[w * LDA + c] = h16(v);
            }
        } else {
            const uint4* sA = (const uint4*)(ain + (((size_t)(b * 256 + h)) * 256 + wv * 128) * 64);
            for (int i = t; i < 1024; i += 256) {
                int w = i >> 3, q = i & 7;
                ((uint4*)aT)[w * 13 + q] = sA[i];
            }
            const uint4* yF = (const uint4*)(g_SynF + wv * 128 * 32);
            for (int i = t; i < 512; i += 256) {
                int w = i >> 2, q = i & 3;
                *(uint4*)(aT + w * LDA + 64 + q * 8) = yF[i];
            }
        }
        if (MODE != 2) {
            const uint4* fF = (const uint4*)(g_FwF + wv * 128);
            for (int i = t; i < 512; i += 256) {
                int r = i >> 4, q = i & 15;
                *(uint4*)(fwh + r * 136 + q * 8) = fF[r * 32 + q];
            }
        }
        __syncthreads();   // S1

        if (MODE >= 1) {
            // ---- main MMA: D[128w x 64o], K=96, single-pass ----
            float d[2][4][4];
            #pragma unroll
            for (int i1 = 0; i1 < 2; i1++)
                #pragma unroll
                for (int i2 = 0; i2 < 4; i2++)
                    #pragma unroll
                    for (int i3 = 0; i3 < 4; i3++) d[i1][i2][i3] = 0.0f;
            #pragma unroll
            for (int k6 = 0; k6 < 6; k6++) {
                int k0 = k6 * 16;
                u32 af[2][4];
                #pragma unroll
                for (int mt = 0; mt < 2; mt++) {
                    u32 ad = (u32)((32 * mg + mt * 16 + aRow) * LDA + k0 + aKq) * 2;
                    ldmx4(af[mt], sa + AOF + ad);
                }
                #pragma unroll
                for (int np = 0; np < 2; np++) {
                    int q0 = ng * 4 + np * 2;
                    u32 bd = (u32)(((q0 + bSel) * 8 + bN) * LDA + k0 + bKq) * 2;
                    u32 bh4[4];
                    ldmx4(bh4, sa + BHI + bd);
                    #pragma unroll
                    for (int sub = 0; sub < 2; sub++) {
                        int nt = np * 2 + sub;
                        #pragma unroll
                        for (int mt = 0; mt < 2; mt++)
                            mma16816(d[mt][nt], af[mt], bh4[2 * sub], bh4[2 * sub + 1]);
                    }
                }
            }
            __syncthreads();   // S2

            // ---- epilogue ----
            int g = lane >> 2, c2 = lane & 3;
            if (MODE == 1) {
                #pragma unroll
                for (int mt = 0; mt < 2; mt++) {
                    int wl = 32 * mg + mt * 16 + g;
                    #pragma unroll
                    for (int nt = 0; nt < 4; nt++) {
                        int ob = (ng * 4 + nt) * 8 + 2 * c2;
                        float v0 = gelu_exact(d[mt][nt][0] + bias[ob]);
                        float v1 = gelu_exact(d[mt][nt][1] + bias[ob + 1]);
                        float v2 = gelu_exact(d[mt][nt][2] + bias[ob]);
                        float v3 = gelu_exact(d[mt][nt][3] + bias[ob + 1]);
                        *(u32*)(aT + wl * LDA + ob) = pkh2(v0, v1);
                        *(u32*)(aT + (wl + 8) * LDA + ob) = pkh2(v2, v3);
                    }
                }
            } else {
                float* stagf = (float*)(sm + STG);   // [128][68]
                #pragma unroll
                for (int mt = 0; mt < 2; mt++) {
                    int wl = 32 * mg + mt * 16 + g;
                    #pragma unroll
                    for (int nt = 0; nt < 4; nt++) {
                        int ob = (ng * 4 + nt) * 8 + 2 * c2;
                        stagf[wl * 68 + ob]           = gelu_exact(d[mt][nt][0] + bias[ob]);
                        stagf[wl * 68 + ob + 1]       = gelu_exact(d[mt][nt][1] + bias[ob + 1]);
                        stagf[(wl + 8) * 68 + ob]     = gelu_exact(d[mt][nt][2] + bias[ob]);
                        stagf[(wl + 8) * 68 + ob + 1] = gelu_exact(d[mt][nt][3] + bias[ob + 1]);
                    }
                }
            }
            __syncthreads();   // S3
        }

        if (MODE != 2) {
            // ---- act gmem store ----
            uint4* dA = (uint4*)(aout + (((size_t)(b * 256 + h)) * 256 + wv * 128) * 64);
            for (int i = t; i < 1024; i += 256) {
                int w = i >> 3, q = i & 7;
                dA[i] = ((uint4*)aT)[w * 13 + q];
            }
            // ---- fwd-w DFT GEMM: dT[32][64] += Fw[32][128] . act[128][64] ----
            #pragma unroll
            for (int ks = 0; ks < 8; ks++) {
                int k0 = ks * 16;
                u32 fh[4], bv[4];
                u32 fad = (u32)((mt2 * 16 + aRow) * 136 + k0 + aKq) * 2;
                ldmx4(fh, sa + FWH + fad);
                u32 bad = (u32)((k0 + khalf * 8 + trow) * LDA + ng2 * 16 + chalf * 8) * 2;
                ldmx4t(bv, sa + AOF + bad);
                #pragma unroll
                for (int nt = 0; nt < 2; nt++)
                    mma16816(dT[nt], fh, bv[2 * nt], bv[2 * nt + 1]);
            }
            __syncthreads();   // S4
        } else {
            // ---- head ----
            float* stagf = (float*)(sm + STG);
            float* w1s = (float*)(sm + FWH);
            float* b1s = (float*)(sm + FWH + 8192);
            float* w2s = (float*)(sm + FWH + 8320);
            int p = t & 127, hf = t >> 7;
            ull x2[32];
            const float2* xr = (const float2*)(stagf + p * 68);
            #pragma unroll
            for (int j = 0; j < 32; j++) {
                float2 xx = xr[j];
                x2[j] = pk(xx.x, xx.y);
            }
            float acc = hf ? 0.0f : __ldg(o2b);
            for (int o2 = hf * 16; o2 < hf * 16 + 16; o2++) {
                ull s = pk(b1s[o2], 0.0f);
                const ulonglong2* wv2 = (const ulonglong2*)(w1s + o2 * 64);
                #pragma unroll
                for (int j = 0; j < 16; j++) {
                    ulonglong2 p4 = wv2[j];
                    s = f2fma(p4.x, x2[2 * j], s);
                    s = f2fma(p4.y, x2[2 * j + 1], s);
                }
                float lo, hi; upk(s, lo, hi);
                acc = fmaf(w2s[o2], gelu_exact(lo + hi), acc);
            }
            psum[hf * 128 + p] = acc;
            __syncthreads();   // S4
            if (t < 128)
                out[((size_t)(b * 256 + h)) * 256 + wv * 128 + t] = psum[t] + psum[128 + t];
            __syncthreads();   // S5
        }
    }

    if (MODE != 2) {
        // ---- store T (fp16) ----
        int g = lane >> 2, c2 = lane & 3;
        #pragma unroll
        for (int nt = 0; nt < 2; nt++) {
            #pragma unroll
            for (int pr = 0; pr < 2; pr++) {
                int row = mt2 * 16 + g + pr * 8;
                int ky = row >> 1, ri = row & 1;
                int c = ng2 * 16 + nt * 8 + 2 * c2;
                size_t bse = (((size_t)(b * 64 + c)) * 256 + h) * 32 + ky * 2 + ri;
                g_T16[bse] = h16(dT[nt][pr * 2 + 0]);
                g_T16[bse + 8192] = h16(dT[nt][pr * 2 + 1]);
            }
        }
    }
}

// ---------------------------------------------------------------------------
extern "C" void kernel_launch(void* const* d_in, const int* in_sizes, int n_in,
                              void* d_out, int out_size) {
    const float* x       = (const float*)d_in[0];
    const float* in_w    = (const float*)d_in[1];
    const float* in_b    = (const float*)d_in[2];
    const float* spec_wr = (const float*)d_in[3];
    const float* spec_wi = (const float*)d_in[4];
    const float* pw_w    = (const float*)d_in[5];
    const float* pw_b    = (const float*)d_in[6];
    const float* o1w     = (const float*)d_in[7];
    const float* o1b     = (const float*)d_in[8];
    const float* o2w     = (const float*)d_in[9];
    const float* o2b     = (const float*)d_in[10];
    float* out = (float*)d_out;

    cudaFuncSetAttribute(k_gemm<0>, cudaFuncAttributeMaxDynamicSharedMemorySize, SMEM_S);
    cudaFuncSetAttribute(k_gemm<1>, cudaFuncAttributeMaxDynamicSharedMemorySize, SMEM_S);
    cudaFuncSetAttribute(k_gemm<2>, cudaFuncAttributeMaxDynamicSharedMemorySize, SMEM_G);

    u16 *aA, *aB;
    cudaGetSymbolAddress((void**)&aA, g_actA);
    cudaGetSymbolAddress((void**)&aB, g_actB);

    k_prep<<<64, 256>>>(pw_w);
    k_twt<<<dim3(128, 8, NL4), dim3(32, 8)>>>(spec_wr, spec_wi);

    dim3 grid(Hh, Bb);
    k_gemm<0><<<grid, 256, SMEM_S>>>(nullptr, aA, nullptr, 0,
                                     x, in_w, in_b, nullptr,
                                     nullptr, nullptr, nullptr, nullptr);

    const u16* cur = aA;
    u16* nxt = aB;
    for (int l = 0; l < NL4; l++) {
        k_fwd_h<<<Bb * C0, 512>>>();
        k_modegemm<<<256, 512>>>(l);
        k_inv_h<<<Bb * C0, 512>>>();
        if (l < NL4 - 1) {
            k_gemm<1><<<grid, 256, SMEM_S>>>(cur, nxt, pw_b + l * 64, l,
                                             nullptr, nullptr, nullptr, nullptr,
                                             nullptr, nullptr, nullptr, nullptr);
            const u16* tmp = cur; cur = nxt; nxt = (u16*)tmp;
        } else {
            k_gemm<2><<<grid, 256, SMEM_G>>>(cur, nullptr, pw_b + l * 64, l,
                                             nullptr, nullptr, nullptr, out,
                                             o1w, o1b, o2w, o2b);
        }
    }
}